// round 6
// baseline (speedup 1.0000x reference)
#include <cuda_runtime.h>
#include <cuda_bf16.h>
#include <math.h>
#include <stdint.h>

#define BB 2
#define TT 2048
#define CC 1024
#define HH 16
#define DD 64
#define NR 65                      // 2*MAXREL+1
#define BH (BB*HH)                 // 32
#define BT (BB*TT)                 // 4096

// ---------------- device scratch (no allocations allowed) ----------------
__device__ float g_q[BH*TT*DD];        // fp32 q (for qrel)
__device__ float g_qrel[BH*TT*NR];     // [bh][t][r]
__device__ float g_o[BT*CC];           // pre-proj context
__device__ float g_y[BT*CC];           // fallback y sink
__device__ float g_att[(size_t)BH*TT*TT]; // fallback att sink

// bf16 hi/lo operands
__device__ __nv_bfloat16 g_qh[BH*TT*DD], g_ql[BH*TT*DD];
__device__ __nv_bfloat16 g_kh[BH*TT*DD], g_kl[BH*TT*DD];
__device__ __nv_bfloat16 g_vh[BH*TT*DD], g_vl[BH*TT*DD];
__device__ __nv_bfloat16 g_xa_hi[BT*CC],  g_xa_lo[BT*CC];     // x split   [M][K]
__device__ __nv_bfloat16 g_oa_hi[BT*CC],  g_oa_lo[BT*CC];     // o split   [M][K]
__device__ __nv_bfloat16 g_wta_hi[3*CC*CC], g_wta_lo[3*CC*CC];// w_attn^T  [N][K]
__device__ __nv_bfloat16 g_wtp_hi[CC*CC],   g_wtp_lo[CC*CC];  // w_proj^T  [N][K]

// ===================== mma.sync helper =====================
__device__ __forceinline__ void mma_16816(float* c, const uint32_t* a, const uint32_t* b) {
    asm volatile("mma.sync.aligned.m16n8k16.row.col.f32.bf16.bf16.f32 "
        "{%0,%1,%2,%3}, {%4,%5,%6,%7}, {%8,%9}, {%0,%1,%2,%3};"
        : "+f"(c[0]), "+f"(c[1]), "+f"(c[2]), "+f"(c[3])
        : "r"(a[0]), "r"(a[1]), "r"(a[2]), "r"(a[3]), "r"(b[0]), "r"(b[1]));
}
__device__ __forceinline__ uint32_t pack_bf2(__nv_bfloat16 a, __nv_bfloat16 b) {
    return ((uint32_t)__bfloat16_as_ushort(b) << 16) | __bfloat16_as_ushort(a);
}

// =====================================================================
// Conversion kernels: fp32 -> (hi, lo) bf16 split
// =====================================================================
template<int SRC>   // 0: x param -> g_xa,  1: g_o -> g_oa
__global__ __launch_bounds__(256) void split_kernel(const float* __restrict__ in)
{
    const float* src = (SRC == 0) ? in : (const float*)g_o;
    __nv_bfloat16* hi = (SRC == 0) ? g_xa_hi : g_oa_hi;
    __nv_bfloat16* lo = (SRC == 0) ? g_xa_lo : g_oa_lo;
    int i = blockIdx.x * 256 + threadIdx.x;          // float4 index
    float4 v = ((const float4*)src)[i];
    float a[4] = {v.x, v.y, v.z, v.w};
    __nv_bfloat16 hb[4], lb[4];
    #pragma unroll
    for (int c = 0; c < 4; c++) {
        hb[c] = __float2bfloat16(a[c]);
        lb[c] = __float2bfloat16(a[c] - __bfloat162float(hb[c]));
    }
    ((uint32_t*)hi)[i*2+0] = pack_bf2(hb[0], hb[1]);
    ((uint32_t*)hi)[i*2+1] = pack_bf2(hb[2], hb[3]);
    ((uint32_t*)lo)[i*2+0] = pack_bf2(lb[0], lb[1]);
    ((uint32_t*)lo)[i*2+1] = pack_bf2(lb[2], lb[3]);
}

// W[K=1024, N] -> Wt_hi/lo[N][K] bf16 (transpose + split)
template<int WSEL>  // 0: w_attn -> g_wta, 1: w_proj -> g_wtp
__global__ __launch_bounds__(256) void wsplit_kernel(const float* __restrict__ W, int N)
{
    __shared__ float ts[32][33];
    __nv_bfloat16* hi = (WSEL == 0) ? g_wta_hi : g_wtp_hi;
    __nv_bfloat16* lo = (WSEL == 0) ? g_wta_lo : g_wtp_lo;
    int nx = blockIdx.x * 32, kx = blockIdx.y * 32;
    int tx = threadIdx.x, ty = threadIdx.y;
    #pragma unroll
    for (int j = ty; j < 32; j += 8)
        ts[j][tx] = W[(size_t)(kx + j)*N + nx + tx];
    __syncthreads();
    #pragma unroll
    for (int j = ty; j < 32; j += 8) {
        float v = ts[tx][j];
        __nv_bfloat16 h = __float2bfloat16(v);
        __nv_bfloat16 l = __float2bfloat16(v - __bfloat162float(h));
        hi[(size_t)(nx + j)*CC + kx + tx] = h;
        lo[(size_t)(nx + j)*CC + kx + tx] = l;
    }
}

// =====================================================================
// mma.sync bf16x3 GEMM (unchanged core from R5)
// MODE 0: scatter -> q (fp32+bf16 hi/lo), k/v (bf16 hi/lo), +bias (N=3072)
// MODE 1: A = g_oa, B = g_wtp, out -> y + bias (N=1024)
// =====================================================================
#define LDA 72
#define SM_ARR (128*LDA)
#define GEMM_SMEM_BYTES (4*SM_ARR*2)

template<int MODE>
__global__ __launch_bounds__(256) void mma_gemm_kernel(const float* __restrict__ bias,
                                                       float* __restrict__ outp)
{
    extern __shared__ __nv_bfloat16 sb[];
    __nv_bfloat16* sAh = sb;
    __nv_bfloat16* sAl = sb + SM_ARR;
    __nv_bfloat16* sBh = sb + 2*SM_ARR;
    __nv_bfloat16* sBl = sb + 3*SM_ARR;

    const int tid  = threadIdx.x;
    const int wid  = tid >> 5, lane = tid & 31;
    const int wm   = wid >> 2, wn = wid & 3;
    const int m0   = blockIdx.y * 128;
    const int n0   = blockIdx.x * 128;

    const __nv_bfloat16* Ah = (MODE == 0) ? g_xa_hi : g_oa_hi;
    const __nv_bfloat16* Al = (MODE == 0) ? g_xa_lo : g_oa_lo;
    const __nv_bfloat16* Bh = (MODE == 0) ? g_wta_hi : g_wtp_hi;
    const __nv_bfloat16* Bl = (MODE == 0) ? g_wta_lo : g_wtp_lo;

    float acc[4][4][4];
    #pragma unroll
    for (int i = 0; i < 4; i++)
        #pragma unroll
        for (int j = 0; j < 4; j++)
            #pragma unroll
            for (int c = 0; c < 4; c++) acc[i][j][c] = 0.f;

    const int g  = lane >> 2;
    const int t2 = (lane & 3) * 2;

    for (int kt = 0; kt < 16; kt++) {
        const int k0 = kt * 64;
        #pragma unroll
        for (int it = 0; it < 4; it++) {
            int i = tid + it * 256;
            int r = i >> 3, c8 = i & 7;
            size_t ga = (size_t)(m0 + r) * CC + k0 + c8 * 8;
            size_t gb = (size_t)(n0 + r) * CC + k0 + c8 * 8;
            int so = r * LDA + c8 * 8;
            *(float4*)&sAh[so] = *(const float4*)&Ah[ga];
            *(float4*)&sAl[so] = *(const float4*)&Al[ga];
            *(float4*)&sBh[so] = *(const float4*)&Bh[gb];
            *(float4*)&sBl[so] = *(const float4*)&Bl[gb];
        }
        __syncthreads();

        #pragma unroll
        for (int ks = 0; ks < 4; ks++) {
            const int kb = ks * 16 + t2;
            uint32_t ah[4][4], al[4][4];
            #pragma unroll
            for (int tm = 0; tm < 4; tm++) {
                int r0 = (wm*64 + tm*16 + g) * LDA + kb;
                int r1 = r0 + 8 * LDA;
                ah[tm][0] = *(const uint32_t*)&sAh[r0];
                ah[tm][1] = *(const uint32_t*)&sAh[r1];
                ah[tm][2] = *(const uint32_t*)&sAh[r0 + 8];
                ah[tm][3] = *(const uint32_t*)&sAh[r1 + 8];
                al[tm][0] = *(const uint32_t*)&sAl[r0];
                al[tm][1] = *(const uint32_t*)&sAl[r1];
                al[tm][2] = *(const uint32_t*)&sAl[r0 + 8];
                al[tm][3] = *(const uint32_t*)&sAl[r1 + 8];
            }
            #pragma unroll
            for (int tn = 0; tn < 4; tn++) {
                int rb = (wn*32 + tn*8 + g) * LDA + kb;
                uint32_t bh[2], bl[2];
                bh[0] = *(const uint32_t*)&sBh[rb];
                bh[1] = *(const uint32_t*)&sBh[rb + 8];
                bl[0] = *(const uint32_t*)&sBl[rb];
                bl[1] = *(const uint32_t*)&sBl[rb + 8];
                #pragma unroll
                for (int tm = 0; tm < 4; tm++) {
                    mma_16816(acc[tm][tn], ah[tm], bh);
                    mma_16816(acc[tm][tn], ah[tm], bl);
                    mma_16816(acc[tm][tn], al[tm], bh);
                }
            }
        }
        __syncthreads();
    }

    // ---- epilogue ----
    const int lr = lane >> 2;
    const int lc = (lane & 3) * 2;
    #pragma unroll
    for (int tm = 0; tm < 4; tm++) {
        #pragma unroll
        for (int tn = 0; tn < 4; tn++) {
            int c = n0 + wn*32 + tn*8 + lc;
            float b0 = bias[c], b1 = bias[c+1];
            #pragma unroll
            for (int half = 0; half < 2; half++) {
                int m = m0 + wm*64 + tm*16 + lr + half*8;
                float v0 = acc[tm][tn][half*2+0] + b0;
                float v1 = acc[tm][tn][half*2+1] + b1;
                if (MODE == 0) {
                    int which = c >> 10, hh = (c >> 6) & 15, dd = c & 63;
                    int b_ = m >> 11, t_ = m & 2047;
                    size_t di = ((size_t)(b_*HH + hh)*TT + t_)*DD + dd;
                    __nv_bfloat16 h0 = __float2bfloat16(v0);
                    __nv_bfloat16 h1 = __float2bfloat16(v1);
                    __nv_bfloat16 l0 = __float2bfloat16(v0 - __bfloat162float(h0));
                    __nv_bfloat16 l1 = __float2bfloat16(v1 - __bfloat162float(h1));
                    uint32_t hw = pack_bf2(h0, h1), lw = pack_bf2(l0, l1);
                    if (which == 0) {
                        *(float2*)&g_q[di] = make_float2(v0, v1);
                        *(uint32_t*)&g_qh[di] = hw;
                        *(uint32_t*)&g_ql[di] = lw;
                    } else if (which == 1) {
                        *(uint32_t*)&g_kh[di] = hw;
                        *(uint32_t*)&g_kl[di] = lw;
                    } else {
                        *(uint32_t*)&g_vh[di] = hw;
                        *(uint32_t*)&g_vl[di] = lw;
                    }
                } else {
                    float* dst = outp ? outp : g_y;
                    *(float2*)&dst[(size_t)m*CC + c] = make_float2(v0, v1);
                }
            }
        }
    }
}

// =====================================================================
// qrel[bh*T + t][r] = q[bh][t][:] . rel_k_table[r][:]
// =====================================================================
__device__ __forceinline__ float dot4(float4 a, float4 b) {
    return a.x*b.x + a.y*b.y + a.z*b.z + a.w*b.w;
}

__global__ __launch_bounds__(256) void qrel_kernel(const float* __restrict__ rel)
{
    __shared__ float rs[NR*64];
    __shared__ float qs[32*64];
    const int tid = threadIdx.x;
    const int r0  = blockIdx.x * 32;

    for (int i = tid; i < NR*16; i += 256)
        ((float4*)rs)[i] = ((const float4*)rel)[i];
    for (int i = tid; i < 32*16; i += 256) {
        int t = i >> 4, d4 = i & 15;
        *(float4*)&qs[t*64 + d4*4] = *(const float4*)&g_q[(size_t)(r0+t)*64 + d4*4];
    }
    __syncthreads();

    for (int i = tid; i < 32*NR; i += 256) {
        int t = i / NR, r = i % NR;
        const float4* qq = (const float4*)&qs[t*64];
        const float4* rr = (const float4*)&rs[r*64];
        float acc = 0.f;
        #pragma unroll
        for (int d4 = 0; d4 < 16; d4++) acc += dot4(qq[d4], rr[d4]);
        g_qrel[(size_t)(r0+t)*NR + r] = acc;
    }
}

// =====================================================================
// Tensor-core attention: block = (qt, bh), 16 q-rows.
//  S = QK^T via mma.sync bf16x3 (warps split keys), +rel, scale -> S smem fp32
//  softmax fp32 in smem
//  att write + in-place repack of p as (ph|pl) bf16x2 in S slots
//  O = P·V via mma.sync bf16x3 (V^T staged hi/lo, warps split keys, smem reduce)
// =====================================================================
#define SLDA 2056
#define KVU_BYTES 73728
#define ATTN_SMEM_BYTES (16*SLDA*4 + KVU_BYTES + 16*66*4 + 64)

__global__ __launch_bounds__(256) void attn_kernel(float* __restrict__ out_att, int att_mode)
{
    extern __shared__ float sm[];
    float* S   = sm;                                 // [16][SLDA] fp32 / packed
    char*  KVU = (char*)(sm + 16*SLDA);              // staging union
    float* QR  = (float*)(KVU + KVU_BYTES);          // [16][66]
    float* lrow = QR + 16*66;

    __nv_bfloat16* sKh = (__nv_bfloat16*)KVU;        // [256][72]
    __nv_bfloat16* sKl = sKh + 256*72;
    __nv_bfloat16* sVTh = (__nv_bfloat16*)KVU;       // [64][264] (V^T)
    __nv_bfloat16* sVTl = sVTh + 64*264;

    const int tid = threadIdx.x;
    const int w   = tid >> 5, lane = tid & 31;
    const int g   = lane >> 2, t2 = (lane & 3) * 2;
    const int qt  = blockIdx.x;
    const int bh  = blockIdx.y;
    const int q0  = qt * 16;
    const int kend = q0 + 16;
    const size_t qbase = (size_t)bh * TT;

    float* att = att_mode ? g_att : out_att;

    // ---- load QR rows ----
    for (int i = tid; i < 16*NR; i += 256) {
        int t = i / NR, r = i % NR;
        QR[t*66 + r] = g_qrel[(qbase + q0 + t)*NR + r];
    }

    // ---- Q fragments (hi/lo) straight from gmem ----
    uint32_t qh[4][4], ql[4][4];
    {
        size_t ra = (qbase + q0 + g) * DD;
        size_t rb = (qbase + q0 + g + 8) * DD;
        #pragma unroll
        for (int ks = 0; ks < 4; ks++) {
            int c0 = ks*16 + t2;
            qh[ks][0] = *(const uint32_t*)&g_qh[ra + c0];
            qh[ks][1] = *(const uint32_t*)&g_qh[rb + c0];
            qh[ks][2] = *(const uint32_t*)&g_qh[ra + c0 + 8];
            qh[ks][3] = *(const uint32_t*)&g_qh[rb + c0 + 8];
            ql[ks][0] = *(const uint32_t*)&g_ql[ra + c0];
            ql[ks][1] = *(const uint32_t*)&g_ql[rb + c0];
            ql[ks][2] = *(const uint32_t*)&g_ql[ra + c0 + 8];
            ql[ks][3] = *(const uint32_t*)&g_ql[rb + c0 + 8];
        }
    }
    __syncthreads();

    // ---- S = QK^T (bf16x3 MMA) ----
    for (int kc = 0; kc < kend; kc += 256) {
        int klen = min(256, kend - kc);
        if (kc) __syncthreads();
        for (int i = tid; i < klen*8; i += 256) {
            int r = i >> 3, c = i & 7;
            size_t gsrc = (qbase + kc + r)*DD + c*8;
            *(float4*)&sKh[r*72 + c*8] = *(const float4*)&g_kh[gsrc];
            *(float4*)&sKl[r*72 + c*8] = *(const float4*)&g_kl[gsrc];
        }
        __syncthreads();

        #pragma unroll
        for (int nt = 0; nt < 4; nt++) {
            int n0 = w*32 + nt*8;
            if (n0 < klen) {
                float c4[4] = {0.f, 0.f, 0.f, 0.f};
                #pragma unroll
                for (int ks = 0; ks < 4; ks++) {
                    int rb = (n0 + g)*72 + ks*16 + t2;
                    uint32_t bh2[2], bl2[2];
                    bh2[0] = *(const uint32_t*)&sKh[rb];
                    bh2[1] = *(const uint32_t*)&sKh[rb + 8];
                    bl2[0] = *(const uint32_t*)&sKl[rb];
                    bl2[1] = *(const uint32_t*)&sKl[rb + 8];
                    mma_16816(c4, qh[ks], bh2);
                    mma_16816(c4, qh[ks], bl2);
                    mma_16816(c4, ql[ks], bh2);
                }
                #pragma unroll
                for (int half = 0; half < 2; half++)
                    #pragma unroll
                    for (int cc = 0; cc < 2; cc++) {
                        int t = g + 8*half;
                        int kg = kc + n0 + t2 + cc;
                        int dd = kg - (q0 + t);
                        int idx = min(max(dd, -32), 32) + 32;
                        S[t*SLDA + kg] = (c4[half*2+cc] + QR[t*66 + idx]) * 0.125f;
                    }
            }
        }
    }
    __syncthreads();

    // ---- softmax (fp32, unnormalized exp kept in S) ----
    {
        #pragma unroll
        for (int tt = 0; tt < 2; tt++) {
            int t = w*2 + tt;
            float* Srow = S + t*SLDA;
            int n = q0 + t + 1;
            float m = -1e30f;
            for (int k = lane; k < n; k += 32) m = fmaxf(m, Srow[k]);
            #pragma unroll
            for (int off = 16; off; off >>= 1)
                m = fmaxf(m, __shfl_xor_sync(0xffffffffu, m, off));
            float l = 0.f;
            for (int k = lane; k < n; k += 32) {
                float e = __expf(Srow[k] - m);
                Srow[k] = e;
                l += e;
            }
            #pragma unroll
            for (int off = 16; off; off >>= 1)
                l += __shfl_xor_sync(0xffffffffu, l, off);
            for (int k = n + lane; k < kend; k += 32) Srow[k] = 0.f;
            if (lane == 0) lrow[t] = 1.f / l;
        }
    }
    __syncthreads();

    // ---- att write + in-place repack p -> (ph|pl) bf16x2 ----
    for (int t = 0; t < 16; t++) {
        float inv = lrow[t];
        int n = q0 + t + 1;
        float* dst = att + ((size_t)bh*TT + (q0 + t)) * TT;
        float* Srow = S + t*SLDA;
        uint32_t* Spack = (uint32_t*)Srow;
        for (int k4 = tid; k4 < TT/4; k4 += 256) {
            int k = k4*4;
            float p[4];
            #pragma unroll
            for (int i = 0; i < 4; i++)
                p[i] = (k + i < n) ? Srow[k+i]*inv : 0.f;
            *(float4*)&dst[k] = make_float4(p[0], p[1], p[2], p[3]);
            if (k < kend) {
                #pragma unroll
                for (int i = 0; i < 4; i++) {
                    __nv_bfloat16 ph = __float2bfloat16(p[i]);
                    __nv_bfloat16 pl = __float2bfloat16(p[i] - __bfloat162float(ph));
                    Spack[k+i] = pack_bf2(ph, pl);
                }
            }
        }
    }

    // ---- O = P·V (bf16x3 MMA, warps split keys, reduce at end) ----
    float c8[8][4];
    #pragma unroll
    for (int nt = 0; nt < 8; nt++)
        #pragma unroll
        for (int c = 0; c < 4; c++) c8[nt][c] = 0.f;

    const uint32_t* Su = (const uint32_t*)S;
    for (int kc = 0; kc < kend; kc += 256) {
        int klen = min(256, kend - kc);
        __syncthreads();
        // stage V^T hi/lo (transposed): thread pair-transpose
        {
            int t2p = tid & 127, dh = tid >> 7;
            int tA = 2*t2p;
            if (tA < klen) {
                const uint32_t* sAh2 = (const uint32_t*)&g_vh[(qbase + kc + tA)*DD + dh*32];
                const uint32_t* sBh2 = (const uint32_t*)&g_vh[(qbase + kc + tA + 1)*DD + dh*32];
                const uint32_t* sAl2 = (const uint32_t*)&g_vl[(qbase + kc + tA)*DD + dh*32];
                const uint32_t* sBl2 = (const uint32_t*)&g_vl[(qbase + kc + tA + 1)*DD + dh*32];
                #pragma unroll
                for (int j = 0; j < 16; j++) {
                    uint32_t a = sAh2[j], b = sBh2[j];
                    int d0 = dh*32 + 2*j;
                    *(uint32_t*)&sVTh[d0*264 + tA]     = __byte_perm(a, b, 0x5410);
                    *(uint32_t*)&sVTh[(d0+1)*264 + tA] = __byte_perm(a, b, 0x7632);
                    a = sAl2[j]; b = sBl2[j];
                    *(uint32_t*)&sVTl[d0*264 + tA]     = __byte_perm(a, b, 0x5410);
                    *(uint32_t*)&sVTl[(d0+1)*264 + tA] = __byte_perm(a, b, 0x7632);
                }
            }
        }
        __syncthreads();

        #pragma unroll
        for (int ksl = 0; ksl < 2; ksl++) {
            int kg0 = kc + w*32 + ksl*16;
            if (kg0 < kend) {
                int ca = kg0 + t2;
                uint32_t s00 = Su[g*SLDA + ca],         s01 = Su[g*SLDA + ca + 1];
                uint32_t s10 = Su[(g+8)*SLDA + ca],     s11 = Su[(g+8)*SLDA + ca + 1];
                uint32_t s02 = Su[g*SLDA + ca + 8],     s03 = Su[g*SLDA + ca + 9];
                uint32_t s12 = Su[(g+8)*SLDA + ca + 8], s13 = Su[(g+8)*SLDA + ca + 9];
                uint32_t ah[4], al[4];
                ah[0] = __byte_perm(s00, s01, 0x5410); al[0] = __byte_perm(s00, s01, 0x7632);
                ah[1] = __byte_perm(s10, s11, 0x5410); al[1] = __byte_perm(s10, s11, 0x7632);
                ah[2] = __byte_perm(s02, s03, 0x5410); al[2] = __byte_perm(s02, s03, 0x7632);
                ah[3] = __byte_perm(s12, s13, 0x5410); al[3] = __byte_perm(s12, s13, 0x7632);
                int kloc = w*32 + ksl*16;
                #pragma unroll
                for (int nt = 0; nt < 8; nt++) {
                    int db = (nt*8 + g)*264 + kloc + t2;
                    uint32_t bh2[2], bl2[2];
                    bh2[0] = *(const uint32_t*)&sVTh[db];
                    bh2[1] = *(const uint32_t*)&sVTh[db + 8];
                    bl2[0] = *(const uint32_t*)&sVTl[db];
                    bl2[1] = *(const uint32_t*)&sVTl[db + 8];
                    mma_16816(c8[nt], ah, bh2);
                    mma_16816(c8[nt], ah, bl2);
                    mma_16816(c8[nt], al, bh2);
                }
            }
        }
    }
    __syncthreads();

    // ---- cross-warp reduce + write g_o ----
    float* red = (float*)KVU;    // 8 x [16][64]
    #pragma unroll
    for (int nt = 0; nt < 8; nt++)
        #pragma unroll
        for (int h = 0; h < 2; h++)
            #pragma unroll
            for (int cc = 0; cc < 2; cc++)
                red[w*1024 + (g + 8*h)*64 + nt*8 + t2 + cc] = c8[nt][h*2+cc];
    __syncthreads();
    for (int i = tid; i < 1024; i += 256) {
        float s = 0.f;
        #pragma unroll
        for (int ww = 0; ww < 8; ww++) s += red[ww*1024 + i];
        int t = i >> 6, d = i & 63;
        g_o[((size_t)(bh >> 4)*TT + q0 + t)*CC + (bh & 15)*64 + d] = s;
    }
}

// =====================================================================
extern "C" void kernel_launch(void* const* d_in, const int* in_sizes, int n_in,
                              void* d_out, int out_size)
{
    const float* x      = (const float*)d_in[0];
    const float* w_attn = (const float*)d_in[2];
    const float* b_attn = (const float*)d_in[3];
    const float* w_proj = (const float*)d_in[4];
    const float* b_proj = (const float*)d_in[5];
    const float* rel_k  = (const float*)d_in[6];
    float* out = (float*)d_out;

    const size_t YS = (size_t)BT*CC;
    const size_t AS = (size_t)BH*TT*TT;

    float* y_out = out;
    float* att_base = nullptr;
    int att_mode = 1;
    if ((size_t)out_size >= YS + AS) {
        y_out = out; att_base = out + YS; att_mode = 0;
    } else if ((size_t)out_size == AS) {
        att_base = out; att_mode = 0; y_out = nullptr;
    }

    cudaFuncSetAttribute(attn_kernel,
        cudaFuncAttributeMaxDynamicSharedMemorySize, ATTN_SMEM_BYTES);
    cudaFuncSetAttribute(mma_gemm_kernel<0>,
        cudaFuncAttributeMaxDynamicSharedMemorySize, GEMM_SMEM_BYTES);
    cudaFuncSetAttribute(mma_gemm_kernel<1>,
        cudaFuncAttributeMaxDynamicSharedMemorySize, GEMM_SMEM_BYTES);

    // 1. operand conversion
    split_kernel<0><<<BT*CC/4/256, 256>>>(x);
    wsplit_kernel<0><<<dim3(3*CC/32, CC/32), dim3(32,8)>>>(w_attn, 3*CC);
    wsplit_kernel<1><<<dim3(CC/32,   CC/32), dim3(32,8)>>>(w_proj, CC);
    // 2. QKV projection -> q fp32+bf16, k/v bf16 hi/lo (head-major, +bias)
    mma_gemm_kernel<0><<<dim3(24, 32), 256, GEMM_SMEM_BYTES>>>(b_attn, nullptr);
    // 3. relative-position projections
    qrel_kernel<<<BH*TT/32, 256>>>(rel_k);
    // 4. tensor-core attention -> att + g_o
    attn_kernel<<<dim3(TT/16, BH), 256, ATTN_SMEM_BYTES>>>(att_base, att_mode);
    // 5. split o, output projection -> y
    split_kernel<1><<<BT*CC/4/256, 256>>>(nullptr);
    mma_gemm_kernel<1><<<dim3(8, 32), 256, GEMM_SMEM_BYTES>>>(b_proj, y_out);
}

// round 7
// speedup vs baseline: 1.0087x; 1.0087x over previous
#include <cuda_runtime.h>
#include <cuda_bf16.h>
#include <math.h>
#include <stdint.h>

#define BB 2
#define TT 2048
#define CC 1024
#define HH 16
#define DD 64
#define NR 65                      // 2*MAXREL+1
#define BH (BB*HH)                 // 32
#define BT (BB*TT)                 // 4096

// ---------------- device scratch (no allocations allowed) ----------------
__device__ float g_q[BH*TT*DD];        // fp32 q (for qrel)
__device__ float g_qrel[BH*TT*NR];     // [bh][t][r]
__device__ float g_o[BT*CC];           // pre-proj context
__device__ float g_y[BT*CC];           // fallback y sink
__device__ float g_att[(size_t)BH*TT*TT]; // fallback att sink

// bf16 hi/lo operands
__device__ __nv_bfloat16 g_qh[BH*TT*DD], g_ql[BH*TT*DD];
__device__ __nv_bfloat16 g_kh[BH*TT*DD], g_kl[BH*TT*DD];
__device__ __nv_bfloat16 g_vh[BH*TT*DD], g_vl[BH*TT*DD];
__device__ __nv_bfloat16 g_xa_hi[BT*CC],  g_xa_lo[BT*CC];     // x split   [M][K]
__device__ __nv_bfloat16 g_oa_hi[BT*CC],  g_oa_lo[BT*CC];     // o split   [M][K]
__device__ __nv_bfloat16 g_wta_hi[3*CC*CC], g_wta_lo[3*CC*CC];// w_attn^T  [N][K]
__device__ __nv_bfloat16 g_wtp_hi[CC*CC],   g_wtp_lo[CC*CC];  // w_proj^T  [N][K]

// ===================== mma.sync helper =====================
__device__ __forceinline__ void mma_16816(float* c, const uint32_t* a, const uint32_t* b) {
    asm volatile("mma.sync.aligned.m16n8k16.row.col.f32.bf16.bf16.f32 "
        "{%0,%1,%2,%3}, {%4,%5,%6,%7}, {%8,%9}, {%0,%1,%2,%3};"
        : "+f"(c[0]), "+f"(c[1]), "+f"(c[2]), "+f"(c[3])
        : "r"(a[0]), "r"(a[1]), "r"(a[2]), "r"(a[3]), "r"(b[0]), "r"(b[1]));
}
__device__ __forceinline__ uint32_t pack_bf2(__nv_bfloat16 a, __nv_bfloat16 b) {
    return ((uint32_t)__bfloat16_as_ushort(b) << 16) | __bfloat16_as_ushort(a);
}

// =====================================================================
// Conversion kernels: fp32 -> (hi, lo) bf16 split
// =====================================================================
template<int SRC>   // 0: x param -> g_xa,  1: g_o -> g_oa
__global__ __launch_bounds__(256) void split_kernel(const float* __restrict__ in)
{
    const float* src = (SRC == 0) ? in : (const float*)g_o;
    __nv_bfloat16* hi = (SRC == 0) ? g_xa_hi : g_oa_hi;
    __nv_bfloat16* lo = (SRC == 0) ? g_xa_lo : g_oa_lo;
    int i = blockIdx.x * 256 + threadIdx.x;          // float4 index
    float4 v = ((const float4*)src)[i];
    float a[4] = {v.x, v.y, v.z, v.w};
    __nv_bfloat16 hb[4], lb[4];
    #pragma unroll
    for (int c = 0; c < 4; c++) {
        hb[c] = __float2bfloat16(a[c]);
        lb[c] = __float2bfloat16(a[c] - __bfloat162float(hb[c]));
    }
    ((uint32_t*)hi)[i*2+0] = pack_bf2(hb[0], hb[1]);
    ((uint32_t*)hi)[i*2+1] = pack_bf2(hb[2], hb[3]);
    ((uint32_t*)lo)[i*2+0] = pack_bf2(lb[0], lb[1]);
    ((uint32_t*)lo)[i*2+1] = pack_bf2(lb[2], lb[3]);
}

// W[K=1024, N] -> Wt_hi/lo[N][K] bf16 (transpose + split)
template<int WSEL>  // 0: w_attn -> g_wta, 1: w_proj -> g_wtp
__global__ __launch_bounds__(256) void wsplit_kernel(const float* __restrict__ W, int N)
{
    __shared__ float ts[32][33];
    __nv_bfloat16* hi = (WSEL == 0) ? g_wta_hi : g_wtp_hi;
    __nv_bfloat16* lo = (WSEL == 0) ? g_wta_lo : g_wtp_lo;
    int nx = blockIdx.x * 32, kx = blockIdx.y * 32;
    int tx = threadIdx.x, ty = threadIdx.y;
    #pragma unroll
    for (int j = ty; j < 32; j += 8)
        ts[j][tx] = W[(size_t)(kx + j)*N + nx + tx];
    __syncthreads();
    #pragma unroll
    for (int j = ty; j < 32; j += 8) {
        float v = ts[tx][j];
        __nv_bfloat16 h = __float2bfloat16(v);
        __nv_bfloat16 l = __float2bfloat16(v - __bfloat162float(h));
        hi[(size_t)(nx + j)*CC + kx + tx] = h;
        lo[(size_t)(nx + j)*CC + kx + tx] = l;
    }
}

// =====================================================================
// mma.sync bf16x3 GEMM (unchanged core from R5)
// MODE 0: scatter -> q (fp32+bf16 hi/lo), k/v (bf16 hi/lo), +bias (N=3072)
// MODE 1: A = g_oa, B = g_wtp, out -> y + bias (N=1024)
// =====================================================================
#define LDA 72
#define SM_ARR (128*LDA)
#define GEMM_SMEM_BYTES (4*SM_ARR*2)

template<int MODE>
__global__ __launch_bounds__(256) void mma_gemm_kernel(const float* __restrict__ bias,
                                                       float* __restrict__ outp)
{
    extern __shared__ __nv_bfloat16 sb[];
    __nv_bfloat16* sAh = sb;
    __nv_bfloat16* sAl = sb + SM_ARR;
    __nv_bfloat16* sBh = sb + 2*SM_ARR;
    __nv_bfloat16* sBl = sb + 3*SM_ARR;

    const int tid  = threadIdx.x;
    const int wid  = tid >> 5, lane = tid & 31;
    const int wm   = wid >> 2, wn = wid & 3;
    const int m0   = blockIdx.y * 128;
    const int n0   = blockIdx.x * 128;

    const __nv_bfloat16* Ah = (MODE == 0) ? g_xa_hi : g_oa_hi;
    const __nv_bfloat16* Al = (MODE == 0) ? g_xa_lo : g_oa_lo;
    const __nv_bfloat16* Bh = (MODE == 0) ? g_wta_hi : g_wtp_hi;
    const __nv_bfloat16* Bl = (MODE == 0) ? g_wta_lo : g_wtp_lo;

    float acc[4][4][4];
    #pragma unroll
    for (int i = 0; i < 4; i++)
        #pragma unroll
        for (int j = 0; j < 4; j++)
            #pragma unroll
            for (int c = 0; c < 4; c++) acc[i][j][c] = 0.f;

    const int g  = lane >> 2;
    const int t2 = (lane & 3) * 2;

    for (int kt = 0; kt < 16; kt++) {
        const int k0 = kt * 64;
        #pragma unroll
        for (int it = 0; it < 4; it++) {
            int i = tid + it * 256;
            int r = i >> 3, c8 = i & 7;
            size_t ga = (size_t)(m0 + r) * CC + k0 + c8 * 8;
            size_t gb = (size_t)(n0 + r) * CC + k0 + c8 * 8;
            int so = r * LDA + c8 * 8;
            *(float4*)&sAh[so] = *(const float4*)&Ah[ga];
            *(float4*)&sAl[so] = *(const float4*)&Al[ga];
            *(float4*)&sBh[so] = *(const float4*)&Bh[gb];
            *(float4*)&sBl[so] = *(const float4*)&Bl[gb];
        }
        __syncthreads();

        #pragma unroll
        for (int ks = 0; ks < 4; ks++) {
            const int kb = ks * 16 + t2;
            uint32_t ah[4][4], al[4][4];
            #pragma unroll
            for (int tm = 0; tm < 4; tm++) {
                int r0 = (wm*64 + tm*16 + g) * LDA + kb;
                int r1 = r0 + 8 * LDA;
                ah[tm][0] = *(const uint32_t*)&sAh[r0];
                ah[tm][1] = *(const uint32_t*)&sAh[r1];
                ah[tm][2] = *(const uint32_t*)&sAh[r0 + 8];
                ah[tm][3] = *(const uint32_t*)&sAh[r1 + 8];
                al[tm][0] = *(const uint32_t*)&sAl[r0];
                al[tm][1] = *(const uint32_t*)&sAl[r1];
                al[tm][2] = *(const uint32_t*)&sAl[r0 + 8];
                al[tm][3] = *(const uint32_t*)&sAl[r1 + 8];
            }
            #pragma unroll
            for (int tn = 0; tn < 4; tn++) {
                int rb = (wn*32 + tn*8 + g) * LDA + kb;
                uint32_t bh[2], bl[2];
                bh[0] = *(const uint32_t*)&sBh[rb];
                bh[1] = *(const uint32_t*)&sBh[rb + 8];
                bl[0] = *(const uint32_t*)&sBl[rb];
                bl[1] = *(const uint32_t*)&sBl[rb + 8];
                #pragma unroll
                for (int tm = 0; tm < 4; tm++) {
                    mma_16816(acc[tm][tn], ah[tm], bh);
                    mma_16816(acc[tm][tn], ah[tm], bl);
                    mma_16816(acc[tm][tn], al[tm], bh);
                }
            }
        }
        __syncthreads();
    }

    // ---- epilogue ----
    const int lr = lane >> 2;
    const int lc = (lane & 3) * 2;
    #pragma unroll
    for (int tm = 0; tm < 4; tm++) {
        #pragma unroll
        for (int tn = 0; tn < 4; tn++) {
            int c = n0 + wn*32 + tn*8 + lc;
            float b0 = bias[c], b1 = bias[c+1];
            #pragma unroll
            for (int half = 0; half < 2; half++) {
                int m = m0 + wm*64 + tm*16 + lr + half*8;
                float v0 = acc[tm][tn][half*2+0] + b0;
                float v1 = acc[tm][tn][half*2+1] + b1;
                if (MODE == 0) {
                    int which = c >> 10, hh = (c >> 6) & 15, dd = c & 63;
                    int b_ = m >> 11, t_ = m & 2047;
                    size_t di = ((size_t)(b_*HH + hh)*TT + t_)*DD + dd;
                    __nv_bfloat16 h0 = __float2bfloat16(v0);
                    __nv_bfloat16 h1 = __float2bfloat16(v1);
                    __nv_bfloat16 l0 = __float2bfloat16(v0 - __bfloat162float(h0));
                    __nv_bfloat16 l1 = __float2bfloat16(v1 - __bfloat162float(h1));
                    uint32_t hw = pack_bf2(h0, h1), lw = pack_bf2(l0, l1);
                    if (which == 0) {
                        *(float2*)&g_q[di] = make_float2(v0, v1);
                        *(uint32_t*)&g_qh[di] = hw;
                        *(uint32_t*)&g_ql[di] = lw;
                    } else if (which == 1) {
                        *(uint32_t*)&g_kh[di] = hw;
                        *(uint32_t*)&g_kl[di] = lw;
                    } else {
                        *(uint32_t*)&g_vh[di] = hw;
                        *(uint32_t*)&g_vl[di] = lw;
                    }
                } else {
                    float* dst = outp ? outp : g_y;
                    *(float2*)&dst[(size_t)m*CC + c] = make_float2(v0, v1);
                }
            }
        }
    }
}

// =====================================================================
// qrel[bh*T + t][r] = q[bh][t][:] . rel_k_table[r][:]
// =====================================================================
__device__ __forceinline__ float dot4(float4 a, float4 b) {
    return a.x*b.x + a.y*b.y + a.z*b.z + a.w*b.w;
}

__global__ __launch_bounds__(256) void qrel_kernel(const float* __restrict__ rel)
{
    __shared__ float rs[NR*64];
    __shared__ float qs[32*64];
    const int tid = threadIdx.x;
    const int r0  = blockIdx.x * 32;

    for (int i = tid; i < NR*16; i += 256)
        ((float4*)rs)[i] = ((const float4*)rel)[i];
    for (int i = tid; i < 32*16; i += 256) {
        int t = i >> 4, d4 = i & 15;
        *(float4*)&qs[t*64 + d4*4] = *(const float4*)&g_q[(size_t)(r0+t)*64 + d4*4];
    }
    __syncthreads();

    for (int i = tid; i < 32*NR; i += 256) {
        int t = i / NR, r = i % NR;
        const float4* qq = (const float4*)&qs[t*64];
        const float4* rr = (const float4*)&rs[r*64];
        float acc = 0.f;
        #pragma unroll
        for (int d4 = 0; d4 < 16; d4++) acc += dot4(qq[d4], rr[d4]);
        g_qrel[(size_t)(r0+t)*NR + r] = acc;
    }
}

// =====================================================================
// Tensor-core attention: block = (qt, bh), 16 q-rows.
//  S = QK^T via mma.sync bf16x3 (warps split keys), +rel, scale -> S smem fp32
//  softmax fp32 in smem
//  att write + in-place repack of p as (ph|pl) bf16x2 in S slots
//  O = P·V via mma.sync bf16x3 (V^T staged hi/lo, warps split keys, smem reduce)
// =====================================================================
#define SLDA 2056
#define KVU_BYTES 73728
#define ATTN_SMEM_BYTES (16*SLDA*4 + KVU_BYTES + 16*66*4 + 64)

__global__ __launch_bounds__(256) void attn_kernel(float* __restrict__ out_att, int att_mode)
{
    extern __shared__ float sm[];
    float* S   = sm;                                 // [16][SLDA] fp32 / packed
    char*  KVU = (char*)(sm + 16*SLDA);              // staging union
    float* QR  = (float*)(KVU + KVU_BYTES);          // [16][66]
    float* lrow = QR + 16*66;

    __nv_bfloat16* sKh = (__nv_bfloat16*)KVU;        // [256][72]
    __nv_bfloat16* sKl = sKh + 256*72;
    __nv_bfloat16* sVTh = (__nv_bfloat16*)KVU;       // [64][264] (V^T)
    __nv_bfloat16* sVTl = sVTh + 64*264;

    const int tid = threadIdx.x;
    const int w   = tid >> 5, lane = tid & 31;
    const int g   = lane >> 2, t2 = (lane & 3) * 2;
    const int qt  = blockIdx.x;
    const int bh  = blockIdx.y;
    const int q0  = qt * 16;
    const int kend = q0 + 16;
    const size_t qbase = (size_t)bh * TT;

    float* att = att_mode ? g_att : out_att;

    // ---- load QR rows ----
    for (int i = tid; i < 16*NR; i += 256) {
        int t = i / NR, r = i % NR;
        QR[t*66 + r] = g_qrel[(qbase + q0 + t)*NR + r];
    }

    // ---- Q fragments (hi/lo) straight from gmem ----
    uint32_t qh[4][4], ql[4][4];
    {
        size_t ra = (qbase + q0 + g) * DD;
        size_t rb = (qbase + q0 + g + 8) * DD;
        #pragma unroll
        for (int ks = 0; ks < 4; ks++) {
            int c0 = ks*16 + t2;
            qh[ks][0] = *(const uint32_t*)&g_qh[ra + c0];
            qh[ks][1] = *(const uint32_t*)&g_qh[rb + c0];
            qh[ks][2] = *(const uint32_t*)&g_qh[ra + c0 + 8];
            qh[ks][3] = *(const uint32_t*)&g_qh[rb + c0 + 8];
            ql[ks][0] = *(const uint32_t*)&g_ql[ra + c0];
            ql[ks][1] = *(const uint32_t*)&g_ql[rb + c0];
            ql[ks][2] = *(const uint32_t*)&g_ql[ra + c0 + 8];
            ql[ks][3] = *(const uint32_t*)&g_ql[rb + c0 + 8];
        }
    }
    __syncthreads();

    // ---- S = QK^T (bf16x3 MMA) ----
    for (int kc = 0; kc < kend; kc += 256) {
        int klen = min(256, kend - kc);
        if (kc) __syncthreads();
        for (int i = tid; i < klen*8; i += 256) {
            int r = i >> 3, c = i & 7;
            size_t gsrc = (qbase + kc + r)*DD + c*8;
            *(float4*)&sKh[r*72 + c*8] = *(const float4*)&g_kh[gsrc];
            *(float4*)&sKl[r*72 + c*8] = *(const float4*)&g_kl[gsrc];
        }
        __syncthreads();

        #pragma unroll
        for (int nt = 0; nt < 4; nt++) {
            int n0 = w*32 + nt*8;
            if (n0 < klen) {
                float c4[4] = {0.f, 0.f, 0.f, 0.f};
                #pragma unroll
                for (int ks = 0; ks < 4; ks++) {
                    int rb = (n0 + g)*72 + ks*16 + t2;
                    uint32_t bh2[2], bl2[2];
                    bh2[0] = *(const uint32_t*)&sKh[rb];
                    bh2[1] = *(const uint32_t*)&sKh[rb + 8];
                    bl2[0] = *(const uint32_t*)&sKl[rb];
                    bl2[1] = *(const uint32_t*)&sKl[rb + 8];
                    mma_16816(c4, qh[ks], bh2);
                    mma_16816(c4, qh[ks], bl2);
                    mma_16816(c4, ql[ks], bh2);
                }
                #pragma unroll
                for (int half = 0; half < 2; half++)
                    #pragma unroll
                    for (int cc = 0; cc < 2; cc++) {
                        int t = g + 8*half;
                        int kg = kc + n0 + t2 + cc;
                        int dd = kg - (q0 + t);
                        int idx = min(max(dd, -32), 32) + 32;
                        S[t*SLDA + kg] = (c4[half*2+cc] + QR[t*66 + idx]) * 0.125f;
                    }
            }
        }
    }
    __syncthreads();

    // ---- softmax (fp32, unnormalized exp kept in S) ----
    {
        #pragma unroll
        for (int tt = 0; tt < 2; tt++) {
            int t = w*2 + tt;
            float* Srow = S + t*SLDA;
            int n = q0 + t + 1;
            float m = -1e30f;
            for (int k = lane; k < n; k += 32) m = fmaxf(m, Srow[k]);
            #pragma unroll
            for (int off = 16; off; off >>= 1)
                m = fmaxf(m, __shfl_xor_sync(0xffffffffu, m, off));
            float l = 0.f;
            for (int k = lane; k < n; k += 32) {
                float e = __expf(Srow[k] - m);
                Srow[k] = e;
                l += e;
            }
            #pragma unroll
            for (int off = 16; off; off >>= 1)
                l += __shfl_xor_sync(0xffffffffu, l, off);
            for (int k = n + lane; k < kend; k += 32) Srow[k] = 0.f;
            if (lane == 0) lrow[t] = 1.f / l;
        }
    }
    __syncthreads();

    // ---- att write + in-place repack p -> (ph|pl) bf16x2 ----
    for (int t = 0; t < 16; t++) {
        float inv = lrow[t];
        int n = q0 + t + 1;
        float* dst = att + ((size_t)bh*TT + (q0 + t)) * TT;
        float* Srow = S + t*SLDA;
        uint32_t* Spack = (uint32_t*)Srow;
        for (int k4 = tid; k4 < TT/4; k4 += 256) {
            int k = k4*4;
            float p[4];
            #pragma unroll
            for (int i = 0; i < 4; i++)
                p[i] = (k + i < n) ? Srow[k+i]*inv : 0.f;
            *(float4*)&dst[k] = make_float4(p[0], p[1], p[2], p[3]);
            if (k < kend) {
                #pragma unroll
                for (int i = 0; i < 4; i++) {
                    __nv_bfloat16 ph = __float2bfloat16(p[i]);
                    __nv_bfloat16 pl = __float2bfloat16(p[i] - __bfloat162float(ph));
                    Spack[k+i] = pack_bf2(ph, pl);
                }
            }
        }
    }

    // ---- O = P·V (bf16x3 MMA, warps split keys, reduce at end) ----
    float c8[8][4];
    #pragma unroll
    for (int nt = 0; nt < 8; nt++)
        #pragma unroll
        for (int c = 0; c < 4; c++) c8[nt][c] = 0.f;

    const uint32_t* Su = (const uint32_t*)S;
    for (int kc = 0; kc < kend; kc += 256) {
        int klen = min(256, kend - kc);
        __syncthreads();
        // stage V^T hi/lo (transposed): thread pair-transpose
        {
            int t2p = tid & 127, dh = tid >> 7;
            int tA = 2*t2p;
            if (tA < klen) {
                const uint32_t* sAh2 = (const uint32_t*)&g_vh[(qbase + kc + tA)*DD + dh*32];
                const uint32_t* sBh2 = (const uint32_t*)&g_vh[(qbase + kc + tA + 1)*DD + dh*32];
                const uint32_t* sAl2 = (const uint32_t*)&g_vl[(qbase + kc + tA)*DD + dh*32];
                const uint32_t* sBl2 = (const uint32_t*)&g_vl[(qbase + kc + tA + 1)*DD + dh*32];
                #pragma unroll
                for (int j = 0; j < 16; j++) {
                    uint32_t a = sAh2[j], b = sBh2[j];
                    int d0 = dh*32 + 2*j;
                    *(uint32_t*)&sVTh[d0*264 + tA]     = __byte_perm(a, b, 0x5410);
                    *(uint32_t*)&sVTh[(d0+1)*264 + tA] = __byte_perm(a, b, 0x7632);
                    a = sAl2[j]; b = sBl2[j];
                    *(uint32_t*)&sVTl[d0*264 + tA]     = __byte_perm(a, b, 0x5410);
                    *(uint32_t*)&sVTl[(d0+1)*264 + tA] = __byte_perm(a, b, 0x7632);
                }
            }
        }
        __syncthreads();

        #pragma unroll
        for (int ksl = 0; ksl < 2; ksl++) {
            int kg0 = kc + w*32 + ksl*16;
            if (kg0 < kend) {
                int ca = kg0 + t2;
                uint32_t s00 = Su[g*SLDA + ca],         s01 = Su[g*SLDA + ca + 1];
                uint32_t s10 = Su[(g+8)*SLDA + ca],     s11 = Su[(g+8)*SLDA + ca + 1];
                uint32_t s02 = Su[g*SLDA + ca + 8],     s03 = Su[g*SLDA + ca + 9];
                uint32_t s12 = Su[(g+8)*SLDA + ca + 8], s13 = Su[(g+8)*SLDA + ca + 9];
                uint32_t ah[4], al[4];
                ah[0] = __byte_perm(s00, s01, 0x5410); al[0] = __byte_perm(s00, s01, 0x7632);
                ah[1] = __byte_perm(s10, s11, 0x5410); al[1] = __byte_perm(s10, s11, 0x7632);
                ah[2] = __byte_perm(s02, s03, 0x5410); al[2] = __byte_perm(s02, s03, 0x7632);
                ah[3] = __byte_perm(s12, s13, 0x5410); al[3] = __byte_perm(s12, s13, 0x7632);
                int kloc = w*32 + ksl*16;
                #pragma unroll
                for (int nt = 0; nt < 8; nt++) {
                    int db = (nt*8 + g)*264 + kloc + t2;
                    uint32_t bh2[2], bl2[2];
                    bh2[0] = *(const uint32_t*)&sVTh[db];
                    bh2[1] = *(const uint32_t*)&sVTh[db + 8];
                    bl2[0] = *(const uint32_t*)&sVTl[db];
                    bl2[1] = *(const uint32_t*)&sVTl[db + 8];
                    mma_16816(c8[nt], ah, bh2);
                    mma_16816(c8[nt], ah, bl2);
                    mma_16816(c8[nt], al, bh2);
                }
            }
        }
    }
    __syncthreads();

    // ---- cross-warp reduce + write g_o ----
    float* red = (float*)KVU;    // 8 x [16][64]
    #pragma unroll
    for (int nt = 0; nt < 8; nt++)
        #pragma unroll
        for (int h = 0; h < 2; h++)
            #pragma unroll
            for (int cc = 0; cc < 2; cc++)
                red[w*1024 + (g + 8*h)*64 + nt*8 + t2 + cc] = c8[nt][h*2+cc];
    __syncthreads();
    for (int i = tid; i < 1024; i += 256) {
        float s = 0.f;
        #pragma unroll
        for (int ww = 0; ww < 8; ww++) s += red[ww*1024 + i];
        int t = i >> 6, d = i & 63;
        g_o[((size_t)(bh >> 4)*TT + q0 + t)*CC + (bh & 15)*64 + d] = s;
    }
}

// =====================================================================
extern "C" void kernel_launch(void* const* d_in, const int* in_sizes, int n_in,
                              void* d_out, int out_size)
{
    const float* x      = (const float*)d_in[0];
    const float* w_attn = (const float*)d_in[2];
    const float* b_attn = (const float*)d_in[3];
    const float* w_proj = (const float*)d_in[4];
    const float* b_proj = (const float*)d_in[5];
    const float* rel_k  = (const float*)d_in[6];
    float* out = (float*)d_out;

    const size_t YS = (size_t)BT*CC;
    const size_t AS = (size_t)BH*TT*TT;

    float* y_out = out;
    float* att_base = nullptr;
    int att_mode = 1;
    if ((size_t)out_size >= YS + AS) {
        y_out = out; att_base = out + YS; att_mode = 0;
    } else if ((size_t)out_size == AS) {
        att_base = out; att_mode = 0; y_out = nullptr;
    }

    cudaFuncSetAttribute(attn_kernel,
        cudaFuncAttributeMaxDynamicSharedMemorySize, ATTN_SMEM_BYTES);
    cudaFuncSetAttribute(mma_gemm_kernel<0>,
        cudaFuncAttributeMaxDynamicSharedMemorySize, GEMM_SMEM_BYTES);
    cudaFuncSetAttribute(mma_gemm_kernel<1>,
        cudaFuncAttributeMaxDynamicSharedMemorySize, GEMM_SMEM_BYTES);

    // 1. operand conversion
    split_kernel<0><<<BT*CC/4/256, 256>>>(x);
    wsplit_kernel<0><<<dim3(3*CC/32, CC/32), dim3(32,8)>>>(w_attn, 3*CC);
    wsplit_kernel<1><<<dim3(CC/32,   CC/32), dim3(32,8)>>>(w_proj, CC);
    // 2. QKV projection -> q fp32+bf16, k/v bf16 hi/lo (head-major, +bias)
    mma_gemm_kernel<0><<<dim3(24, 32), 256, GEMM_SMEM_BYTES>>>(b_attn, nullptr);
    // 3. relative-position projections
    qrel_kernel<<<BH*TT/32, 256>>>(rel_k);
    // 4. tensor-core attention -> att + g_o
    attn_kernel<<<dim3(TT/16, BH), 256, ATTN_SMEM_BYTES>>>(att_base, att_mode);
    // 5. split o, output projection -> y
    split_kernel<1><<<BT*CC/4/256, 256>>>(nullptr);
    mma_gemm_kernel<1><<<dim3(8, 32), 256, GEMM_SMEM_BYTES>>>(b_proj, y_out);
}

// round 8
// speedup vs baseline: 2.1601x; 2.1414x over previous
#include <cuda_runtime.h>
#include <cuda_bf16.h>
#include <math.h>
#include <stdint.h>

#define BB 2
#define TT 2048
#define CC 1024
#define HH 16
#define DD 64
#define NR 65                      // 2*MAXREL+1
#define BH (BB*HH)                 // 32
#define BT (BB*TT)                 // 4096
#define BLKM 128                   // q-rows per attention CTA

// ---------------- device scratch ----------------
__device__ float g_q[BH*TT*DD];        // fp32 q (for qrel)
__device__ float g_qrel[BH*TT*NR];     // [bh][t][r]
__device__ float g_o[BT*CC];           // pre-proj context
__device__ float g_y[BT*CC];           // fallback y sink
__device__ float g_att[(size_t)BH*TT*TT]; // fallback att sink

// bf16 hi/lo operands
__device__ __nv_bfloat16 g_qh[BH*TT*DD], g_ql[BH*TT*DD];   // [bh][t][d]
__device__ __nv_bfloat16 g_kh[BH*TT*DD], g_kl[BH*TT*DD];   // [bh][t][d]
__device__ __nv_bfloat16 g_vth[BH*DD*TT], g_vtl[BH*DD*TT]; // V^T [bh][d][t]
__device__ __nv_bfloat16 g_xa_hi[BT*CC],  g_xa_lo[BT*CC];
__device__ __nv_bfloat16 g_oa_hi[BT*CC],  g_oa_lo[BT*CC];
__device__ __nv_bfloat16 g_wta_hi[3*CC*CC], g_wta_lo[3*CC*CC];
__device__ __nv_bfloat16 g_wtp_hi[CC*CC],   g_wtp_lo[CC*CC];

// ===================== mma.sync helpers =====================
__device__ __forceinline__ void mma_16816(float* c, const uint32_t* a, const uint32_t* b) {
    asm volatile("mma.sync.aligned.m16n8k16.row.col.f32.bf16.bf16.f32 "
        "{%0,%1,%2,%3}, {%4,%5,%6,%7}, {%8,%9}, {%0,%1,%2,%3};"
        : "+f"(c[0]), "+f"(c[1]), "+f"(c[2]), "+f"(c[3])
        : "r"(a[0]), "r"(a[1]), "r"(a[2]), "r"(a[3]), "r"(b[0]), "r"(b[1]));
}
__device__ __forceinline__ uint32_t pack_bf2(__nv_bfloat16 a, __nv_bfloat16 b) {
    return ((uint32_t)__bfloat16_as_ushort(b) << 16) | __bfloat16_as_ushort(a);
}
__device__ __forceinline__ uint32_t pack_hi_lo(float p0, float p1, uint32_t& lo) {
    __nv_bfloat16 h0 = __float2bfloat16(p0), h1 = __float2bfloat16(p1);
    __nv_bfloat16 l0 = __float2bfloat16(p0 - __bfloat162float(h0));
    __nv_bfloat16 l1 = __float2bfloat16(p1 - __bfloat162float(h1));
    lo = pack_bf2(l0, l1);
    return pack_bf2(h0, h1);
}

// =====================================================================
// Conversion kernels
// =====================================================================
template<int SRC>   // 0: x param -> g_xa,  1: g_o -> g_oa
__global__ __launch_bounds__(256) void split_kernel(const float* __restrict__ in)
{
    const float* src = (SRC == 0) ? in : (const float*)g_o;
    __nv_bfloat16* hi = (SRC == 0) ? g_xa_hi : g_oa_hi;
    __nv_bfloat16* lo = (SRC == 0) ? g_xa_lo : g_oa_lo;
    int i = blockIdx.x * 256 + threadIdx.x;
    float4 v = ((const float4*)src)[i];
    float a[4] = {v.x, v.y, v.z, v.w};
    __nv_bfloat16 hb[4], lb[4];
    #pragma unroll
    for (int c = 0; c < 4; c++) {
        hb[c] = __float2bfloat16(a[c]);
        lb[c] = __float2bfloat16(a[c] - __bfloat162float(hb[c]));
    }
    ((uint32_t*)hi)[i*2+0] = pack_bf2(hb[0], hb[1]);
    ((uint32_t*)hi)[i*2+1] = pack_bf2(hb[2], hb[3]);
    ((uint32_t*)lo)[i*2+0] = pack_bf2(lb[0], lb[1]);
    ((uint32_t*)lo)[i*2+1] = pack_bf2(lb[2], lb[3]);
}

template<int WSEL>  // 0: w_attn -> g_wta, 1: w_proj -> g_wtp
__global__ __launch_bounds__(256) void wsplit_kernel(const float* __restrict__ W, int N)
{
    __shared__ float ts[32][33];
    __nv_bfloat16* hi = (WSEL == 0) ? g_wta_hi : g_wtp_hi;
    __nv_bfloat16* lo = (WSEL == 0) ? g_wta_lo : g_wtp_lo;
    int nx = blockIdx.x * 32, kx = blockIdx.y * 32;
    int tx = threadIdx.x, ty = threadIdx.y;
    #pragma unroll
    for (int j = ty; j < 32; j += 8)
        ts[j][tx] = W[(size_t)(kx + j)*N + nx + tx];
    __syncthreads();
    #pragma unroll
    for (int j = ty; j < 32; j += 8) {
        float v = ts[tx][j];
        __nv_bfloat16 h = __float2bfloat16(v);
        __nv_bfloat16 l = __float2bfloat16(v - __bfloat162float(h));
        hi[(size_t)(nx + j)*CC + kx + tx] = h;
        lo[(size_t)(nx + j)*CC + kx + tx] = l;
    }
}

// =====================================================================
// mma.sync bf16x3 GEMM (verified R5 core)
// MODE 0: scatter -> q (fp32+bf16), k (bf16), v (bf16 TRANSPOSED), +bias
// MODE 1: A = g_oa, B = g_wtp, out -> y + bias (N=1024)
// =====================================================================
#define LDA 72
#define SM_ARR (128*LDA)
#define GEMM_SMEM_BYTES (4*SM_ARR*2)

template<int MODE>
__global__ __launch_bounds__(256) void mma_gemm_kernel(const float* __restrict__ bias,
                                                       float* __restrict__ outp)
{
    extern __shared__ __nv_bfloat16 sb[];
    __nv_bfloat16* sAh = sb;
    __nv_bfloat16* sAl = sb + SM_ARR;
    __nv_bfloat16* sBh = sb + 2*SM_ARR;
    __nv_bfloat16* sBl = sb + 3*SM_ARR;

    const int tid  = threadIdx.x;
    const int wid  = tid >> 5, lane = tid & 31;
    const int wm   = wid >> 2, wn = wid & 3;
    const int m0   = blockIdx.y * 128;
    const int n0   = blockIdx.x * 128;

    const __nv_bfloat16* Ah = (MODE == 0) ? g_xa_hi : g_oa_hi;
    const __nv_bfloat16* Al = (MODE == 0) ? g_xa_lo : g_oa_lo;
    const __nv_bfloat16* Bh = (MODE == 0) ? g_wta_hi : g_wtp_hi;
    const __nv_bfloat16* Bl = (MODE == 0) ? g_wta_lo : g_wtp_lo;

    float acc[4][4][4];
    #pragma unroll
    for (int i = 0; i < 4; i++)
        #pragma unroll
        for (int j = 0; j < 4; j++)
            #pragma unroll
            for (int c = 0; c < 4; c++) acc[i][j][c] = 0.f;

    const int g  = lane >> 2;
    const int t2 = (lane & 3) * 2;

    for (int kt = 0; kt < 16; kt++) {
        const int k0 = kt * 64;
        #pragma unroll
        for (int it = 0; it < 4; it++) {
            int i = tid + it * 256;
            int r = i >> 3, c8 = i & 7;
            size_t ga = (size_t)(m0 + r) * CC + k0 + c8 * 8;
            size_t gb = (size_t)(n0 + r) * CC + k0 + c8 * 8;
            int so = r * LDA + c8 * 8;
            *(float4*)&sAh[so] = *(const float4*)&Ah[ga];
            *(float4*)&sAl[so] = *(const float4*)&Al[ga];
            *(float4*)&sBh[so] = *(const float4*)&Bh[gb];
            *(float4*)&sBl[so] = *(const float4*)&Bl[gb];
        }
        __syncthreads();

        #pragma unroll
        for (int ks = 0; ks < 4; ks++) {
            const int kb = ks * 16 + t2;
            uint32_t ah[4][4], al[4][4];
            #pragma unroll
            for (int tm = 0; tm < 4; tm++) {
                int r0 = (wm*64 + tm*16 + g) * LDA + kb;
                int r1 = r0 + 8 * LDA;
                ah[tm][0] = *(const uint32_t*)&sAh[r0];
                ah[tm][1] = *(const uint32_t*)&sAh[r1];
                ah[tm][2] = *(const uint32_t*)&sAh[r0 + 8];
                ah[tm][3] = *(const uint32_t*)&sAh[r1 + 8];
                al[tm][0] = *(const uint32_t*)&sAl[r0];
                al[tm][1] = *(const uint32_t*)&sAl[r1];
                al[tm][2] = *(const uint32_t*)&sAl[r0 + 8];
                al[tm][3] = *(const uint32_t*)&sAl[r1 + 8];
            }
            #pragma unroll
            for (int tn = 0; tn < 4; tn++) {
                int rb = (wn*32 + tn*8 + g) * LDA + kb;
                uint32_t bh[2], bl[2];
                bh[0] = *(const uint32_t*)&sBh[rb];
                bh[1] = *(const uint32_t*)&sBh[rb + 8];
                bl[0] = *(const uint32_t*)&sBl[rb];
                bl[1] = *(const uint32_t*)&sBl[rb + 8];
                #pragma unroll
                for (int tm = 0; tm < 4; tm++) {
                    mma_16816(acc[tm][tn], ah[tm], bh);
                    mma_16816(acc[tm][tn], ah[tm], bl);
                    mma_16816(acc[tm][tn], al[tm], bh);
                }
            }
        }
        __syncthreads();
    }

    // ---- epilogue ----
    const int lr = lane >> 2;
    const int lc = (lane & 3) * 2;
    #pragma unroll
    for (int tm = 0; tm < 4; tm++) {
        #pragma unroll
        for (int tn = 0; tn < 4; tn++) {
            int c = n0 + wn*32 + tn*8 + lc;
            float b0 = bias[c], b1 = bias[c+1];
            #pragma unroll
            for (int half = 0; half < 2; half++) {
                int m = m0 + wm*64 + tm*16 + lr + half*8;
                float v0 = acc[tm][tn][half*2+0] + b0;
                float v1 = acc[tm][tn][half*2+1] + b1;
                if (MODE == 0) {
                    int which = c >> 10, hh = (c >> 6) & 15, dd = c & 63;
                    int b_ = m >> 11, t_ = m & 2047;
                    int bhx = b_*HH + hh;
                    __nv_bfloat16 h0 = __float2bfloat16(v0);
                    __nv_bfloat16 h1 = __float2bfloat16(v1);
                    __nv_bfloat16 l0 = __float2bfloat16(v0 - __bfloat162float(h0));
                    __nv_bfloat16 l1 = __float2bfloat16(v1 - __bfloat162float(h1));
                    if (which == 0) {
                        size_t di = ((size_t)bhx*TT + t_)*DD + dd;
                        *(float2*)&g_q[di] = make_float2(v0, v1);
                        *(uint32_t*)&g_qh[di] = pack_bf2(h0, h1);
                        *(uint32_t*)&g_ql[di] = pack_bf2(l0, l1);
                    } else if (which == 1) {
                        size_t di = ((size_t)bhx*TT + t_)*DD + dd;
                        *(uint32_t*)&g_kh[di] = pack_bf2(h0, h1);
                        *(uint32_t*)&g_kl[di] = pack_bf2(l0, l1);
                    } else {
                        // V transposed: [bh][d][t]
                        size_t vb = (size_t)bhx*DD;
                        g_vth[(vb + dd    )*TT + t_] = h0;
                        g_vth[(vb + dd + 1)*TT + t_] = h1;
                        g_vtl[(vb + dd    )*TT + t_] = l0;
                        g_vtl[(vb + dd + 1)*TT + t_] = l1;
                    }
                } else {
                    float* dst = outp ? outp : g_y;
                    *(float2*)&dst[(size_t)m*CC + c] = make_float2(v0, v1);
                }
            }
        }
    }
}

// =====================================================================
// qrel
// =====================================================================
__device__ __forceinline__ float dot4(float4 a, float4 b) {
    return a.x*b.x + a.y*b.y + a.z*b.z + a.w*b.w;
}

__global__ __launch_bounds__(256) void qrel_kernel(const float* __restrict__ rel)
{
    __shared__ float rs[NR*64];
    __shared__ float qs[32*64];
    const int tid = threadIdx.x;
    const int r0  = blockIdx.x * 32;

    for (int i = tid; i < NR*16; i += 256)
        ((float4*)rs)[i] = ((const float4*)rel)[i];
    for (int i = tid; i < 32*16; i += 256) {
        int t = i >> 4, d4 = i & 15;
        *(float4*)&qs[t*64 + d4*4] = *(const float4*)&g_q[(size_t)(r0+t)*64 + d4*4];
    }
    __syncthreads();

    for (int i = tid; i < 32*NR; i += 256) {
        int t = i / NR, r = i % NR;
        const float4* qq = (const float4*)&qs[t*64];
        const float4* rr = (const float4*)&rs[r*64];
        float acc = 0.f;
        #pragma unroll
        for (int d4 = 0; d4 < 16; d4++) acc += dot4(qq[d4], rr[d4]);
        g_qrel[(size_t)(r0+t)*NR + r] = acc;
    }
}

// =====================================================================
// Flash-style tensor-core attention: 128 q-rows/CTA, 2 passes.
// Warp w owns rows q0+16w .. q0+16w+15. Q frags + O accum in registers.
// =====================================================================
#define SKW 72          // K smem row pitch (bf16)
#define SVW 136         // V^T smem row pitch (bf16)
#define ATTN_SMEM_BYTES (2*128*SKW*2 + 2*64*SVW*2 + 128*66*4 + 64)

__global__ __launch_bounds__(256) void attn_kernel(float* __restrict__ out_att, int att_mode)
{
    extern __shared__ char smc[];
    __nv_bfloat16* sKh = (__nv_bfloat16*)smc;          // [128][72]
    __nv_bfloat16* sKl = sKh + 128*SKW;
    __nv_bfloat16* sVh = sKl + 128*SKW;                // [64][136]
    __nv_bfloat16* sVl = sVh + 64*SVW;
    float* QR = (float*)(sVl + 64*SVW);                // [128][66]

    const int tid = threadIdx.x, w = tid >> 5, lane = tid & 31;
    const int g = lane >> 2, t2 = (lane & 3) * 2;
    const int q0 = blockIdx.x * BLKM;
    const int bh = blockIdx.y;
    const int kend = q0 + BLKM;
    const size_t qbase = (size_t)bh * TT;
    float* att = att_mode ? g_att : out_att;

    // QR rows for this block
    for (int i = tid; i < BLKM*NR; i += 256) {
        int t = i / NR, r = i % NR;
        QR[t*66 + r] = g_qrel[(qbase + q0 + t)*NR + r];
    }

    const int tr0 = w*16 + g;          // local row
    const int r0 = q0 + tr0;           // global row (lane's row pair: r0, r0+8)
    const int r1 = r0 + 8;
    const int wmax = q0 + w*16 + 15;   // warp's max row

    // Q fragments (hi/lo) from gmem
    uint32_t qfh[4][4], qfl[4][4];
    {
        size_t ra = (qbase + (size_t)r0) * DD;
        size_t rb = ra + 8*DD;
        #pragma unroll
        for (int ks = 0; ks < 4; ks++) {
            int c0 = ks*16 + t2;
            qfh[ks][0] = *(const uint32_t*)&g_qh[ra + c0];
            qfh[ks][1] = *(const uint32_t*)&g_qh[rb + c0];
            qfh[ks][2] = *(const uint32_t*)&g_qh[ra + c0 + 8];
            qfh[ks][3] = *(const uint32_t*)&g_qh[rb + c0 + 8];
            qfl[ks][0] = *(const uint32_t*)&g_ql[ra + c0];
            qfl[ks][1] = *(const uint32_t*)&g_ql[rb + c0];
            qfl[ks][2] = *(const uint32_t*)&g_ql[ra + c0 + 8];
            qfl[ks][3] = *(const uint32_t*)&g_ql[rb + c0 + 8];
        }
    }

    // ================= PASS A: row max + sum =================
    float m0v = -1e30f, m1v = -1e30f, l0v = 0.f, l1v = 0.f;
    for (int kc = 0; kc < kend; kc += 128) {
        __syncthreads();
        for (int i = tid; i < 128*8; i += 256) {
            int r = i >> 3, c = i & 7;
            size_t gs = (qbase + kc + r)*DD + c*8;
            *(float4*)&sKh[r*SKW + c*8] = *(const float4*)&g_kh[gs];
            *(float4*)&sKl[r*SKW + c*8] = *(const float4*)&g_kl[gs];
        }
        __syncthreads();

        int ntm = (wmax >= kc) ? min(16, ((wmax - kc) >> 3) + 1) : 0;
        for (int nt = 0; nt < ntm; nt++) {
            float c4[4] = {0.f, 0.f, 0.f, 0.f};
            #pragma unroll
            for (int ks = 0; ks < 4; ks++) {
                int rb = (nt*8 + g)*SKW + ks*16 + t2;
                uint32_t bh2[2], bl2[2];
                bh2[0] = *(const uint32_t*)&sKh[rb];
                bh2[1] = *(const uint32_t*)&sKh[rb + 8];
                bl2[0] = *(const uint32_t*)&sKl[rb];
                bl2[1] = *(const uint32_t*)&sKl[rb + 8];
                mma_16816(c4, qfh[ks], bh2);
                mma_16816(c4, qfh[ks], bl2);
                mma_16816(c4, qfl[ks], bh2);
            }
            int kg = kc + nt*8 + t2;
            // row 0
            {
                int d0 = min(max(kg - r0, -32), 32) + 32;
                int d1 = min(max(kg + 1 - r0, -32), 32) + 32;
                float s0 = (kg     <= r0) ? (c4[0] + QR[tr0*66 + d0]) * 0.125f : -1e30f;
                float s1 = (kg + 1 <= r0) ? (c4[1] + QR[tr0*66 + d1]) * 0.125f : -1e30f;
                float mx = fmaxf(s0, s1);
                if (mx > m0v) { l0v *= __expf(m0v - mx); m0v = mx; }
                l0v += __expf(s0 - m0v) + __expf(s1 - m0v);
            }
            // row 1
            {
                int d0 = min(max(kg - r1, -32), 32) + 32;
                int d1 = min(max(kg + 1 - r1, -32), 32) + 32;
                float s0 = (kg     <= r1) ? (c4[2] + QR[(tr0+8)*66 + d0]) * 0.125f : -1e30f;
                float s1 = (kg + 1 <= r1) ? (c4[3] + QR[(tr0+8)*66 + d1]) * 0.125f : -1e30f;
                float mx = fmaxf(s0, s1);
                if (mx > m1v) { l1v *= __expf(m1v - mx); m1v = mx; }
                l1v += __expf(s0 - m1v) + __expf(s1 - m1v);
            }
        }
    }
    // lane merge (4 lanes share each row)
    #pragma unroll
    for (int off = 1; off <= 2; off <<= 1) {
        float mo = __shfl_xor_sync(0xffffffffu, m0v, off);
        float lo2 = __shfl_xor_sync(0xffffffffu, l0v, off);
        float mn = fmaxf(m0v, mo);
        l0v = l0v*__expf(m0v - mn) + lo2*__expf(mo - mn);
        m0v = mn;
        mo = __shfl_xor_sync(0xffffffffu, m1v, off);
        lo2 = __shfl_xor_sync(0xffffffffu, l1v, off);
        mn = fmaxf(m1v, mo);
        l1v = l1v*__expf(m1v - mn) + lo2*__expf(mo - mn);
        m1v = mn;
    }
    const float inv0 = 1.f / l0v, inv1 = 1.f / l1v;

    // ================= PASS B: att write + O = P·V =================
    float o[8][4];
    #pragma unroll
    for (int dt = 0; dt < 8; dt++)
        #pragma unroll
        for (int c = 0; c < 4; c++) o[dt][c] = 0.f;

    const size_t ab0 = (qbase + (size_t)r0) * TT;
    const size_t ab1 = (qbase + (size_t)r1) * TT;

    for (int kc = 0; kc < kend; kc += 128) {
        __syncthreads();
        for (int i = tid; i < 128*8; i += 256) {
            int r = i >> 3, c = i & 7;
            size_t gs = (qbase + kc + r)*DD + c*8;
            *(float4*)&sKh[r*SKW + c*8] = *(const float4*)&g_kh[gs];
            *(float4*)&sKl[r*SKW + c*8] = *(const float4*)&g_kl[gs];
        }
        for (int i = tid; i < 64*16; i += 256) {
            int d = i >> 4, c = i & 15;
            size_t gs = ((size_t)bh*DD + d)*TT + kc + c*8;
            *(float4*)&sVh[d*SVW + c*8] = *(const float4*)&g_vth[gs];
            *(float4*)&sVl[d*SVW + c*8] = *(const float4*)&g_vtl[gs];
        }
        __syncthreads();

        #pragma unroll
        for (int ss = 0; ss < 2; ss++) {
            float p4[8][4];
            #pragma unroll
            for (int nt8 = 0; nt8 < 8; nt8++) {
                int nt = ss*8 + nt8;
                int kbase = kc + nt*8;
                float c4[4] = {0.f, 0.f, 0.f, 0.f};
                if (kbase <= wmax) {
                    #pragma unroll
                    for (int ks = 0; ks < 4; ks++) {
                        int rb = (nt*8 + g)*SKW + ks*16 + t2;
                        uint32_t bh2[2], bl2[2];
                        bh2[0] = *(const uint32_t*)&sKh[rb];
                        bh2[1] = *(const uint32_t*)&sKh[rb + 8];
                        bl2[0] = *(const uint32_t*)&sKl[rb];
                        bl2[1] = *(const uint32_t*)&sKl[rb + 8];
                        mma_16816(c4, qfh[ks], bh2);
                        mma_16816(c4, qfh[ks], bl2);
                        mma_16816(c4, qfl[ks], bh2);
                    }
                }
                int kg = kbase + t2;
                {
                    int d0 = min(max(kg - r0, -32), 32) + 32;
                    int d1 = min(max(kg + 1 - r0, -32), 32) + 32;
                    float s0 = (c4[0] + QR[tr0*66 + d0]) * 0.125f;
                    float s1 = (c4[1] + QR[tr0*66 + d1]) * 0.125f;
                    p4[nt8][0] = (kg     <= r0) ? __expf(s0 - m0v) * inv0 : 0.f;
                    p4[nt8][1] = (kg + 1 <= r0) ? __expf(s1 - m0v) * inv0 : 0.f;
                }
                {
                    int d0 = min(max(kg - r1, -32), 32) + 32;
                    int d1 = min(max(kg + 1 - r1, -32), 32) + 32;
                    float s0 = (c4[2] + QR[(tr0+8)*66 + d0]) * 0.125f;
                    float s1 = (c4[3] + QR[(tr0+8)*66 + d1]) * 0.125f;
                    p4[nt8][2] = (kg     <= r1) ? __expf(s0 - m1v) * inv1 : 0.f;
                    p4[nt8][3] = (kg + 1 <= r1) ? __expf(s1 - m1v) * inv1 : 0.f;
                }
                *(float2*)&att[ab0 + kbase + t2] = make_float2(p4[nt8][0], p4[nt8][1]);
                *(float2*)&att[ab1 + kbase + t2] = make_float2(p4[nt8][2], p4[nt8][3]);
            }
            // PV MMAs for this 64-key sub-chunk
            #pragma unroll
            for (int ksl = 0; ksl < 4; ksl++) {
                int kslice = kc + ss*64 + ksl*16;
                if (kslice <= wmax) {
                    uint32_t ah[4], al[4];
                    ah[0] = pack_hi_lo(p4[2*ksl][0],   p4[2*ksl][1],   al[0]);
                    ah[1] = pack_hi_lo(p4[2*ksl][2],   p4[2*ksl][3],   al[1]);
                    ah[2] = pack_hi_lo(p4[2*ksl+1][0], p4[2*ksl+1][1], al[2]);
                    ah[3] = pack_hi_lo(p4[2*ksl+1][2], p4[2*ksl+1][3], al[3]);
                    int kloc = ss*64 + ksl*16 + t2;
                    #pragma unroll
                    for (int dt = 0; dt < 8; dt++) {
                        int db = (dt*8 + g)*SVW + kloc;
                        uint32_t bh2[2], bl2[2];
                        bh2[0] = *(const uint32_t*)&sVh[db];
                        bh2[1] = *(const uint32_t*)&sVh[db + 8];
                        bl2[0] = *(const uint32_t*)&sVl[db];
                        bl2[1] = *(const uint32_t*)&sVl[db + 8];
                        mma_16816(o[dt], ah, bh2);
                        mma_16816(o[dt], ah, bl2);
                        mma_16816(o[dt], al, bh2);
                    }
                }
            }
        }
    }

    // ---- write O (warp owns its rows; no reduce) ----
    {
        int b_ = bh >> 4, h_ = bh & 15;
        size_t ob0 = ((size_t)b_*TT + r0)*CC + h_*64;
        size_t ob1 = ((size_t)b_*TT + r1)*CC + h_*64;
        #pragma unroll
        for (int dt = 0; dt < 8; dt++) {
            *(float2*)&g_o[ob0 + dt*8 + t2] = make_float2(o[dt][0], o[dt][1]);
            *(float2*)&g_o[ob1 + dt*8 + t2] = make_float2(o[dt][2], o[dt][3]);
        }
    }

    // ---- zero-fill att cols [kend, TT) ----
    {
        int zc4 = (TT - kend) >> 2;
        float4 z = make_float4(0.f, 0.f, 0.f, 0.f);
        for (int i = tid; i < BLKM*zc4; i += 256) {
            int row = i / (zc4 > 0 ? zc4 : 1);
            int c4i = i - row*zc4;
            if (zc4 > 0)
                *(float4*)&att[(qbase + q0 + row)*TT + kend + c4i*4] = z;
        }
    }
}

// =====================================================================
extern "C" void kernel_launch(void* const* d_in, const int* in_sizes, int n_in,
                              void* d_out, int out_size)
{
    const float* x      = (const float*)d_in[0];
    const float* w_attn = (const float*)d_in[2];
    const float* b_attn = (const float*)d_in[3];
    const float* w_proj = (const float*)d_in[4];
    const float* b_proj = (const float*)d_in[5];
    const float* rel_k  = (const float*)d_in[6];
    float* out = (float*)d_out;

    const size_t YS = (size_t)BT*CC;
    const size_t AS = (size_t)BH*TT*TT;

    float* y_out = out;
    float* att_base = nullptr;
    int att_mode = 1;
    if ((size_t)out_size >= YS + AS) {
        y_out = out; att_base = out + YS; att_mode = 0;
    } else if ((size_t)out_size == AS) {
        att_base = out; att_mode = 0; y_out = nullptr;
    }

    cudaFuncSetAttribute(attn_kernel,
        cudaFuncAttributeMaxDynamicSharedMemorySize, ATTN_SMEM_BYTES);
    cudaFuncSetAttribute(mma_gemm_kernel<0>,
        cudaFuncAttributeMaxDynamicSharedMemorySize, GEMM_SMEM_BYTES);
    cudaFuncSetAttribute(mma_gemm_kernel<1>,
        cudaFuncAttributeMaxDynamicSharedMemorySize, GEMM_SMEM_BYTES);

    split_kernel<0><<<BT*CC/4/256, 256>>>(x);
    wsplit_kernel<0><<<dim3(3*CC/32, CC/32), dim3(32,8)>>>(w_attn, 3*CC);
    wsplit_kernel<1><<<dim3(CC/32,   CC/32), dim3(32,8)>>>(w_proj, CC);
    mma_gemm_kernel<0><<<dim3(24, 32), 256, GEMM_SMEM_BYTES>>>(b_attn, nullptr);
    qrel_kernel<<<BH*TT/32, 256>>>(rel_k);
    attn_kernel<<<dim3(TT/BLKM, BH), 256, ATTN_SMEM_BYTES>>>(att_base, att_mode);
    split_kernel<1><<<BT*CC/4/256, 256>>>(nullptr);
    mma_gemm_kernel<1><<<dim3(8, 32), 256, GEMM_SMEM_BYTES>>>(b_proj, y_out);
}

// round 9
// speedup vs baseline: 2.3258x; 1.0767x over previous
#include <cuda_runtime.h>
#include <cuda_bf16.h>
#include <math.h>
#include <stdint.h>

#define BB 2
#define TT 2048
#define CC 1024
#define HH 16
#define DD 64
#define NR 65                      // 2*MAXREL+1
#define BH (BB*HH)                 // 32
#define BT (BB*TT)                 // 4096
#define BLKM 128                   // q-rows per attention CTA

// ---------------- device scratch ----------------
__device__ float g_q[BH*TT*DD];        // fp32 q (for qrel)
__device__ float g_qrel[BH*TT*NR];     // [bh][t][r]
__device__ float g_o[BT*CC];           // pre-proj context
__device__ float g_y[BT*CC];           // fallback y sink
__device__ float g_linv[BH*TT];        // per-row 1/l
__device__ float g_att[(size_t)BH*TT*TT]; // fallback att sink

// bf16 hi/lo operands
__device__ __nv_bfloat16 g_qh[BH*TT*DD], g_ql[BH*TT*DD];   // [bh][t][d]
__device__ __nv_bfloat16 g_kh[BH*TT*DD], g_kl[BH*TT*DD];   // [bh][t][d]
__device__ __nv_bfloat16 g_vth[BH*DD*TT], g_vtl[BH*DD*TT]; // V^T [bh][d][t]
__device__ __nv_bfloat16 g_xa_hi[BT*CC],  g_xa_lo[BT*CC];
__device__ __nv_bfloat16 g_oa_hi[BT*CC],  g_oa_lo[BT*CC];
__device__ __nv_bfloat16 g_wta_hi[3*CC*CC], g_wta_lo[3*CC*CC];
__device__ __nv_bfloat16 g_wtp_hi[CC*CC],   g_wtp_lo[CC*CC];

// ===================== mma.sync helpers =====================
__device__ __forceinline__ void mma_16816(float* c, const uint32_t* a, const uint32_t* b) {
    asm volatile("mma.sync.aligned.m16n8k16.row.col.f32.bf16.bf16.f32 "
        "{%0,%1,%2,%3}, {%4,%5,%6,%7}, {%8,%9}, {%0,%1,%2,%3};"
        : "+f"(c[0]), "+f"(c[1]), "+f"(c[2]), "+f"(c[3])
        : "r"(a[0]), "r"(a[1]), "r"(a[2]), "r"(a[3]), "r"(b[0]), "r"(b[1]));
}
__device__ __forceinline__ uint32_t pack_bf2(__nv_bfloat16 a, __nv_bfloat16 b) {
    return ((uint32_t)__bfloat16_as_ushort(b) << 16) | __bfloat16_as_ushort(a);
}
__device__ __forceinline__ uint32_t pack_hi_lo(float p0, float p1, uint32_t& lo) {
    __nv_bfloat16 h0 = __float2bfloat16(p0), h1 = __float2bfloat16(p1);
    __nv_bfloat16 l0 = __float2bfloat16(p0 - __bfloat162float(h0));
    __nv_bfloat16 l1 = __float2bfloat16(p1 - __bfloat162float(h1));
    lo = pack_bf2(l0, l1);
    return pack_bf2(h0, h1);
}

// =====================================================================
// Conversion kernels
// =====================================================================
template<int SRC>   // 0: x param -> g_xa,  1: g_o -> g_oa
__global__ __launch_bounds__(256) void split_kernel(const float* __restrict__ in)
{
    const float* src = (SRC == 0) ? in : (const float*)g_o;
    __nv_bfloat16* hi = (SRC == 0) ? g_xa_hi : g_oa_hi;
    __nv_bfloat16* lo = (SRC == 0) ? g_xa_lo : g_oa_lo;
    int i = blockIdx.x * 256 + threadIdx.x;
    float4 v = ((const float4*)src)[i];
    float a[4] = {v.x, v.y, v.z, v.w};
    __nv_bfloat16 hb[4], lb[4];
    #pragma unroll
    for (int c = 0; c < 4; c++) {
        hb[c] = __float2bfloat16(a[c]);
        lb[c] = __float2bfloat16(a[c] - __bfloat162float(hb[c]));
    }
    ((uint32_t*)hi)[i*2+0] = pack_bf2(hb[0], hb[1]);
    ((uint32_t*)hi)[i*2+1] = pack_bf2(hb[2], hb[3]);
    ((uint32_t*)lo)[i*2+0] = pack_bf2(lb[0], lb[1]);
    ((uint32_t*)lo)[i*2+1] = pack_bf2(lb[2], lb[3]);
}

template<int WSEL>  // 0: w_attn -> g_wta, 1: w_proj -> g_wtp
__global__ __launch_bounds__(256) void wsplit_kernel(const float* __restrict__ W, int N)
{
    __shared__ float ts[32][33];
    __nv_bfloat16* hi = (WSEL == 0) ? g_wta_hi : g_wtp_hi;
    __nv_bfloat16* lo = (WSEL == 0) ? g_wta_lo : g_wtp_lo;
    int nx = blockIdx.x * 32, kx = blockIdx.y * 32;
    int tx = threadIdx.x, ty = threadIdx.y;
    #pragma unroll
    for (int j = ty; j < 32; j += 8)
        ts[j][tx] = W[(size_t)(kx + j)*N + nx + tx];
    __syncthreads();
    #pragma unroll
    for (int j = ty; j < 32; j += 8) {
        float v = ts[tx][j];
        __nv_bfloat16 h = __float2bfloat16(v);
        __nv_bfloat16 l = __float2bfloat16(v - __bfloat162float(h));
        hi[(size_t)(nx + j)*CC + kx + tx] = h;
        lo[(size_t)(nx + j)*CC + kx + tx] = l;
    }
}

// =====================================================================
// mma.sync bf16x3 GEMM (verified R5 core)
// MODE 0: scatter -> q (fp32+bf16), k (bf16), v (bf16 TRANSPOSED), +bias
// MODE 1: A = g_oa, B = g_wtp, out -> y + bias (N=1024)
// =====================================================================
#define LDA 72
#define SM_ARR (128*LDA)
#define GEMM_SMEM_BYTES (4*SM_ARR*2)

template<int MODE>
__global__ __launch_bounds__(256) void mma_gemm_kernel(const float* __restrict__ bias,
                                                       float* __restrict__ outp)
{
    extern __shared__ __nv_bfloat16 sb[];
    __nv_bfloat16* sAh = sb;
    __nv_bfloat16* sAl = sb + SM_ARR;
    __nv_bfloat16* sBh = sb + 2*SM_ARR;
    __nv_bfloat16* sBl = sb + 3*SM_ARR;

    const int tid  = threadIdx.x;
    const int wid  = tid >> 5, lane = tid & 31;
    const int wm   = wid >> 2, wn = wid & 3;
    const int m0   = blockIdx.y * 128;
    const int n0   = blockIdx.x * 128;

    const __nv_bfloat16* Ah = (MODE == 0) ? g_xa_hi : g_oa_hi;
    const __nv_bfloat16* Al = (MODE == 0) ? g_xa_lo : g_oa_lo;
    const __nv_bfloat16* Bh = (MODE == 0) ? g_wta_hi : g_wtp_hi;
    const __nv_bfloat16* Bl = (MODE == 0) ? g_wta_lo : g_wtp_lo;

    float acc[4][4][4];
    #pragma unroll
    for (int i = 0; i < 4; i++)
        #pragma unroll
        for (int j = 0; j < 4; j++)
            #pragma unroll
            for (int c = 0; c < 4; c++) acc[i][j][c] = 0.f;

    const int g  = lane >> 2;
    const int t2 = (lane & 3) * 2;

    for (int kt = 0; kt < 16; kt++) {
        const int k0 = kt * 64;
        #pragma unroll
        for (int it = 0; it < 4; it++) {
            int i = tid + it * 256;
            int r = i >> 3, c8 = i & 7;
            size_t ga = (size_t)(m0 + r) * CC + k0 + c8 * 8;
            size_t gb = (size_t)(n0 + r) * CC + k0 + c8 * 8;
            int so = r * LDA + c8 * 8;
            *(float4*)&sAh[so] = *(const float4*)&Ah[ga];
            *(float4*)&sAl[so] = *(const float4*)&Al[ga];
            *(float4*)&sBh[so] = *(const float4*)&Bh[gb];
            *(float4*)&sBl[so] = *(const float4*)&Bl[gb];
        }
        __syncthreads();

        #pragma unroll
        for (int ks = 0; ks < 4; ks++) {
            const int kb = ks * 16 + t2;
            uint32_t ah[4][4], al[4][4];
            #pragma unroll
            for (int tm = 0; tm < 4; tm++) {
                int r0 = (wm*64 + tm*16 + g) * LDA + kb;
                int r1 = r0 + 8 * LDA;
                ah[tm][0] = *(const uint32_t*)&sAh[r0];
                ah[tm][1] = *(const uint32_t*)&sAh[r1];
                ah[tm][2] = *(const uint32_t*)&sAh[r0 + 8];
                ah[tm][3] = *(const uint32_t*)&sAh[r1 + 8];
                al[tm][0] = *(const uint32_t*)&sAl[r0];
                al[tm][1] = *(const uint32_t*)&sAl[r1];
                al[tm][2] = *(const uint32_t*)&sAl[r0 + 8];
                al[tm][3] = *(const uint32_t*)&sAl[r1 + 8];
            }
            #pragma unroll
            for (int tn = 0; tn < 4; tn++) {
                int rb = (wn*32 + tn*8 + g) * LDA + kb;
                uint32_t bh[2], bl[2];
                bh[0] = *(const uint32_t*)&sBh[rb];
                bh[1] = *(const uint32_t*)&sBh[rb + 8];
                bl[0] = *(const uint32_t*)&sBl[rb];
                bl[1] = *(const uint32_t*)&sBl[rb + 8];
                #pragma unroll
                for (int tm = 0; tm < 4; tm++) {
                    mma_16816(acc[tm][tn], ah[tm], bh);
                    mma_16816(acc[tm][tn], ah[tm], bl);
                    mma_16816(acc[tm][tn], al[tm], bh);
                }
            }
        }
        __syncthreads();
    }

    const int lr = lane >> 2;
    const int lc = (lane & 3) * 2;
    #pragma unroll
    for (int tm = 0; tm < 4; tm++) {
        #pragma unroll
        for (int tn = 0; tn < 4; tn++) {
            int c = n0 + wn*32 + tn*8 + lc;
            float b0 = bias[c], b1 = bias[c+1];
            #pragma unroll
            for (int half = 0; half < 2; half++) {
                int m = m0 + wm*64 + tm*16 + lr + half*8;
                float v0 = acc[tm][tn][half*2+0] + b0;
                float v1 = acc[tm][tn][half*2+1] + b1;
                if (MODE == 0) {
                    int which = c >> 10, hh = (c >> 6) & 15, dd = c & 63;
                    int b_ = m >> 11, t_ = m & 2047;
                    int bhx = b_*HH + hh;
                    __nv_bfloat16 h0 = __float2bfloat16(v0);
                    __nv_bfloat16 h1 = __float2bfloat16(v1);
                    __nv_bfloat16 l0 = __float2bfloat16(v0 - __bfloat162float(h0));
                    __nv_bfloat16 l1 = __float2bfloat16(v1 - __bfloat162float(h1));
                    if (which == 0) {
                        size_t di = ((size_t)bhx*TT + t_)*DD + dd;
                        *(float2*)&g_q[di] = make_float2(v0, v1);
                        *(uint32_t*)&g_qh[di] = pack_bf2(h0, h1);
                        *(uint32_t*)&g_ql[di] = pack_bf2(l0, l1);
                    } else if (which == 1) {
                        size_t di = ((size_t)bhx*TT + t_)*DD + dd;
                        *(uint32_t*)&g_kh[di] = pack_bf2(h0, h1);
                        *(uint32_t*)&g_kl[di] = pack_bf2(l0, l1);
                    } else {
                        size_t vb = (size_t)bhx*DD;
                        g_vth[(vb + dd    )*TT + t_] = h0;
                        g_vth[(vb + dd + 1)*TT + t_] = h1;
                        g_vtl[(vb + dd    )*TT + t_] = l0;
                        g_vtl[(vb + dd + 1)*TT + t_] = l1;
                    }
                } else {
                    float* dst = outp ? outp : g_y;
                    *(float2*)&dst[(size_t)m*CC + c] = make_float2(v0, v1);
                }
            }
        }
    }
}

// =====================================================================
// qrel
// =====================================================================
__device__ __forceinline__ float dot4(float4 a, float4 b) {
    return a.x*b.x + a.y*b.y + a.z*b.z + a.w*b.w;
}

__global__ __launch_bounds__(256) void qrel_kernel(const float* __restrict__ rel)
{
    __shared__ float rs[NR*64];
    __shared__ float qs[32*64];
    const int tid = threadIdx.x;
    const int r0  = blockIdx.x * 32;

    for (int i = tid; i < NR*16; i += 256)
        ((float4*)rs)[i] = ((const float4*)rel)[i];
    for (int i = tid; i < 32*16; i += 256) {
        int t = i >> 4, d4 = i & 15;
        *(float4*)&qs[t*64 + d4*4] = *(const float4*)&g_q[(size_t)(r0+t)*64 + d4*4];
    }
    __syncthreads();

    for (int i = tid; i < 32*NR; i += 256) {
        int t = i / NR, r = i % NR;
        const float4* qq = (const float4*)&qs[t*64];
        const float4* rr = (const float4*)&rs[r*64];
        float acc = 0.f;
        #pragma unroll
        for (int d4 = 0; d4 < 16; d4++) acc += dot4(qq[d4], rr[d4]);
        g_qrel[(size_t)(r0+t)*NR + r] = acc;
    }
}

// =====================================================================
// Single-pass flash attention (no max subtraction; exp arg clamped):
//  per chunk: S-MMA -> p~=exp(s) -> write p~ to att (unnormalized),
//  accumulate l and O=P~·V. End: O *= 1/l; store 1/l for normalize pass.
// =====================================================================
#define SKW 72          // K smem row pitch (bf16)
#define SVW 136         // V^T smem row pitch (bf16)
#define ATTN_SMEM_BYTES (2*128*SKW*2 + 2*64*SVW*2 + 128*66*4 + 64)

__global__ __launch_bounds__(256) void attn_kernel(float* __restrict__ out_att, int att_mode)
{
    extern __shared__ char smc[];
    __nv_bfloat16* sKh = (__nv_bfloat16*)smc;          // [128][72]
    __nv_bfloat16* sKl = sKh + 128*SKW;
    __nv_bfloat16* sVh = sKl + 128*SKW;                // [64][136]
    __nv_bfloat16* sVl = sVh + 64*SVW;
    float* QR = (float*)(sVl + 64*SVW);                // [128][66]

    const int tid = threadIdx.x, w = tid >> 5, lane = tid & 31;
    const int g = lane >> 2, t2 = (lane & 3) * 2;
    const int q0 = blockIdx.x * BLKM;
    const int bh = blockIdx.y;
    const int kend = q0 + BLKM;
    const size_t qbase = (size_t)bh * TT;
    float* att = att_mode ? g_att : out_att;

    for (int i = tid; i < BLKM*NR; i += 256) {
        int t = i / NR, r = i % NR;
        QR[t*66 + r] = g_qrel[(qbase + q0 + t)*NR + r];
    }

    const int tr0 = w*16 + g;
    const int r0 = q0 + tr0;
    const int r1 = r0 + 8;
    const int wmax = q0 + w*16 + 15;

    // Q fragments (hi/lo)
    uint32_t qfh[4][4], qfl[4][4];
    {
        size_t ra = (qbase + (size_t)r0) * DD;
        size_t rb = ra + 8*DD;
        #pragma unroll
        for (int ks = 0; ks < 4; ks++) {
            int c0 = ks*16 + t2;
            qfh[ks][0] = *(const uint32_t*)&g_qh[ra + c0];
            qfh[ks][1] = *(const uint32_t*)&g_qh[rb + c0];
            qfh[ks][2] = *(const uint32_t*)&g_qh[ra + c0 + 8];
            qfh[ks][3] = *(const uint32_t*)&g_qh[rb + c0 + 8];
            qfl[ks][0] = *(const uint32_t*)&g_ql[ra + c0];
            qfl[ks][1] = *(const uint32_t*)&g_ql[rb + c0];
            qfl[ks][2] = *(const uint32_t*)&g_ql[ra + c0 + 8];
            qfl[ks][3] = *(const uint32_t*)&g_ql[rb + c0 + 8];
        }
    }

    float o[8][4];
    #pragma unroll
    for (int dt = 0; dt < 8; dt++)
        #pragma unroll
        for (int c = 0; c < 4; c++) o[dt][c] = 0.f;
    float l0v = 0.f, l1v = 0.f;

    const size_t ab0 = (qbase + (size_t)r0) * TT;
    const size_t ab1 = (qbase + (size_t)r1) * TT;

    for (int kc = 0; kc < kend; kc += 128) {
        __syncthreads();
        for (int i = tid; i < 128*8; i += 256) {
            int r = i >> 3, c = i & 7;
            size_t gs = (qbase + kc + r)*DD + c*8;
            *(float4*)&sKh[r*SKW + c*8] = *(const float4*)&g_kh[gs];
            *(float4*)&sKl[r*SKW + c*8] = *(const float4*)&g_kl[gs];
        }
        for (int i = tid; i < 64*16; i += 256) {
            int d = i >> 4, c = i & 15;
            size_t gs = ((size_t)bh*DD + d)*TT + kc + c*8;
            *(float4*)&sVh[d*SVW + c*8] = *(const float4*)&g_vth[gs];
            *(float4*)&sVl[d*SVW + c*8] = *(const float4*)&g_vtl[gs];
        }
        __syncthreads();

        #pragma unroll
        for (int ss = 0; ss < 2; ss++) {
            float p4[8][4];
            #pragma unroll
            for (int nt8 = 0; nt8 < 8; nt8++) {
                int nt = ss*8 + nt8;
                int kbase = kc + nt*8;
                float c4[4] = {0.f, 0.f, 0.f, 0.f};
                if (kbase <= wmax) {
                    #pragma unroll
                    for (int ks = 0; ks < 4; ks++) {
                        int rb = (nt*8 + g)*SKW + ks*16 + t2;
                        uint32_t bh2[2], bl2[2];
                        bh2[0] = *(const uint32_t*)&sKh[rb];
                        bh2[1] = *(const uint32_t*)&sKh[rb + 8];
                        bl2[0] = *(const uint32_t*)&sKl[rb];
                        bl2[1] = *(const uint32_t*)&sKl[rb + 8];
                        mma_16816(c4, qfh[ks], bh2);
                        mma_16816(c4, qfh[ks], bl2);
                        mma_16816(c4, qfl[ks], bh2);
                    }
                }
                int kg = kbase + t2;
                {
                    int d0 = min(max(kg - r0, -32), 32) + 32;
                    int d1 = min(max(kg + 1 - r0, -32), 32) + 32;
                    float s0 = (c4[0] + QR[tr0*66 + d0]) * 0.125f;
                    float s1 = (c4[1] + QR[tr0*66 + d1]) * 0.125f;
                    p4[nt8][0] = (kg     <= r0) ? __expf(fminf(s0, 80.f)) : 0.f;
                    p4[nt8][1] = (kg + 1 <= r0) ? __expf(fminf(s1, 80.f)) : 0.f;
                    l0v += p4[nt8][0] + p4[nt8][1];
                }
                {
                    int d0 = min(max(kg - r1, -32), 32) + 32;
                    int d1 = min(max(kg + 1 - r1, -32), 32) + 32;
                    float s0 = (c4[2] + QR[(tr0+8)*66 + d0]) * 0.125f;
                    float s1 = (c4[3] + QR[(tr0+8)*66 + d1]) * 0.125f;
                    p4[nt8][2] = (kg     <= r1) ? __expf(fminf(s0, 80.f)) : 0.f;
                    p4[nt8][3] = (kg + 1 <= r1) ? __expf(fminf(s1, 80.f)) : 0.f;
                    l1v += p4[nt8][2] + p4[nt8][3];
                }
                *(float2*)&att[ab0 + kbase + t2] = make_float2(p4[nt8][0], p4[nt8][1]);
                *(float2*)&att[ab1 + kbase + t2] = make_float2(p4[nt8][2], p4[nt8][3]);
            }
            #pragma unroll
            for (int ksl = 0; ksl < 4; ksl++) {
                int kslice = kc + ss*64 + ksl*16;
                if (kslice <= wmax) {
                    uint32_t ah[4], al[4];
                    ah[0] = pack_hi_lo(p4[2*ksl][0],   p4[2*ksl][1],   al[0]);
                    ah[1] = pack_hi_lo(p4[2*ksl][2],   p4[2*ksl][3],   al[1]);
                    ah[2] = pack_hi_lo(p4[2*ksl+1][0], p4[2*ksl+1][1], al[2]);
                    ah[3] = pack_hi_lo(p4[2*ksl+1][2], p4[2*ksl+1][3], al[3]);
                    int kloc = ss*64 + ksl*16 + t2;
                    #pragma unroll
                    for (int dt = 0; dt < 8; dt++) {
                        int db = (dt*8 + g)*SVW + kloc;
                        uint32_t bh2[2], bl2[2];
                        bh2[0] = *(const uint32_t*)&sVh[db];
                        bh2[1] = *(const uint32_t*)&sVh[db + 8];
                        bl2[0] = *(const uint32_t*)&sVl[db];
                        bl2[1] = *(const uint32_t*)&sVl[db + 8];
                        mma_16816(o[dt], ah, bh2);
                        mma_16816(o[dt], ah, bl2);
                        mma_16816(o[dt], al, bh2);
                    }
                }
            }
        }
    }

    // ---- merge l across the quad (4 lanes share each row) ----
    #pragma unroll
    for (int off = 1; off <= 2; off <<= 1) {
        l0v += __shfl_xor_sync(0xffffffffu, l0v, off);
        l1v += __shfl_xor_sync(0xffffffffu, l1v, off);
    }
    const float inv0 = 1.f / l0v, inv1 = 1.f / l1v;
    if ((lane & 3) == 0) {
        g_linv[qbase + r0] = inv0;
        g_linv[qbase + r1] = inv1;
    }

    // ---- write O (scaled) ----
    {
        int b_ = bh >> 4, h_ = bh & 15;
        size_t ob0 = ((size_t)b_*TT + r0)*CC + h_*64;
        size_t ob1 = ((size_t)b_*TT + r1)*CC + h_*64;
        #pragma unroll
        for (int dt = 0; dt < 8; dt++) {
            *(float2*)&g_o[ob0 + dt*8 + t2] = make_float2(o[dt][0]*inv0, o[dt][1]*inv0);
            *(float2*)&g_o[ob1 + dt*8 + t2] = make_float2(o[dt][2]*inv1, o[dt][3]*inv1);
        }
    }

    // ---- zero-fill att cols [kend, TT) ----
    {
        int zc4 = (TT - kend) >> 2;
        float4 z = make_float4(0.f, 0.f, 0.f, 0.f);
        for (int i = tid; i < BLKM*zc4; i += 256) {
            int row = i / (zc4 > 0 ? zc4 : 1);
            int c4i = i - row*zc4;
            if (zc4 > 0)
                *(float4*)&att[(qbase + q0 + row)*TT + kend + c4i*4] = z;
        }
    }
}

// =====================================================================
// normalize: att[row][0..n) *= g_linv[row]  (causal region only)
// =====================================================================
__global__ __launch_bounds__(256) void norm_kernel(float* __restrict__ att_p, int att_mode)
{
    float* att = att_mode ? g_att : att_p;
    size_t row = blockIdx.x;
    float inv = g_linv[row];
    int t = (int)(row & (TT - 1));
    int n4 = (t + 4) >> 2;                 // ceil((t+1)/4)
    float4* p = (float4*)(att + row * TT);
    for (int i = threadIdx.x; i < n4; i += 256) {
        float4 v = p[i];
        v.x *= inv; v.y *= inv; v.z *= inv; v.w *= inv;
        p[i] = v;
    }
}

// =====================================================================
extern "C" void kernel_launch(void* const* d_in, const int* in_sizes, int n_in,
                              void* d_out, int out_size)
{
    const float* x      = (const float*)d_in[0];
    const float* w_attn = (const float*)d_in[2];
    const float* b_attn = (const float*)d_in[3];
    const float* w_proj = (const float*)d_in[4];
    const float* b_proj = (const float*)d_in[5];
    const float* rel_k  = (const float*)d_in[6];
    float* out = (float*)d_out;

    const size_t YS = (size_t)BT*CC;
    const size_t AS = (size_t)BH*TT*TT;

    float* y_out = out;
    float* att_base = nullptr;
    int att_mode = 1;
    if ((size_t)out_size >= YS + AS) {
        y_out = out; att_base = out + YS; att_mode = 0;
    } else if ((size_t)out_size == AS) {
        att_base = out; att_mode = 0; y_out = nullptr;
    }

    cudaFuncSetAttribute(attn_kernel,
        cudaFuncAttributeMaxDynamicSharedMemorySize, ATTN_SMEM_BYTES);
    cudaFuncSetAttribute(mma_gemm_kernel<0>,
        cudaFuncAttributeMaxDynamicSharedMemorySize, GEMM_SMEM_BYTES);
    cudaFuncSetAttribute(mma_gemm_kernel<1>,
        cudaFuncAttributeMaxDynamicSharedMemorySize, GEMM_SMEM_BYTES);

    split_kernel<0><<<BT*CC/4/256, 256>>>(x);
    wsplit_kernel<0><<<dim3(3*CC/32, CC/32), dim3(32,8)>>>(w_attn, 3*CC);
    wsplit_kernel<1><<<dim3(CC/32,   CC/32), dim3(32,8)>>>(w_proj, CC);
    mma_gemm_kernel<0><<<dim3(24, 32), 256, GEMM_SMEM_BYTES>>>(b_attn, nullptr);
    qrel_kernel<<<BH*TT/32, 256>>>(rel_k);
    attn_kernel<<<dim3(TT/BLKM, BH), 256, ATTN_SMEM_BYTES>>>(att_base, att_mode);
    norm_kernel<<<BH*TT, 256>>>(att_base, att_mode);
    split_kernel<1><<<BT*CC/4/256, 256>>>(nullptr);
    mma_gemm_kernel<1><<<dim3(8, 32), 256, GEMM_SMEM_BYTES>>>(b_proj, y_out);
}

// round 10
// speedup vs baseline: 2.6439x; 1.1368x over previous
#include <cuda_runtime.h>
#include <cuda_bf16.h>
#include <math.h>
#include <stdint.h>

#define BB 2
#define TT 2048
#define CC 1024
#define HH 16
#define DD 64
#define NR 65                      // 2*MAXREL+1
#define BH (BB*HH)                 // 32
#define BT (BB*TT)                 // 4096
#define BLKM 128                   // q-rows per attention CTA

// ---------------- device scratch ----------------
__device__ float g_q[BH*TT*DD];        // fp32 q (for qrel)
__device__ float g_qrel[BH*TT*NR];     // [bh][t][r]
__device__ float g_o[BT*CC];           // pre-proj context
__device__ float g_y[BT*CC];           // fallback y sink
__device__ float g_att[(size_t)BH*TT*TT]; // fallback att sink

// bf16 hi/lo operands
__device__ __nv_bfloat16 g_qh[BH*TT*DD], g_ql[BH*TT*DD];   // [bh][t][d]
__device__ __nv_bfloat16 g_kh[BH*TT*DD], g_kl[BH*TT*DD];   // [bh][t][d]
__device__ __nv_bfloat16 g_vth[BH*DD*TT], g_vtl[BH*DD*TT]; // V^T [bh][d][t]
__device__ __nv_bfloat16 g_xa_hi[BT*CC],  g_xa_lo[BT*CC];
__device__ __nv_bfloat16 g_oa_hi[BT*CC],  g_oa_lo[BT*CC];
__device__ __nv_bfloat16 g_wta_hi[3*CC*CC], g_wta_lo[3*CC*CC];
__device__ __nv_bfloat16 g_wtp_hi[CC*CC],   g_wtp_lo[CC*CC];

// ===================== helpers =====================
__device__ __forceinline__ uint32_t smem_to_u32(const void* p) {
    uint32_t a;
    asm("{ .reg .u64 t; cvta.to.shared.u64 t, %1; cvt.u32.u64 %0, t; }" : "=r"(a) : "l"(p));
    return a;
}
__device__ __forceinline__ void cp_async16(uint32_t saddr, const void* gptr) {
    asm volatile("cp.async.cg.shared.global [%0], [%1], 16;" :: "r"(saddr), "l"(gptr));
}
#define CP_COMMIT() asm volatile("cp.async.commit_group;" ::: "memory")
#define CP_WAIT0()  asm volatile("cp.async.wait_group 0;" ::: "memory")

__device__ __forceinline__ void mma_16816(float* c, const uint32_t* a, const uint32_t* b) {
    asm volatile("mma.sync.aligned.m16n8k16.row.col.f32.bf16.bf16.f32 "
        "{%0,%1,%2,%3}, {%4,%5,%6,%7}, {%8,%9}, {%0,%1,%2,%3};"
        : "+f"(c[0]), "+f"(c[1]), "+f"(c[2]), "+f"(c[3])
        : "r"(a[0]), "r"(a[1]), "r"(a[2]), "r"(a[3]), "r"(b[0]), "r"(b[1]));
}
__device__ __forceinline__ uint32_t pack_bf2(__nv_bfloat16 a, __nv_bfloat16 b) {
    return ((uint32_t)__bfloat16_as_ushort(b) << 16) | __bfloat16_as_ushort(a);
}
__device__ __forceinline__ uint32_t pack_hi_lo(float p0, float p1, uint32_t& lo) {
    __nv_bfloat16 h0 = __float2bfloat16(p0), h1 = __float2bfloat16(p1);
    __nv_bfloat16 l0 = __float2bfloat16(p0 - __bfloat162float(h0));
    __nv_bfloat16 l1 = __float2bfloat16(p1 - __bfloat162float(h1));
    lo = pack_bf2(l0, l1);
    return pack_bf2(h0, h1);
}

// =====================================================================
// Conversion kernels
// =====================================================================
template<int SRC>   // 0: x param -> g_xa,  1: g_o -> g_oa
__global__ __launch_bounds__(256) void split_kernel(const float* __restrict__ in)
{
    const float* src = (SRC == 0) ? in : (const float*)g_o;
    __nv_bfloat16* hi = (SRC == 0) ? g_xa_hi : g_oa_hi;
    __nv_bfloat16* lo = (SRC == 0) ? g_xa_lo : g_oa_lo;
    int i = blockIdx.x * 256 + threadIdx.x;
    float4 v = ((const float4*)src)[i];
    float a[4] = {v.x, v.y, v.z, v.w};
    __nv_bfloat16 hb[4], lb[4];
    #pragma unroll
    for (int c = 0; c < 4; c++) {
        hb[c] = __float2bfloat16(a[c]);
        lb[c] = __float2bfloat16(a[c] - __bfloat162float(hb[c]));
    }
    ((uint32_t*)hi)[i*2+0] = pack_bf2(hb[0], hb[1]);
    ((uint32_t*)hi)[i*2+1] = pack_bf2(hb[2], hb[3]);
    ((uint32_t*)lo)[i*2+0] = pack_bf2(lb[0], lb[1]);
    ((uint32_t*)lo)[i*2+1] = pack_bf2(lb[2], lb[3]);
}

template<int WSEL>  // 0: w_attn -> g_wta, 1: w_proj -> g_wtp
__global__ __launch_bounds__(256) void wsplit_kernel(const float* __restrict__ W, int N)
{
    __shared__ float ts[32][33];
    __nv_bfloat16* hi = (WSEL == 0) ? g_wta_hi : g_wtp_hi;
    __nv_bfloat16* lo = (WSEL == 0) ? g_wta_lo : g_wtp_lo;
    int nx = blockIdx.x * 32, kx = blockIdx.y * 32;
    int tx = threadIdx.x, ty = threadIdx.y;
    #pragma unroll
    for (int j = ty; j < 32; j += 8)
        ts[j][tx] = W[(size_t)(kx + j)*N + nx + tx];
    __syncthreads();
    #pragma unroll
    for (int j = ty; j < 32; j += 8) {
        float v = ts[tx][j];
        __nv_bfloat16 h = __float2bfloat16(v);
        __nv_bfloat16 l = __float2bfloat16(v - __bfloat162float(h));
        hi[(size_t)(nx + j)*CC + kx + tx] = h;
        lo[(size_t)(nx + j)*CC + kx + tx] = l;
    }
}

// =====================================================================
// mma.sync bf16x3 GEMM, cp.async double-buffered.
// MODE 0: scatter -> q (fp32+bf16), k (bf16), v (bf16 TRANSPOSED), +bias
// MODE 1: A = g_oa, B = g_wtp, out -> y + bias (N=1024)
// =====================================================================
#define LDA 72
#define SM_ARR (128*LDA)                   // elems per operand array
#define GEMM_BUF_BYTES (4*SM_ARR*2)        // one buffer: Ah,Al,Bh,Bl
#define GEMM_SMEM_BYTES (2*GEMM_BUF_BYTES) // double-buffered: 147456

template<int MODE>
__global__ __launch_bounds__(256) void mma_gemm_kernel(const float* __restrict__ bias,
                                                       float* __restrict__ outp)
{
    extern __shared__ __nv_bfloat16 sb[];
    const uint32_t sbase = smem_to_u32(sb);

    const int tid  = threadIdx.x;
    const int wid  = tid >> 5, lane = tid & 31;
    const int wm   = wid >> 2, wn = wid & 3;
    const int m0   = blockIdx.y * 128;
    const int n0   = blockIdx.x * 128;

    const __nv_bfloat16* Ah = (MODE == 0) ? g_xa_hi : g_oa_hi;
    const __nv_bfloat16* Al = (MODE == 0) ? g_xa_lo : g_oa_lo;
    const __nv_bfloat16* Bh = (MODE == 0) ? g_wta_hi : g_wtp_hi;
    const __nv_bfloat16* Bl = (MODE == 0) ? g_wta_lo : g_wtp_lo;

    auto load_tile = [&](int kt, int buf) {
        const int k0 = kt * 64;
        const uint32_t b0 = sbase + (uint32_t)buf * GEMM_BUF_BYTES;
        #pragma unroll
        for (int it = 0; it < 4; it++) {
            int i = tid + it * 256;
            int r = i >> 3, c8 = i & 7;
            size_t ga = (size_t)(m0 + r) * CC + k0 + c8 * 8;
            size_t gb = (size_t)(n0 + r) * CC + k0 + c8 * 8;
            uint32_t so = (uint32_t)(r * LDA + c8 * 8) * 2;
            cp_async16(b0 + so,               &Ah[ga]);
            cp_async16(b0 + SM_ARR*2 + so,    &Al[ga]);
            cp_async16(b0 + 2*SM_ARR*2 + so,  &Bh[gb]);
            cp_async16(b0 + 3*SM_ARR*2 + so,  &Bl[gb]);
        }
        CP_COMMIT();
    };

    float acc[4][4][4];
    #pragma unroll
    for (int i = 0; i < 4; i++)
        #pragma unroll
        for (int j = 0; j < 4; j++)
            #pragma unroll
            for (int c = 0; c < 4; c++) acc[i][j][c] = 0.f;

    const int g  = lane >> 2;
    const int t2 = (lane & 3) * 2;

    load_tile(0, 0);

    for (int kt = 0; kt < 16; kt++) {
        CP_WAIT0();
        __syncthreads();
        if (kt + 1 < 16) load_tile(kt + 1, (kt + 1) & 1);

        const __nv_bfloat16* bAh = sb + (kt & 1) * (4*SM_ARR);
        const __nv_bfloat16* bAl = bAh + SM_ARR;
        const __nv_bfloat16* bBh = bAh + 2*SM_ARR;
        const __nv_bfloat16* bBl = bAh + 3*SM_ARR;

        #pragma unroll
        for (int ks = 0; ks < 4; ks++) {
            const int kb = ks * 16 + t2;
            uint32_t ah[4][4], al[4][4];
            #pragma unroll
            for (int tm = 0; tm < 4; tm++) {
                int r0 = (wm*64 + tm*16 + g) * LDA + kb;
                int r1 = r0 + 8 * LDA;
                ah[tm][0] = *(const uint32_t*)&bAh[r0];
                ah[tm][1] = *(const uint32_t*)&bAh[r1];
                ah[tm][2] = *(const uint32_t*)&bAh[r0 + 8];
                ah[tm][3] = *(const uint32_t*)&bAh[r1 + 8];
                al[tm][0] = *(const uint32_t*)&bAl[r0];
                al[tm][1] = *(const uint32_t*)&bAl[r1];
                al[tm][2] = *(const uint32_t*)&bAl[r0 + 8];
                al[tm][3] = *(const uint32_t*)&bAl[r1 + 8];
            }
            #pragma unroll
            for (int tn = 0; tn < 4; tn++) {
                int rb = (wn*32 + tn*8 + g) * LDA + kb;
                uint32_t bh[2], bl[2];
                bh[0] = *(const uint32_t*)&bBh[rb];
                bh[1] = *(const uint32_t*)&bBh[rb + 8];
                bl[0] = *(const uint32_t*)&bBl[rb];
                bl[1] = *(const uint32_t*)&bBl[rb + 8];
                #pragma unroll
                for (int tm = 0; tm < 4; tm++) {
                    mma_16816(acc[tm][tn], ah[tm], bh);
                    mma_16816(acc[tm][tn], ah[tm], bl);
                    mma_16816(acc[tm][tn], al[tm], bh);
                }
            }
        }
        __syncthreads();
    }

    const int lr = lane >> 2;
    const int lc = (lane & 3) * 2;
    #pragma unroll
    for (int tm = 0; tm < 4; tm++) {
        #pragma unroll
        for (int tn = 0; tn < 4; tn++) {
            int c = n0 + wn*32 + tn*8 + lc;
            float b0 = bias[c], b1 = bias[c+1];
            #pragma unroll
            for (int half = 0; half < 2; half++) {
                int m = m0 + wm*64 + tm*16 + lr + half*8;
                float v0 = acc[tm][tn][half*2+0] + b0;
                float v1 = acc[tm][tn][half*2+1] + b1;
                if (MODE == 0) {
                    int which = c >> 10, hh = (c >> 6) & 15, dd = c & 63;
                    int b_ = m >> 11, t_ = m & 2047;
                    int bhx = b_*HH + hh;
                    __nv_bfloat16 h0 = __float2bfloat16(v0);
                    __nv_bfloat16 h1 = __float2bfloat16(v1);
                    __nv_bfloat16 l0 = __float2bfloat16(v0 - __bfloat162float(h0));
                    __nv_bfloat16 l1 = __float2bfloat16(v1 - __bfloat162float(h1));
                    if (which == 0) {
                        size_t di = ((size_t)bhx*TT + t_)*DD + dd;
                        *(float2*)&g_q[di] = make_float2(v0, v1);
                        *(uint32_t*)&g_qh[di] = pack_bf2(h0, h1);
                        *(uint32_t*)&g_ql[di] = pack_bf2(l0, l1);
                    } else if (which == 1) {
                        size_t di = ((size_t)bhx*TT + t_)*DD + dd;
                        *(uint32_t*)&g_kh[di] = pack_bf2(h0, h1);
                        *(uint32_t*)&g_kl[di] = pack_bf2(l0, l1);
                    } else {
                        size_t vb = (size_t)bhx*DD;
                        g_vth[(vb + dd    )*TT + t_] = h0;
                        g_vth[(vb + dd + 1)*TT + t_] = h1;
                        g_vtl[(vb + dd    )*TT + t_] = l0;
                        g_vtl[(vb + dd + 1)*TT + t_] = l1;
                    }
                } else {
                    float* dst = outp ? outp : g_y;
                    *(float2*)&dst[(size_t)m*CC + c] = make_float2(v0, v1);
                }
            }
        }
    }
}

// =====================================================================
// qrel
// =====================================================================
__device__ __forceinline__ float dot4(float4 a, float4 b) {
    return a.x*b.x + a.y*b.y + a.z*b.z + a.w*b.w;
}

__global__ __launch_bounds__(256) void qrel_kernel(const float* __restrict__ rel)
{
    __shared__ float rs[NR*64];
    __shared__ float qs[32*64];
    const int tid = threadIdx.x;
    const int r0  = blockIdx.x * 32;

    for (int i = tid; i < NR*16; i += 256)
        ((float4*)rs)[i] = ((const float4*)rel)[i];
    for (int i = tid; i < 32*16; i += 256) {
        int t = i >> 4, d4 = i & 15;
        *(float4*)&qs[t*64 + d4*4] = *(const float4*)&g_q[(size_t)(r0+t)*64 + d4*4];
    }
    __syncthreads();

    for (int i = tid; i < 32*NR; i += 256) {
        int t = i / NR, r = i % NR;
        const float4* qq = (const float4*)&qs[t*64];
        const float4* rr = (const float4*)&rs[r*64];
        float acc = 0.f;
        #pragma unroll
        for (int d4 = 0; d4 < 16; d4++) acc += dot4(qq[d4], rr[d4]);
        g_qrel[(size_t)(r0+t)*NR + r] = acc;
    }
}

// =====================================================================
// Single-pass flash attention + in-CTA normalization sweep (L2-hot).
// =====================================================================
#define SKW 72          // K smem row pitch (bf16)
#define SVW 136         // V^T smem row pitch (bf16)
#define ATTN_SMEM_BYTES (2*128*SKW*2 + 2*64*SVW*2 + 128*66*4 + 128*4 + 64)

__global__ __launch_bounds__(256) void attn_kernel(float* __restrict__ out_att, int att_mode)
{
    extern __shared__ char smc[];
    __nv_bfloat16* sKh = (__nv_bfloat16*)smc;          // [128][72]
    __nv_bfloat16* sKl = sKh + 128*SKW;
    __nv_bfloat16* sVh = sKl + 128*SKW;                // [64][136]
    __nv_bfloat16* sVl = sVh + 64*SVW;
    float* QR = (float*)(sVl + 64*SVW);                // [128][66]
    float* sInv = QR + 128*66;                         // [128]

    const int tid = threadIdx.x, w = tid >> 5, lane = tid & 31;
    const int g = lane >> 2, t2 = (lane & 3) * 2;
    const int q0 = blockIdx.x * BLKM;
    const int bh = blockIdx.y;
    const int kend = q0 + BLKM;
    const size_t qbase = (size_t)bh * TT;
    float* att = att_mode ? g_att : out_att;

    for (int i = tid; i < BLKM*NR; i += 256) {
        int t = i / NR, r = i % NR;
        QR[t*66 + r] = g_qrel[(qbase + q0 + t)*NR + r];
    }

    const int tr0 = w*16 + g;
    const int r0 = q0 + tr0;
    const int r1 = r0 + 8;
    const int wmax = q0 + w*16 + 15;

    // Q fragments (hi/lo)
    uint32_t qfh[4][4], qfl[4][4];
    {
        size_t ra = (qbase + (size_t)r0) * DD;
        size_t rb = ra + 8*DD;
        #pragma unroll
        for (int ks = 0; ks < 4; ks++) {
            int c0 = ks*16 + t2;
            qfh[ks][0] = *(const uint32_t*)&g_qh[ra + c0];
            qfh[ks][1] = *(const uint32_t*)&g_qh[rb + c0];
            qfh[ks][2] = *(const uint32_t*)&g_qh[ra + c0 + 8];
            qfh[ks][3] = *(const uint32_t*)&g_qh[rb + c0 + 8];
            qfl[ks][0] = *(const uint32_t*)&g_ql[ra + c0];
            qfl[ks][1] = *(const uint32_t*)&g_ql[rb + c0];
            qfl[ks][2] = *(const uint32_t*)&g_ql[ra + c0 + 8];
            qfl[ks][3] = *(const uint32_t*)&g_ql[rb + c0 + 8];
        }
    }

    float o[8][4];
    #pragma unroll
    for (int dt = 0; dt < 8; dt++)
        #pragma unroll
        for (int c = 0; c < 4; c++) o[dt][c] = 0.f;
    float l0v = 0.f, l1v = 0.f;

    const size_t ab0 = (qbase + (size_t)r0) * TT;
    const size_t ab1 = (qbase + (size_t)r1) * TT;

    for (int kc = 0; kc < kend; kc += 128) {
        __syncthreads();
        for (int i = tid; i < 128*8; i += 256) {
            int r = i >> 3, c = i & 7;
            size_t gs = (qbase + kc + r)*DD + c*8;
            *(float4*)&sKh[r*SKW + c*8] = *(const float4*)&g_kh[gs];
            *(float4*)&sKl[r*SKW + c*8] = *(const float4*)&g_kl[gs];
        }
        for (int i = tid; i < 64*16; i += 256) {
            int d = i >> 4, c = i & 15;
            size_t gs = ((size_t)bh*DD + d)*TT + kc + c*8;
            *(float4*)&sVh[d*SVW + c*8] = *(const float4*)&g_vth[gs];
            *(float4*)&sVl[d*SVW + c*8] = *(const float4*)&g_vtl[gs];
        }
        __syncthreads();

        #pragma unroll
        for (int ss = 0; ss < 2; ss++) {
            float p4[8][4];
            #pragma unroll
            for (int nt8 = 0; nt8 < 8; nt8++) {
                int nt = ss*8 + nt8;
                int kbase = kc + nt*8;
                float c4[4] = {0.f, 0.f, 0.f, 0.f};
                if (kbase <= wmax) {
                    #pragma unroll
                    for (int ks = 0; ks < 4; ks++) {
                        int rb = (nt*8 + g)*SKW + ks*16 + t2;
                        uint32_t bh2[2], bl2[2];
                        bh2[0] = *(const uint32_t*)&sKh[rb];
                        bh2[1] = *(const uint32_t*)&sKh[rb + 8];
                        bl2[0] = *(const uint32_t*)&sKl[rb];
                        bl2[1] = *(const uint32_t*)&sKl[rb + 8];
                        mma_16816(c4, qfh[ks], bh2);
                        mma_16816(c4, qfh[ks], bl2);
                        mma_16816(c4, qfl[ks], bh2);
                    }
                }
                int kg = kbase + t2;
                {
                    int d0 = min(max(kg - r0, -32), 32) + 32;
                    int d1 = min(max(kg + 1 - r0, -32), 32) + 32;
                    float s0 = (c4[0] + QR[tr0*66 + d0]) * 0.125f;
                    float s1 = (c4[1] + QR[tr0*66 + d1]) * 0.125f;
                    p4[nt8][0] = (kg     <= r0) ? __expf(fminf(s0, 80.f)) : 0.f;
                    p4[nt8][1] = (kg + 1 <= r0) ? __expf(fminf(s1, 80.f)) : 0.f;
                    l0v += p4[nt8][0] + p4[nt8][1];
                }
                {
                    int d0 = min(max(kg - r1, -32), 32) + 32;
                    int d1 = min(max(kg + 1 - r1, -32), 32) + 32;
                    float s0 = (c4[2] + QR[(tr0+8)*66 + d0]) * 0.125f;
                    float s1 = (c4[3] + QR[(tr0+8)*66 + d1]) * 0.125f;
                    p4[nt8][2] = (kg     <= r1) ? __expf(fminf(s0, 80.f)) : 0.f;
                    p4[nt8][3] = (kg + 1 <= r1) ? __expf(fminf(s1, 80.f)) : 0.f;
                    l1v += p4[nt8][2] + p4[nt8][3];
                }
                *(float2*)&att[ab0 + kbase + t2] = make_float2(p4[nt8][0], p4[nt8][1]);
                *(float2*)&att[ab1 + kbase + t2] = make_float2(p4[nt8][2], p4[nt8][3]);
            }
            #pragma unroll
            for (int ksl = 0; ksl < 4; ksl++) {
                int kslice = kc + ss*64 + ksl*16;
                if (kslice <= wmax) {
                    uint32_t ah[4], al[4];
                    ah[0] = pack_hi_lo(p4[2*ksl][0],   p4[2*ksl][1],   al[0]);
                    ah[1] = pack_hi_lo(p4[2*ksl][2],   p4[2*ksl][3],   al[1]);
                    ah[2] = pack_hi_lo(p4[2*ksl+1][0], p4[2*ksl+1][1], al[2]);
                    ah[3] = pack_hi_lo(p4[2*ksl+1][2], p4[2*ksl+1][3], al[3]);
                    int kloc = ss*64 + ksl*16 + t2;
                    #pragma unroll
                    for (int dt = 0; dt < 8; dt++) {
                        int db = (dt*8 + g)*SVW + kloc;
                        uint32_t bh2[2], bl2[2];
                        bh2[0] = *(const uint32_t*)&sVh[db];
                        bh2[1] = *(const uint32_t*)&sVh[db + 8];
                        bl2[0] = *(const uint32_t*)&sVl[db];
                        bl2[1] = *(const uint32_t*)&sVl[db + 8];
                        mma_16816(o[dt], ah, bh2);
                        mma_16816(o[dt], ah, bl2);
                        mma_16816(o[dt], al, bh2);
                    }
                }
            }
        }
    }

    // ---- merge l across the quad (4 lanes share each row) ----
    #pragma unroll
    for (int off = 1; off <= 2; off <<= 1) {
        l0v += __shfl_xor_sync(0xffffffffu, l0v, off);
        l1v += __shfl_xor_sync(0xffffffffu, l1v, off);
    }
    const float inv0 = 1.f / l0v, inv1 = 1.f / l1v;
    if ((lane & 3) == 0) {
        sInv[tr0]     = inv0;
        sInv[tr0 + 8] = inv1;
    }

    // ---- write O (scaled) ----
    {
        int b_ = bh >> 4, h_ = bh & 15;
        size_t ob0 = ((size_t)b_*TT + r0)*CC + h_*64;
        size_t ob1 = ((size_t)b_*TT + r1)*CC + h_*64;
        #pragma unroll
        for (int dt = 0; dt < 8; dt++) {
            *(float2*)&g_o[ob0 + dt*8 + t2] = make_float2(o[dt][0]*inv0, o[dt][1]*inv0);
            *(float2*)&g_o[ob1 + dt*8 + t2] = make_float2(o[dt][2]*inv1, o[dt][3]*inv1);
        }
    }

    // ---- zero-fill att cols [kend, TT) ----
    {
        int zc4 = (TT - kend) >> 2;
        float4 z = make_float4(0.f, 0.f, 0.f, 0.f);
        for (int i = tid; i < BLKM*zc4; i += 256) {
            int row = i / (zc4 > 0 ? zc4 : 1);
            int c4i = i - row*zc4;
            if (zc4 > 0)
                *(float4*)&att[(qbase + q0 + row)*TT + kend + c4i*4] = z;
        }
    }

    // ---- in-CTA normalization sweep (rows just written, L2-hot) ----
    __syncthreads();
    for (int row = w; row < BLKM; row += 8) {
        float inv = sInv[row];
        int n = q0 + row + 1;
        int n4 = (n + 3) >> 2;               // extra lanes hit in-tile zeros: safe
        float4* p = (float4*)(att + (qbase + q0 + row) * TT);
        for (int i = lane; i < n4; i += 32) {
            float4 v = p[i];
            v.x *= inv; v.y *= inv; v.z *= inv; v.w *= inv;
            p[i] = v;
        }
    }
}

// =====================================================================
extern "C" void kernel_launch(void* const* d_in, const int* in_sizes, int n_in,
                              void* d_out, int out_size)
{
    const float* x      = (const float*)d_in[0];
    const float* w_attn = (const float*)d_in[2];
    const float* b_attn = (const float*)d_in[3];
    const float* w_proj = (const float*)d_in[4];
    const float* b_proj = (const float*)d_in[5];
    const float* rel_k  = (const float*)d_in[6];
    float* out = (float*)d_out;

    const size_t YS = (size_t)BT*CC;
    const size_t AS = (size_t)BH*TT*TT;

    float* y_out = out;
    float* att_base = nullptr;
    int att_mode = 1;
    if ((size_t)out_size >= YS + AS) {
        y_out = out; att_base = out + YS; att_mode = 0;
    } else if ((size_t)out_size == AS) {
        att_base = out; att_mode = 0; y_out = nullptr;
    }

    cudaFuncSetAttribute(attn_kernel,
        cudaFuncAttributeMaxDynamicSharedMemorySize, ATTN_SMEM_BYTES);
    cudaFuncSetAttribute(mma_gemm_kernel<0>,
        cudaFuncAttributeMaxDynamicSharedMemorySize, GEMM_SMEM_BYTES);
    cudaFuncSetAttribute(mma_gemm_kernel<1>,
        cudaFuncAttributeMaxDynamicSharedMemorySize, GEMM_SMEM_BYTES);

    split_kernel<0><<<BT*CC/4/256, 256>>>(x);
    wsplit_kernel<0><<<dim3(3*CC/32, CC/32), dim3(32,8)>>>(w_attn, 3*CC);
    wsplit_kernel<1><<<dim3(CC/32,   CC/32), dim3(32,8)>>>(w_proj, CC);
    mma_gemm_kernel<0><<<dim3(24, 32), 256, GEMM_SMEM_BYTES>>>(b_attn, nullptr);
    qrel_kernel<<<BH*TT/32, 256>>>(rel_k);
    attn_kernel<<<dim3(TT/BLKM, BH), 256, ATTN_SMEM_BYTES>>>(att_base, att_mode);
    split_kernel<1><<<BT*CC/4/256, 256>>>(nullptr);
    mma_gemm_kernel<1><<<dim3(8, 32), 256, GEMM_SMEM_BYTES>>>(b_proj, y_out);
}

// round 11
// speedup vs baseline: 2.7526x; 1.0411x over previous
#include <cuda_runtime.h>
#include <cuda_bf16.h>
#include <math.h>
#include <stdint.h>

#define BB 2
#define TT 2048
#define CC 1024
#define HH 16
#define DD 64
#define NR 65                      // 2*MAXREL+1
#define BH (BB*HH)                 // 32
#define BT (BB*TT)                 // 4096
#define BLKM 256                   // q-rows per attention CTA (16 warps)

// ---------------- device scratch ----------------
__device__ float g_q[BH*TT*DD];        // fp32 q (for qrel)
__device__ float g_qrel[BH*TT*NR];     // [bh][t][r]
__device__ float g_o[BT*CC];           // pre-proj context
__device__ float g_y[BT*CC];           // fallback y sink
__device__ float g_att[(size_t)BH*TT*TT]; // fallback att sink

// bf16 hi/lo operands
__device__ __nv_bfloat16 g_qh[BH*TT*DD], g_ql[BH*TT*DD];   // [bh][t][d]
__device__ __nv_bfloat16 g_kh[BH*TT*DD], g_kl[BH*TT*DD];   // [bh][t][d]
__device__ __nv_bfloat16 g_vth[BH*DD*TT], g_vtl[BH*DD*TT]; // V^T [bh][d][t]
__device__ __nv_bfloat16 g_xa_hi[BT*CC],  g_xa_lo[BT*CC];
__device__ __nv_bfloat16 g_oa_hi[BT*CC],  g_oa_lo[BT*CC];
__device__ __nv_bfloat16 g_wta_hi[3*CC*CC], g_wta_lo[3*CC*CC];
__device__ __nv_bfloat16 g_wtp_hi[CC*CC],   g_wtp_lo[CC*CC];

// ===================== helpers =====================
__device__ __forceinline__ uint32_t smem_to_u32(const void* p) {
    uint32_t a;
    asm("{ .reg .u64 t; cvta.to.shared.u64 t, %1; cvt.u32.u64 %0, t; }" : "=r"(a) : "l"(p));
    return a;
}
__device__ __forceinline__ void cp_async16(uint32_t saddr, const void* gptr) {
    asm volatile("cp.async.cg.shared.global [%0], [%1], 16;" :: "r"(saddr), "l"(gptr));
}
#define CP_COMMIT() asm volatile("cp.async.commit_group;" ::: "memory")
#define CP_WAIT0()  asm volatile("cp.async.wait_group 0;" ::: "memory")

__device__ __forceinline__ void mma_16816(float* c, const uint32_t* a, const uint32_t* b) {
    asm volatile("mma.sync.aligned.m16n8k16.row.col.f32.bf16.bf16.f32 "
        "{%0,%1,%2,%3}, {%4,%5,%6,%7}, {%8,%9}, {%0,%1,%2,%3};"
        : "+f"(c[0]), "+f"(c[1]), "+f"(c[2]), "+f"(c[3])
        : "r"(a[0]), "r"(a[1]), "r"(a[2]), "r"(a[3]), "r"(b[0]), "r"(b[1]));
}
__device__ __forceinline__ uint32_t pack_bf2(__nv_bfloat16 a, __nv_bfloat16 b) {
    return ((uint32_t)__bfloat16_as_ushort(b) << 16) | __bfloat16_as_ushort(a);
}
__device__ __forceinline__ uint32_t pack_hi_lo(float p0, float p1, uint32_t& lo) {
    __nv_bfloat16 h0 = __float2bfloat16(p0), h1 = __float2bfloat16(p1);
    __nv_bfloat16 l0 = __float2bfloat16(p0 - __bfloat162float(h0));
    __nv_bfloat16 l1 = __float2bfloat16(p1 - __bfloat162float(h1));
    lo = pack_bf2(l0, l1);
    return pack_bf2(h0, h1);
}

// =====================================================================
// Conversion kernels
// =====================================================================
template<int SRC>   // 0: x param -> g_xa,  1: g_o -> g_oa
__global__ __launch_bounds__(256) void split_kernel(const float* __restrict__ in)
{
    const float* src = (SRC == 0) ? in : (const float*)g_o;
    __nv_bfloat16* hi = (SRC == 0) ? g_xa_hi : g_oa_hi;
    __nv_bfloat16* lo = (SRC == 0) ? g_xa_lo : g_oa_lo;
    int i = blockIdx.x * 256 + threadIdx.x;
    float4 v = ((const float4*)src)[i];
    float a[4] = {v.x, v.y, v.z, v.w};
    __nv_bfloat16 hb[4], lb[4];
    #pragma unroll
    for (int c = 0; c < 4; c++) {
        hb[c] = __float2bfloat16(a[c]);
        lb[c] = __float2bfloat16(a[c] - __bfloat162float(hb[c]));
    }
    ((uint32_t*)hi)[i*2+0] = pack_bf2(hb[0], hb[1]);
    ((uint32_t*)hi)[i*2+1] = pack_bf2(hb[2], hb[3]);
    ((uint32_t*)lo)[i*2+0] = pack_bf2(lb[0], lb[1]);
    ((uint32_t*)lo)[i*2+1] = pack_bf2(lb[2], lb[3]);
}

template<int WSEL>  // 0: w_attn -> g_wta, 1: w_proj -> g_wtp
__global__ __launch_bounds__(256) void wsplit_kernel(const float* __restrict__ W, int N)
{
    __shared__ float ts[32][33];
    __nv_bfloat16* hi = (WSEL == 0) ? g_wta_hi : g_wtp_hi;
    __nv_bfloat16* lo = (WSEL == 0) ? g_wta_lo : g_wtp_lo;
    int nx = blockIdx.x * 32, kx = blockIdx.y * 32;
    int tx = threadIdx.x, ty = threadIdx.y;
    #pragma unroll
    for (int j = ty; j < 32; j += 8)
        ts[j][tx] = W[(size_t)(kx + j)*N + nx + tx];
    __syncthreads();
    #pragma unroll
    for (int j = ty; j < 32; j += 8) {
        float v = ts[tx][j];
        __nv_bfloat16 h = __float2bfloat16(v);
        __nv_bfloat16 l = __float2bfloat16(v - __bfloat162float(h));
        hi[(size_t)(nx + j)*CC + kx + tx] = h;
        lo[(size_t)(nx + j)*CC + kx + tx] = l;
    }
}

// =====================================================================
// mma.sync bf16x3 GEMM, cp.async double-buffered (unchanged from R9)
// =====================================================================
#define LDA 72
#define SM_ARR (128*LDA)
#define GEMM_BUF_BYTES (4*SM_ARR*2)
#define GEMM_SMEM_BYTES (2*GEMM_BUF_BYTES)

template<int MODE>
__global__ __launch_bounds__(256) void mma_gemm_kernel(const float* __restrict__ bias,
                                                       float* __restrict__ outp)
{
    extern __shared__ __nv_bfloat16 sb[];
    const uint32_t sbase = smem_to_u32(sb);

    const int tid  = threadIdx.x;
    const int wid  = tid >> 5, lane = tid & 31;
    const int wm   = wid >> 2, wn = wid & 3;
    const int m0   = blockIdx.y * 128;
    const int n0   = blockIdx.x * 128;

    const __nv_bfloat16* Ah = (MODE == 0) ? g_xa_hi : g_oa_hi;
    const __nv_bfloat16* Al = (MODE == 0) ? g_xa_lo : g_oa_lo;
    const __nv_bfloat16* Bh = (MODE == 0) ? g_wta_hi : g_wtp_hi;
    const __nv_bfloat16* Bl = (MODE == 0) ? g_wta_lo : g_wtp_lo;

    auto load_tile = [&](int kt, int buf) {
        const int k0 = kt * 64;
        const uint32_t b0 = sbase + (uint32_t)buf * GEMM_BUF_BYTES;
        #pragma unroll
        for (int it = 0; it < 4; it++) {
            int i = tid + it * 256;
            int r = i >> 3, c8 = i & 7;
            size_t ga = (size_t)(m0 + r) * CC + k0 + c8 * 8;
            size_t gb = (size_t)(n0 + r) * CC + k0 + c8 * 8;
            uint32_t so = (uint32_t)(r * LDA + c8 * 8) * 2;
            cp_async16(b0 + so,               &Ah[ga]);
            cp_async16(b0 + SM_ARR*2 + so,    &Al[ga]);
            cp_async16(b0 + 2*SM_ARR*2 + so,  &Bh[gb]);
            cp_async16(b0 + 3*SM_ARR*2 + so,  &Bl[gb]);
        }
        CP_COMMIT();
    };

    float acc[4][4][4];
    #pragma unroll
    for (int i = 0; i < 4; i++)
        #pragma unroll
        for (int j = 0; j < 4; j++)
            #pragma unroll
            for (int c = 0; c < 4; c++) acc[i][j][c] = 0.f;

    const int g  = lane >> 2;
    const int t2 = (lane & 3) * 2;

    load_tile(0, 0);

    for (int kt = 0; kt < 16; kt++) {
        CP_WAIT0();
        __syncthreads();
        if (kt + 1 < 16) load_tile(kt + 1, (kt + 1) & 1);

        const __nv_bfloat16* bAh = sb + (kt & 1) * (4*SM_ARR);
        const __nv_bfloat16* bAl = bAh + SM_ARR;
        const __nv_bfloat16* bBh = bAh + 2*SM_ARR;
        const __nv_bfloat16* bBl = bAh + 3*SM_ARR;

        #pragma unroll
        for (int ks = 0; ks < 4; ks++) {
            const int kb = ks * 16 + t2;
            uint32_t ah[4][4], al[4][4];
            #pragma unroll
            for (int tm = 0; tm < 4; tm++) {
                int r0 = (wm*64 + tm*16 + g) * LDA + kb;
                int r1 = r0 + 8 * LDA;
                ah[tm][0] = *(const uint32_t*)&bAh[r0];
                ah[tm][1] = *(const uint32_t*)&bAh[r1];
                ah[tm][2] = *(const uint32_t*)&bAh[r0 + 8];
                ah[tm][3] = *(const uint32_t*)&bAh[r1 + 8];
                al[tm][0] = *(const uint32_t*)&bAl[r0];
                al[tm][1] = *(const uint32_t*)&bAl[r1];
                al[tm][2] = *(const uint32_t*)&bAl[r0 + 8];
                al[tm][3] = *(const uint32_t*)&bAl[r1 + 8];
            }
            #pragma unroll
            for (int tn = 0; tn < 4; tn++) {
                int rb = (wn*32 + tn*8 + g) * LDA + kb;
                uint32_t bh[2], bl[2];
                bh[0] = *(const uint32_t*)&bBh[rb];
                bh[1] = *(const uint32_t*)&bBh[rb + 8];
                bl[0] = *(const uint32_t*)&bBl[rb];
                bl[1] = *(const uint32_t*)&bBl[rb + 8];
                #pragma unroll
                for (int tm = 0; tm < 4; tm++) {
                    mma_16816(acc[tm][tn], ah[tm], bh);
                    mma_16816(acc[tm][tn], ah[tm], bl);
                    mma_16816(acc[tm][tn], al[tm], bh);
                }
            }
        }
        __syncthreads();
    }

    const int lr = lane >> 2;
    const int lc = (lane & 3) * 2;
    #pragma unroll
    for (int tm = 0; tm < 4; tm++) {
        #pragma unroll
        for (int tn = 0; tn < 4; tn++) {
            int c = n0 + wn*32 + tn*8 + lc;
            float b0 = bias[c], b1 = bias[c+1];
            #pragma unroll
            for (int half = 0; half < 2; half++) {
                int m = m0 + wm*64 + tm*16 + lr + half*8;
                float v0 = acc[tm][tn][half*2+0] + b0;
                float v1 = acc[tm][tn][half*2+1] + b1;
                if (MODE == 0) {
                    int which = c >> 10, hh = (c >> 6) & 15, dd = c & 63;
                    int b_ = m >> 11, t_ = m & 2047;
                    int bhx = b_*HH + hh;
                    __nv_bfloat16 h0 = __float2bfloat16(v0);
                    __nv_bfloat16 h1 = __float2bfloat16(v1);
                    __nv_bfloat16 l0 = __float2bfloat16(v0 - __bfloat162float(h0));
                    __nv_bfloat16 l1 = __float2bfloat16(v1 - __bfloat162float(h1));
                    if (which == 0) {
                        size_t di = ((size_t)bhx*TT + t_)*DD + dd;
                        *(float2*)&g_q[di] = make_float2(v0, v1);
                        *(uint32_t*)&g_qh[di] = pack_bf2(h0, h1);
                        *(uint32_t*)&g_ql[di] = pack_bf2(l0, l1);
                    } else if (which == 1) {
                        size_t di = ((size_t)bhx*TT + t_)*DD + dd;
                        *(uint32_t*)&g_kh[di] = pack_bf2(h0, h1);
                        *(uint32_t*)&g_kl[di] = pack_bf2(l0, l1);
                    } else {
                        size_t vb = (size_t)bhx*DD;
                        g_vth[(vb + dd    )*TT + t_] = h0;
                        g_vth[(vb + dd + 1)*TT + t_] = h1;
                        g_vtl[(vb + dd    )*TT + t_] = l0;
                        g_vtl[(vb + dd + 1)*TT + t_] = l1;
                    }
                } else {
                    float* dst = outp ? outp : g_y;
                    *(float2*)&dst[(size_t)m*CC + c] = make_float2(v0, v1);
                }
            }
        }
    }
}

// =====================================================================
// qrel
// =====================================================================
__device__ __forceinline__ float dot4(float4 a, float4 b) {
    return a.x*b.x + a.y*b.y + a.z*b.z + a.w*b.w;
}

__global__ __launch_bounds__(256) void qrel_kernel(const float* __restrict__ rel)
{
    __shared__ float rs[NR*64];
    __shared__ float qs[32*64];
    const int tid = threadIdx.x;
    const int r0  = blockIdx.x * 32;

    for (int i = tid; i < NR*16; i += 256)
        ((float4*)rs)[i] = ((const float4*)rel)[i];
    for (int i = tid; i < 32*16; i += 256) {
        int t = i >> 4, d4 = i & 15;
        *(float4*)&qs[t*64 + d4*4] = *(const float4*)&g_q[(size_t)(r0+t)*64 + d4*4];
    }
    __syncthreads();

    for (int i = tid; i < 32*NR; i += 256) {
        int t = i / NR, r = i % NR;
        const float4* qq = (const float4*)&qs[t*64];
        const float4* rr = (const float4*)&rs[r*64];
        float acc = 0.f;
        #pragma unroll
        for (int d4 = 0; d4 < 16; d4++) acc += dot4(qq[d4], rr[d4]);
        g_qrel[(size_t)(r0+t)*NR + r] = acc;
    }
}

// =====================================================================
// Single-pass flash attention, 512 threads / 256 q-rows per CTA.
// Warp w owns rows q0+16w..q0+16w+15. Far-tile rel fast path.
// =====================================================================
#define SKW 72          // K smem row pitch (bf16)
#define SVW 136         // V^T smem row pitch (bf16)
#define NTH 512
#define ATTN_SMEM_BYTES (2*128*SKW*2 + 2*64*SVW*2 + BLKM*66*4 + BLKM*4 + 64)

__global__ __launch_bounds__(NTH, 1) void attn_kernel(float* __restrict__ out_att, int att_mode)
{
    extern __shared__ char smc[];
    __nv_bfloat16* sKh = (__nv_bfloat16*)smc;          // [128][72]
    __nv_bfloat16* sKl = sKh + 128*SKW;
    __nv_bfloat16* sVh = sKl + 128*SKW;                // [64][136]
    __nv_bfloat16* sVl = sVh + 64*SVW;
    float* QR = (float*)(sVl + 64*SVW);                // [256][66]
    float* sInv = QR + BLKM*66;                        // [256]

    const int tid = threadIdx.x, w = tid >> 5, lane = tid & 31;
    const int g = lane >> 2, t2 = (lane & 3) * 2;
    const int q0 = blockIdx.x * BLKM;
    const int bh = blockIdx.y;
    const int kend = q0 + BLKM;
    const size_t qbase = (size_t)bh * TT;
    float* att = att_mode ? g_att : out_att;

    for (int i = tid; i < BLKM*NR; i += NTH) {
        int t = i / NR, r = i % NR;
        QR[t*66 + r] = g_qrel[(qbase + q0 + t)*NR + r];
    }

    const int tr0 = w*16 + g;
    const int r0 = q0 + tr0;
    const int r1 = r0 + 8;
    const int wmax = q0 + w*16 + 15;

    // Q fragments (hi/lo)
    uint32_t qfh[4][4], qfl[4][4];
    {
        size_t ra = (qbase + (size_t)r0) * DD;
        size_t rb = ra + 8*DD;
        #pragma unroll
        for (int ks = 0; ks < 4; ks++) {
            int c0 = ks*16 + t2;
            qfh[ks][0] = *(const uint32_t*)&g_qh[ra + c0];
            qfh[ks][1] = *(const uint32_t*)&g_qh[rb + c0];
            qfh[ks][2] = *(const uint32_t*)&g_qh[ra + c0 + 8];
            qfh[ks][3] = *(const uint32_t*)&g_qh[rb + c0 + 8];
            qfl[ks][0] = *(const uint32_t*)&g_ql[ra + c0];
            qfl[ks][1] = *(const uint32_t*)&g_ql[rb + c0];
            qfl[ks][2] = *(const uint32_t*)&g_ql[ra + c0 + 8];
            qfl[ks][3] = *(const uint32_t*)&g_ql[rb + c0 + 8];
        }
    }
    __syncthreads();
    const float qr0c = QR[tr0*66];        // rel constant for far tiles (idx 0)
    const float qr1c = QR[(tr0+8)*66];

    float o[8][4];
    #pragma unroll
    for (int dt = 0; dt < 8; dt++)
        #pragma unroll
        for (int c = 0; c < 4; c++) o[dt][c] = 0.f;
    float l0v = 0.f, l1v = 0.f;

    const size_t ab0 = (qbase + (size_t)r0) * TT;
    const size_t ab1 = (qbase + (size_t)r1) * TT;

    for (int kc = 0; kc < kend; kc += 128) {
        __syncthreads();
        for (int i = tid; i < 128*8; i += NTH) {
            int r = i >> 3, c = i & 7;
            size_t gs = (qbase + kc + r)*DD + c*8;
            *(float4*)&sKh[r*SKW + c*8] = *(const float4*)&g_kh[gs];
            *(float4*)&sKl[r*SKW + c*8] = *(const float4*)&g_kl[gs];
        }
        for (int i = tid; i < 64*16; i += NTH) {
            int d = i >> 4, c = i & 15;
            size_t gs = ((size_t)bh*DD + d)*TT + kc + c*8;
            *(float4*)&sVh[d*SVW + c*8] = *(const float4*)&g_vth[gs];
            *(float4*)&sVl[d*SVW + c*8] = *(const float4*)&g_vtl[gs];
        }
        __syncthreads();

        #pragma unroll
        for (int ss2 = 0; ss2 < 4; ss2++) {       // 32-key sub-slices
            float p4[4][4];
            #pragma unroll
            for (int nt4 = 0; nt4 < 4; nt4++) {
                int nt = ss2*4 + nt4;
                int kbase = kc + nt*8;
                float c4[4] = {0.f, 0.f, 0.f, 0.f};
                if (kbase <= wmax) {
                    #pragma unroll
                    for (int ks = 0; ks < 4; ks++) {
                        int rb = (nt*8 + g)*SKW + ks*16 + t2;
                        uint32_t bh2[2], bl2[2];
                        bh2[0] = *(const uint32_t*)&sKh[rb];
                        bh2[1] = *(const uint32_t*)&sKh[rb + 8];
                        bl2[0] = *(const uint32_t*)&sKl[rb];
                        bl2[1] = *(const uint32_t*)&sKl[rb + 8];
                        mma_16816(c4, qfh[ks], bh2);
                        mma_16816(c4, qfh[ks], bl2);
                        mma_16816(c4, qfl[ks], bh2);
                    }
                }
                int kg = kbase + t2;
                if (kbase + 8 + 32 <= r0) {
                    // FAR tile: dist <= -33 for both rows -> rel idx 0, no mask
                    p4[nt4][0] = __expf((c4[0] + qr0c) * 0.125f);
                    p4[nt4][1] = __expf((c4[1] + qr0c) * 0.125f);
                    p4[nt4][2] = __expf((c4[2] + qr1c) * 0.125f);
                    p4[nt4][3] = __expf((c4[3] + qr1c) * 0.125f);
                    l0v += p4[nt4][0] + p4[nt4][1];
                    l1v += p4[nt4][2] + p4[nt4][3];
                } else {
                    {
                        int d0 = min(max(kg - r0, -32), 32) + 32;
                        int d1 = min(max(kg + 1 - r0, -32), 32) + 32;
                        float s0 = (c4[0] + QR[tr0*66 + d0]) * 0.125f;
                        float s1 = (c4[1] + QR[tr0*66 + d1]) * 0.125f;
                        p4[nt4][0] = (kg     <= r0) ? __expf(fminf(s0, 80.f)) : 0.f;
                        p4[nt4][1] = (kg + 1 <= r0) ? __expf(fminf(s1, 80.f)) : 0.f;
                        l0v += p4[nt4][0] + p4[nt4][1];
                    }
                    {
                        int d0 = min(max(kg - r1, -32), 32) + 32;
                        int d1 = min(max(kg + 1 - r1, -32), 32) + 32;
                        float s0 = (c4[2] + QR[(tr0+8)*66 + d0]) * 0.125f;
                        float s1 = (c4[3] + QR[(tr0+8)*66 + d1]) * 0.125f;
                        p4[nt4][2] = (kg     <= r1) ? __expf(fminf(s0, 80.f)) : 0.f;
                        p4[nt4][3] = (kg + 1 <= r1) ? __expf(fminf(s1, 80.f)) : 0.f;
                        l1v += p4[nt4][2] + p4[nt4][3];
                    }
                }
                *(float2*)&att[ab0 + kbase + t2] = make_float2(p4[nt4][0], p4[nt4][1]);
                *(float2*)&att[ab1 + kbase + t2] = make_float2(p4[nt4][2], p4[nt4][3]);
            }
            #pragma unroll
            for (int ksl = 0; ksl < 2; ksl++) {
                int kslice = kc + ss2*32 + ksl*16;
                if (kslice <= wmax) {
                    uint32_t ah[4], al[4];
                    ah[0] = pack_hi_lo(p4[2*ksl][0],   p4[2*ksl][1],   al[0]);
                    ah[1] = pack_hi_lo(p4[2*ksl][2],   p4[2*ksl][3],   al[1]);
                    ah[2] = pack_hi_lo(p4[2*ksl+1][0], p4[2*ksl+1][1], al[2]);
                    ah[3] = pack_hi_lo(p4[2*ksl+1][2], p4[2*ksl+1][3], al[3]);
                    int kloc = ss2*32 + ksl*16 + t2;
                    #pragma unroll
                    for (int dt = 0; dt < 8; dt++) {
                        int db = (dt*8 + g)*SVW + kloc;
                        uint32_t bh2[2], bl2[2];
                        bh2[0] = *(const uint32_t*)&sVh[db];
                        bh2[1] = *(const uint32_t*)&sVh[db + 8];
                        bl2[0] = *(const uint32_t*)&sVl[db];
                        bl2[1] = *(const uint32_t*)&sVl[db + 8];
                        mma_16816(o[dt], ah, bh2);
                        mma_16816(o[dt], ah, bl2);
                        mma_16816(o[dt], al, bh2);
                    }
                }
            }
        }
    }

    // ---- merge l across the quad (4 lanes share each row) ----
    #pragma unroll
    for (int off = 1; off <= 2; off <<= 1) {
        l0v += __shfl_xor_sync(0xffffffffu, l0v, off);
        l1v += __shfl_xor_sync(0xffffffffu, l1v, off);
    }
    const float inv0 = 1.f / l0v, inv1 = 1.f / l1v;
    if ((lane & 3) == 0) {
        sInv[tr0]     = inv0;
        sInv[tr0 + 8] = inv1;
    }

    // ---- write O (scaled) ----
    {
        int b_ = bh >> 4, h_ = bh & 15;
        size_t ob0 = ((size_t)b_*TT + r0)*CC + h_*64;
        size_t ob1 = ((size_t)b_*TT + r1)*CC + h_*64;
        #pragma unroll
        for (int dt = 0; dt < 8; dt++) {
            *(float2*)&g_o[ob0 + dt*8 + t2] = make_float2(o[dt][0]*inv0, o[dt][1]*inv0);
            *(float2*)&g_o[ob1 + dt*8 + t2] = make_float2(o[dt][2]*inv1, o[dt][3]*inv1);
        }
    }

    // ---- zero-fill att cols [kend, TT) ----
    {
        int zc4 = (TT - kend) >> 2;
        float4 z = make_float4(0.f, 0.f, 0.f, 0.f);
        if (zc4 > 0) {
            for (int i = tid; i < BLKM*zc4; i += NTH) {
                int row = i / zc4;
                int c4i = i - row*zc4;
                *(float4*)&att[(qbase + q0 + row)*TT + kend + c4i*4] = z;
            }
        }
    }

    // ---- in-CTA normalization sweep (rows just written, L2-hot) ----
    __syncthreads();
    for (int row = w; row < BLKM; row += 16) {
        float inv = sInv[row];
        int n = q0 + row + 1;
        int n4 = (n + 3) >> 2;
        float4* p = (float4*)(att + (qbase + q0 + row) * TT);
        for (int i = lane; i < n4; i += 32) {
            float4 v = p[i];
            v.x *= inv; v.y *= inv; v.z *= inv; v.w *= inv;
            p[i] = v;
        }
    }
}

// =====================================================================
extern "C" void kernel_launch(void* const* d_in, const int* in_sizes, int n_in,
                              void* d_out, int out_size)
{
    const float* x      = (const float*)d_in[0];
    const float* w_attn = (const float*)d_in[2];
    const float* b_attn = (const float*)d_in[3];
    const float* w_proj = (const float*)d_in[4];
    const float* b_proj = (const float*)d_in[5];
    const float* rel_k  = (const float*)d_in[6];
    float* out = (float*)d_out;

    const size_t YS = (size_t)BT*CC;
    const size_t AS = (size_t)BH*TT*TT;

    float* y_out = out;
    float* att_base = nullptr;
    int att_mode = 1;
    if ((size_t)out_size >= YS + AS) {
        y_out = out; att_base = out + YS; att_mode = 0;
    } else if ((size_t)out_size == AS) {
        att_base = out; att_mode = 0; y_out = nullptr;
    }

    cudaFuncSetAttribute(attn_kernel,
        cudaFuncAttributeMaxDynamicSharedMemorySize, ATTN_SMEM_BYTES);
    cudaFuncSetAttribute(mma_gemm_kernel<0>,
        cudaFuncAttributeMaxDynamicSharedMemorySize, GEMM_SMEM_BYTES);
    cudaFuncSetAttribute(mma_gemm_kernel<1>,
        cudaFuncAttributeMaxDynamicSharedMemorySize, GEMM_SMEM_BYTES);

    split_kernel<0><<<BT*CC/4/256, 256>>>(x);
    wsplit_kernel<0><<<dim3(3*CC/32, CC/32), dim3(32,8)>>>(w_attn, 3*CC);
    wsplit_kernel<1><<<dim3(CC/32,   CC/32), dim3(32,8)>>>(w_proj, CC);
    mma_gemm_kernel<0><<<dim3(24, 32), 256, GEMM_SMEM_BYTES>>>(b_attn, nullptr);
    qrel_kernel<<<BH*TT/32, 256>>>(rel_k);
    attn_kernel<<<dim3(TT/BLKM, BH), NTH, ATTN_SMEM_BYTES>>>(att_base, att_mode);
    split_kernel<1><<<BT*CC/4/256, 256>>>(nullptr);
    mma_gemm_kernel<1><<<dim3(8, 32), 256, GEMM_SMEM_BYTES>>>(b_proj, y_out);
}

// round 12
// speedup vs baseline: 2.7527x; 1.0000x over previous
#include <cuda_runtime.h>
#include <cuda_bf16.h>
#include <math.h>
#include <stdint.h>

#define BB 2
#define TT 2048
#define CC 1024
#define HH 16
#define DD 64
#define NR 65                      // 2*MAXREL+1
#define BH (BB*HH)                 // 32
#define BT (BB*TT)                 // 4096
#define BLKM 256                   // q-rows per attention CTA (16 warps)

// ---------------- device scratch ----------------
__device__ float g_q[BH*TT*DD];        // fp32 q (for qrel)
__device__ float g_qrel[BH*TT*NR];     // [bh][t][r]
__device__ float g_o[BT*CC];           // pre-proj context
__device__ float g_y[BT*CC];           // fallback y sink
__device__ float g_att[(size_t)BH*TT*TT]; // fallback att sink

// bf16 hi/lo operands
__device__ __nv_bfloat16 g_qh[BH*TT*DD], g_ql[BH*TT*DD];   // [bh][t][d]
__device__ __nv_bfloat16 g_kh[BH*TT*DD], g_kl[BH*TT*DD];   // [bh][t][d]
__device__ __nv_bfloat16 g_vth[BH*DD*TT], g_vtl[BH*DD*TT]; // V^T [bh][d][t]
__device__ __nv_bfloat16 g_xa_hi[BT*CC],  g_xa_lo[BT*CC];
__device__ __nv_bfloat16 g_oa_hi[BT*CC],  g_oa_lo[BT*CC];
__device__ __nv_bfloat16 g_wta_hi[3*CC*CC], g_wta_lo[3*CC*CC];
__device__ __nv_bfloat16 g_wtp_hi[CC*CC],   g_wtp_lo[CC*CC];

// ===================== helpers =====================
__device__ __forceinline__ uint32_t smem_to_u32(const void* p) {
    uint32_t a;
    asm("{ .reg .u64 t; cvta.to.shared.u64 t, %1; cvt.u32.u64 %0, t; }" : "=r"(a) : "l"(p));
    return a;
}
__device__ __forceinline__ void cp_async16(uint32_t saddr, const void* gptr) {
    asm volatile("cp.async.cg.shared.global [%0], [%1], 16;" :: "r"(saddr), "l"(gptr));
}
#define CP_COMMIT() asm volatile("cp.async.commit_group;" ::: "memory")
#define CP_WAIT0()  asm volatile("cp.async.wait_group 0;" ::: "memory")

__device__ __forceinline__ void mma_16816(float* c, const uint32_t* a, const uint32_t* b) {
    asm volatile("mma.sync.aligned.m16n8k16.row.col.f32.bf16.bf16.f32 "
        "{%0,%1,%2,%3}, {%4,%5,%6,%7}, {%8,%9}, {%0,%1,%2,%3};"
        : "+f"(c[0]), "+f"(c[1]), "+f"(c[2]), "+f"(c[3])
        : "r"(a[0]), "r"(a[1]), "r"(a[2]), "r"(a[3]), "r"(b[0]), "r"(b[1]));
}
__device__ __forceinline__ uint32_t pack_bf2(__nv_bfloat16 a, __nv_bfloat16 b) {
    return ((uint32_t)__bfloat16_as_ushort(b) << 16) | __bfloat16_as_ushort(a);
}
__device__ __forceinline__ uint32_t pack_hi_lo(float p0, float p1, uint32_t& lo) {
    __nv_bfloat16 h0 = __float2bfloat16(p0), h1 = __float2bfloat16(p1);
    __nv_bfloat16 l0 = __float2bfloat16(p0 - __bfloat162float(h0));
    __nv_bfloat16 l1 = __float2bfloat16(p1 - __bfloat162float(h1));
    lo = pack_bf2(l0, l1);
    return pack_bf2(h0, h1);
}

// =====================================================================
// Conversion kernels
// =====================================================================
template<int SRC>   // 0: x param -> g_xa,  1: g_o -> g_oa
__global__ __launch_bounds__(256) void split_kernel(const float* __restrict__ in)
{
    const float* src = (SRC == 0) ? in : (const float*)g_o;
    __nv_bfloat16* hi = (SRC == 0) ? g_xa_hi : g_oa_hi;
    __nv_bfloat16* lo = (SRC == 0) ? g_xa_lo : g_oa_lo;
    int i = blockIdx.x * 256 + threadIdx.x;
    float4 v = ((const float4*)src)[i];
    float a[4] = {v.x, v.y, v.z, v.w};
    __nv_bfloat16 hb[4], lb[4];
    #pragma unroll
    for (int c = 0; c < 4; c++) {
        hb[c] = __float2bfloat16(a[c]);
        lb[c] = __float2bfloat16(a[c] - __bfloat162float(hb[c]));
    }
    ((uint32_t*)hi)[i*2+0] = pack_bf2(hb[0], hb[1]);
    ((uint32_t*)hi)[i*2+1] = pack_bf2(hb[2], hb[3]);
    ((uint32_t*)lo)[i*2+0] = pack_bf2(lb[0], lb[1]);
    ((uint32_t*)lo)[i*2+1] = pack_bf2(lb[2], lb[3]);
}

template<int WSEL>  // 0: w_attn -> g_wta, 1: w_proj -> g_wtp
__global__ __launch_bounds__(256) void wsplit_kernel(const float* __restrict__ W, int N)
{
    __shared__ float ts[32][33];
    __nv_bfloat16* hi = (WSEL == 0) ? g_wta_hi : g_wtp_hi;
    __nv_bfloat16* lo = (WSEL == 0) ? g_wta_lo : g_wtp_lo;
    int nx = blockIdx.x * 32, kx = blockIdx.y * 32;
    int tx = threadIdx.x, ty = threadIdx.y;
    #pragma unroll
    for (int j = ty; j < 32; j += 8)
        ts[j][tx] = W[(size_t)(kx + j)*N + nx + tx];
    __syncthreads();
    #pragma unroll
    for (int j = ty; j < 32; j += 8) {
        float v = ts[tx][j];
        __nv_bfloat16 h = __float2bfloat16(v);
        __nv_bfloat16 l = __float2bfloat16(v - __bfloat162float(h));
        hi[(size_t)(nx + j)*CC + kx + tx] = h;
        lo[(size_t)(nx + j)*CC + kx + tx] = l;
    }
}

// =====================================================================
// mma.sync bf16x3 GEMM, cp.async double-buffered (unchanged from R9)
// =====================================================================
#define LDA 72
#define SM_ARR (128*LDA)
#define GEMM_BUF_BYTES (4*SM_ARR*2)
#define GEMM_SMEM_BYTES (2*GEMM_BUF_BYTES)

template<int MODE>
__global__ __launch_bounds__(256) void mma_gemm_kernel(const float* __restrict__ bias,
                                                       float* __restrict__ outp)
{
    extern __shared__ __nv_bfloat16 sb[];
    const uint32_t sbase = smem_to_u32(sb);

    const int tid  = threadIdx.x;
    const int wid  = tid >> 5, lane = tid & 31;
    const int wm   = wid >> 2, wn = wid & 3;
    const int m0   = blockIdx.y * 128;
    const int n0   = blockIdx.x * 128;

    const __nv_bfloat16* Ah = (MODE == 0) ? g_xa_hi : g_oa_hi;
    const __nv_bfloat16* Al = (MODE == 0) ? g_xa_lo : g_oa_lo;
    const __nv_bfloat16* Bh = (MODE == 0) ? g_wta_hi : g_wtp_hi;
    const __nv_bfloat16* Bl = (MODE == 0) ? g_wta_lo : g_wtp_lo;

    auto load_tile = [&](int kt, int buf) {
        const int k0 = kt * 64;
        const uint32_t b0 = sbase + (uint32_t)buf * GEMM_BUF_BYTES;
        #pragma unroll
        for (int it = 0; it < 4; it++) {
            int i = tid + it * 256;
            int r = i >> 3, c8 = i & 7;
            size_t ga = (size_t)(m0 + r) * CC + k0 + c8 * 8;
            size_t gb = (size_t)(n0 + r) * CC + k0 + c8 * 8;
            uint32_t so = (uint32_t)(r * LDA + c8 * 8) * 2;
            cp_async16(b0 + so,               &Ah[ga]);
            cp_async16(b0 + SM_ARR*2 + so,    &Al[ga]);
            cp_async16(b0 + 2*SM_ARR*2 + so,  &Bh[gb]);
            cp_async16(b0 + 3*SM_ARR*2 + so,  &Bl[gb]);
        }
        CP_COMMIT();
    };

    float acc[4][4][4];
    #pragma unroll
    for (int i = 0; i < 4; i++)
        #pragma unroll
        for (int j = 0; j < 4; j++)
            #pragma unroll
            for (int c = 0; c < 4; c++) acc[i][j][c] = 0.f;

    const int g  = lane >> 2;
    const int t2 = (lane & 3) * 2;

    load_tile(0, 0);

    for (int kt = 0; kt < 16; kt++) {
        CP_WAIT0();
        __syncthreads();
        if (kt + 1 < 16) load_tile(kt + 1, (kt + 1) & 1);

        const __nv_bfloat16* bAh = sb + (kt & 1) * (4*SM_ARR);
        const __nv_bfloat16* bAl = bAh + SM_ARR;
        const __nv_bfloat16* bBh = bAh + 2*SM_ARR;
        const __nv_bfloat16* bBl = bAh + 3*SM_ARR;

        #pragma unroll
        for (int ks = 0; ks < 4; ks++) {
            const int kb = ks * 16 + t2;
            uint32_t ah[4][4], al[4][4];
            #pragma unroll
            for (int tm = 0; tm < 4; tm++) {
                int r0 = (wm*64 + tm*16 + g) * LDA + kb;
                int r1 = r0 + 8 * LDA;
                ah[tm][0] = *(const uint32_t*)&bAh[r0];
                ah[tm][1] = *(const uint32_t*)&bAh[r1];
                ah[tm][2] = *(const uint32_t*)&bAh[r0 + 8];
                ah[tm][3] = *(const uint32_t*)&bAh[r1 + 8];
                al[tm][0] = *(const uint32_t*)&bAl[r0];
                al[tm][1] = *(const uint32_t*)&bAl[r1];
                al[tm][2] = *(const uint32_t*)&bAl[r0 + 8];
                al[tm][3] = *(const uint32_t*)&bAl[r1 + 8];
            }
            #pragma unroll
            for (int tn = 0; tn < 4; tn++) {
                int rb = (wn*32 + tn*8 + g) * LDA + kb;
                uint32_t bh[2], bl[2];
                bh[0] = *(const uint32_t*)&bBh[rb];
                bh[1] = *(const uint32_t*)&bBh[rb + 8];
                bl[0] = *(const uint32_t*)&bBl[rb];
                bl[1] = *(const uint32_t*)&bBl[rb + 8];
                #pragma unroll
                for (int tm = 0; tm < 4; tm++) {
                    mma_16816(acc[tm][tn], ah[tm], bh);
                    mma_16816(acc[tm][tn], ah[tm], bl);
                    mma_16816(acc[tm][tn], al[tm], bh);
                }
            }
        }
        __syncthreads();
    }

    const int lr = lane >> 2;
    const int lc = (lane & 3) * 2;
    #pragma unroll
    for (int tm = 0; tm < 4; tm++) {
        #pragma unroll
        for (int tn = 0; tn < 4; tn++) {
            int c = n0 + wn*32 + tn*8 + lc;
            float b0 = bias[c], b1 = bias[c+1];
            #pragma unroll
            for (int half = 0; half < 2; half++) {
                int m = m0 + wm*64 + tm*16 + lr + half*8;
                float v0 = acc[tm][tn][half*2+0] + b0;
                float v1 = acc[tm][tn][half*2+1] + b1;
                if (MODE == 0) {
                    int which = c >> 10, hh = (c >> 6) & 15, dd = c & 63;
                    int b_ = m >> 11, t_ = m & 2047;
                    int bhx = b_*HH + hh;
                    __nv_bfloat16 h0 = __float2bfloat16(v0);
                    __nv_bfloat16 h1 = __float2bfloat16(v1);
                    __nv_bfloat16 l0 = __float2bfloat16(v0 - __bfloat162float(h0));
                    __nv_bfloat16 l1 = __float2bfloat16(v1 - __bfloat162float(h1));
                    if (which == 0) {
                        size_t di = ((size_t)bhx*TT + t_)*DD + dd;
                        *(float2*)&g_q[di] = make_float2(v0, v1);
                        *(uint32_t*)&g_qh[di] = pack_bf2(h0, h1);
                        *(uint32_t*)&g_ql[di] = pack_bf2(l0, l1);
                    } else if (which == 1) {
                        size_t di = ((size_t)bhx*TT + t_)*DD + dd;
                        *(uint32_t*)&g_kh[di] = pack_bf2(h0, h1);
                        *(uint32_t*)&g_kl[di] = pack_bf2(l0, l1);
                    } else {
                        size_t vb = (size_t)bhx*DD;
                        g_vth[(vb + dd    )*TT + t_] = h0;
                        g_vth[(vb + dd + 1)*TT + t_] = h1;
                        g_vtl[(vb + dd    )*TT + t_] = l0;
                        g_vtl[(vb + dd + 1)*TT + t_] = l1;
                    }
                } else {
                    float* dst = outp ? outp : g_y;
                    *(float2*)&dst[(size_t)m*CC + c] = make_float2(v0, v1);
                }
            }
        }
    }
}

// =====================================================================
// qrel
// =====================================================================
__device__ __forceinline__ float dot4(float4 a, float4 b) {
    return a.x*b.x + a.y*b.y + a.z*b.z + a.w*b.w;
}

__global__ __launch_bounds__(256) void qrel_kernel(const float* __restrict__ rel)
{
    __shared__ float rs[NR*64];
    __shared__ float qs[32*64];
    const int tid = threadIdx.x;
    const int r0  = blockIdx.x * 32;

    for (int i = tid; i < NR*16; i += 256)
        ((float4*)rs)[i] = ((const float4*)rel)[i];
    for (int i = tid; i < 32*16; i += 256) {
        int t = i >> 4, d4 = i & 15;
        *(float4*)&qs[t*64 + d4*4] = *(const float4*)&g_q[(size_t)(r0+t)*64 + d4*4];
    }
    __syncthreads();

    for (int i = tid; i < 32*NR; i += 256) {
        int t = i / NR, r = i % NR;
        const float4* qq = (const float4*)&qs[t*64];
        const float4* rr = (const float4*)&rs[r*64];
        float acc = 0.f;
        #pragma unroll
        for (int d4 = 0; d4 < 16; d4++) acc += dot4(qq[d4], rr[d4]);
        g_qrel[(size_t)(r0+t)*NR + r] = acc;
    }
}

// =====================================================================
// Single-pass flash attention, 512 threads / 256 q-rows per CTA.
// Warp w owns rows q0+16w..q0+16w+15. Far-tile rel fast path.
// =====================================================================
#define SKW 72          // K smem row pitch (bf16)
#define SVW 136         // V^T smem row pitch (bf16)
#define NTH 512
#define ATTN_SMEM_BYTES (2*128*SKW*2 + 2*64*SVW*2 + BLKM*66*4 + BLKM*4 + 64)

__global__ __launch_bounds__(NTH, 1) void attn_kernel(float* __restrict__ out_att, int att_mode)
{
    extern __shared__ char smc[];
    __nv_bfloat16* sKh = (__nv_bfloat16*)smc;          // [128][72]
    __nv_bfloat16* sKl = sKh + 128*SKW;
    __nv_bfloat16* sVh = sKl + 128*SKW;                // [64][136]
    __nv_bfloat16* sVl = sVh + 64*SVW;
    float* QR = (float*)(sVl + 64*SVW);                // [256][66]
    float* sInv = QR + BLKM*66;                        // [256]

    const int tid = threadIdx.x, w = tid >> 5, lane = tid & 31;
    const int g = lane >> 2, t2 = (lane & 3) * 2;
    const int q0 = blockIdx.x * BLKM;
    const int bh = blockIdx.y;
    const int kend = q0 + BLKM;
    const size_t qbase = (size_t)bh * TT;
    float* att = att_mode ? g_att : out_att;

    for (int i = tid; i < BLKM*NR; i += NTH) {
        int t = i / NR, r = i % NR;
        QR[t*66 + r] = g_qrel[(qbase + q0 + t)*NR + r];
    }

    const int tr0 = w*16 + g;
    const int r0 = q0 + tr0;
    const int r1 = r0 + 8;
    const int wmax = q0 + w*16 + 15;

    // Q fragments (hi/lo)
    uint32_t qfh[4][4], qfl[4][4];
    {
        size_t ra = (qbase + (size_t)r0) * DD;
        size_t rb = ra + 8*DD;
        #pragma unroll
        for (int ks = 0; ks < 4; ks++) {
            int c0 = ks*16 + t2;
            qfh[ks][0] = *(const uint32_t*)&g_qh[ra + c0];
            qfh[ks][1] = *(const uint32_t*)&g_qh[rb + c0];
            qfh[ks][2] = *(const uint32_t*)&g_qh[ra + c0 + 8];
            qfh[ks][3] = *(const uint32_t*)&g_qh[rb + c0 + 8];
            qfl[ks][0] = *(const uint32_t*)&g_ql[ra + c0];
            qfl[ks][1] = *(const uint32_t*)&g_ql[rb + c0];
            qfl[ks][2] = *(const uint32_t*)&g_ql[ra + c0 + 8];
            qfl[ks][3] = *(const uint32_t*)&g_ql[rb + c0 + 8];
        }
    }
    __syncthreads();
    const float qr0c = QR[tr0*66];        // rel constant for far tiles (idx 0)
    const float qr1c = QR[(tr0+8)*66];

    float o[8][4];
    #pragma unroll
    for (int dt = 0; dt < 8; dt++)
        #pragma unroll
        for (int c = 0; c < 4; c++) o[dt][c] = 0.f;
    float l0v = 0.f, l1v = 0.f;

    const size_t ab0 = (qbase + (size_t)r0) * TT;
    const size_t ab1 = (qbase + (size_t)r1) * TT;

    for (int kc = 0; kc < kend; kc += 128) {
        __syncthreads();
        for (int i = tid; i < 128*8; i += NTH) {
            int r = i >> 3, c = i & 7;
            size_t gs = (qbase + kc + r)*DD + c*8;
            *(float4*)&sKh[r*SKW + c*8] = *(const float4*)&g_kh[gs];
            *(float4*)&sKl[r*SKW + c*8] = *(const float4*)&g_kl[gs];
        }
        for (int i = tid; i < 64*16; i += NTH) {
            int d = i >> 4, c = i & 15;
            size_t gs = ((size_t)bh*DD + d)*TT + kc + c*8;
            *(float4*)&sVh[d*SVW + c*8] = *(const float4*)&g_vth[gs];
            *(float4*)&sVl[d*SVW + c*8] = *(const float4*)&g_vtl[gs];
        }
        __syncthreads();

        #pragma unroll
        for (int ss2 = 0; ss2 < 4; ss2++) {       // 32-key sub-slices
            float p4[4][4];
            #pragma unroll
            for (int nt4 = 0; nt4 < 4; nt4++) {
                int nt = ss2*4 + nt4;
                int kbase = kc + nt*8;
                float c4[4] = {0.f, 0.f, 0.f, 0.f};
                if (kbase <= wmax) {
                    #pragma unroll
                    for (int ks = 0; ks < 4; ks++) {
                        int rb = (nt*8 + g)*SKW + ks*16 + t2;
                        uint32_t bh2[2], bl2[2];
                        bh2[0] = *(const uint32_t*)&sKh[rb];
                        bh2[1] = *(const uint32_t*)&sKh[rb + 8];
                        bl2[0] = *(const uint32_t*)&sKl[rb];
                        bl2[1] = *(const uint32_t*)&sKl[rb + 8];
                        mma_16816(c4, qfh[ks], bh2);
                        mma_16816(c4, qfh[ks], bl2);
                        mma_16816(c4, qfl[ks], bh2);
                    }
                }
                int kg = kbase + t2;
                if (kbase + 8 + 32 <= r0) {
                    // FAR tile: dist <= -33 for both rows -> rel idx 0, no mask
                    p4[nt4][0] = __expf((c4[0] + qr0c) * 0.125f);
                    p4[nt4][1] = __expf((c4[1] + qr0c) * 0.125f);
                    p4[nt4][2] = __expf((c4[2] + qr1c) * 0.125f);
                    p4[nt4][3] = __expf((c4[3] + qr1c) * 0.125f);
                    l0v += p4[nt4][0] + p4[nt4][1];
                    l1v += p4[nt4][2] + p4[nt4][3];
                } else {
                    {
                        int d0 = min(max(kg - r0, -32), 32) + 32;
                        int d1 = min(max(kg + 1 - r0, -32), 32) + 32;
                        float s0 = (c4[0] + QR[tr0*66 + d0]) * 0.125f;
                        float s1 = (c4[1] + QR[tr0*66 + d1]) * 0.125f;
                        p4[nt4][0] = (kg     <= r0) ? __expf(fminf(s0, 80.f)) : 0.f;
                        p4[nt4][1] = (kg + 1 <= r0) ? __expf(fminf(s1, 80.f)) : 0.f;
                        l0v += p4[nt4][0] + p4[nt4][1];
                    }
                    {
                        int d0 = min(max(kg - r1, -32), 32) + 32;
                        int d1 = min(max(kg + 1 - r1, -32), 32) + 32;
                        float s0 = (c4[2] + QR[(tr0+8)*66 + d0]) * 0.125f;
                        float s1 = (c4[3] + QR[(tr0+8)*66 + d1]) * 0.125f;
                        p4[nt4][2] = (kg     <= r1) ? __expf(fminf(s0, 80.f)) : 0.f;
                        p4[nt4][3] = (kg + 1 <= r1) ? __expf(fminf(s1, 80.f)) : 0.f;
                        l1v += p4[nt4][2] + p4[nt4][3];
                    }
                }
                *(float2*)&att[ab0 + kbase + t2] = make_float2(p4[nt4][0], p4[nt4][1]);
                *(float2*)&att[ab1 + kbase + t2] = make_float2(p4[nt4][2], p4[nt4][3]);
            }
            #pragma unroll
            for (int ksl = 0; ksl < 2; ksl++) {
                int kslice = kc + ss2*32 + ksl*16;
                if (kslice <= wmax) {
                    uint32_t ah[4], al[4];
                    ah[0] = pack_hi_lo(p4[2*ksl][0],   p4[2*ksl][1],   al[0]);
                    ah[1] = pack_hi_lo(p4[2*ksl][2],   p4[2*ksl][3],   al[1]);
                    ah[2] = pack_hi_lo(p4[2*ksl+1][0], p4[2*ksl+1][1], al[2]);
                    ah[3] = pack_hi_lo(p4[2*ksl+1][2], p4[2*ksl+1][3], al[3]);
                    int kloc = ss2*32 + ksl*16 + t2;
                    #pragma unroll
                    for (int dt = 0; dt < 8; dt++) {
                        int db = (dt*8 + g)*SVW + kloc;
                        uint32_t bh2[2], bl2[2];
                        bh2[0] = *(const uint32_t*)&sVh[db];
                        bh2[1] = *(const uint32_t*)&sVh[db + 8];
                        bl2[0] = *(const uint32_t*)&sVl[db];
                        bl2[1] = *(const uint32_t*)&sVl[db + 8];
                        mma_16816(o[dt], ah, bh2);
                        mma_16816(o[dt], ah, bl2);
                        mma_16816(o[dt], al, bh2);
                    }
                }
            }
        }
    }

    // ---- merge l across the quad (4 lanes share each row) ----
    #pragma unroll
    for (int off = 1; off <= 2; off <<= 1) {
        l0v += __shfl_xor_sync(0xffffffffu, l0v, off);
        l1v += __shfl_xor_sync(0xffffffffu, l1v, off);
    }
    const float inv0 = 1.f / l0v, inv1 = 1.f / l1v;
    if ((lane & 3) == 0) {
        sInv[tr0]     = inv0;
        sInv[tr0 + 8] = inv1;
    }

    // ---- write O (scaled) ----
    {
        int b_ = bh >> 4, h_ = bh & 15;
        size_t ob0 = ((size_t)b_*TT + r0)*CC + h_*64;
        size_t ob1 = ((size_t)b_*TT + r1)*CC + h_*64;
        #pragma unroll
        for (int dt = 0; dt < 8; dt++) {
            *(float2*)&g_o[ob0 + dt*8 + t2] = make_float2(o[dt][0]*inv0, o[dt][1]*inv0);
            *(float2*)&g_o[ob1 + dt*8 + t2] = make_float2(o[dt][2]*inv1, o[dt][3]*inv1);
        }
    }

    // ---- zero-fill att cols [kend, TT) ----
    {
        int zc4 = (TT - kend) >> 2;
        float4 z = make_float4(0.f, 0.f, 0.f, 0.f);
        if (zc4 > 0) {
            for (int i = tid; i < BLKM*zc4; i += NTH) {
                int row = i / zc4;
                int c4i = i - row*zc4;
                *(float4*)&att[(qbase + q0 + row)*TT + kend + c4i*4] = z;
            }
        }
    }

    // ---- in-CTA normalization sweep (rows just written, L2-hot) ----
    __syncthreads();
    for (int row = w; row < BLKM; row += 16) {
        float inv = sInv[row];
        int n = q0 + row + 1;
        int n4 = (n + 3) >> 2;
        float4* p = (float4*)(att + (qbase + q0 + row) * TT);
        for (int i = lane; i < n4; i += 32) {
            float4 v = p[i];
            v.x *= inv; v.y *= inv; v.z *= inv; v.w *= inv;
            p[i] = v;
        }
    }
}

// =====================================================================
extern "C" void kernel_launch(void* const* d_in, const int* in_sizes, int n_in,
                              void* d_out, int out_size)
{
    const float* x      = (const float*)d_in[0];
    const float* w_attn = (const float*)d_in[2];
    const float* b_attn = (const float*)d_in[3];
    const float* w_proj = (const float*)d_in[4];
    const float* b_proj = (const float*)d_in[5];
    const float* rel_k  = (const float*)d_in[6];
    float* out = (float*)d_out;

    const size_t YS = (size_t)BT*CC;
    const size_t AS = (size_t)BH*TT*TT;

    float* y_out = out;
    float* att_base = nullptr;
    int att_mode = 1;
    if ((size_t)out_size >= YS + AS) {
        y_out = out; att_base = out + YS; att_mode = 0;
    } else if ((size_t)out_size == AS) {
        att_base = out; att_mode = 0; y_out = nullptr;
    }

    cudaFuncSetAttribute(attn_kernel,
        cudaFuncAttributeMaxDynamicSharedMemorySize, ATTN_SMEM_BYTES);
    cudaFuncSetAttribute(mma_gemm_kernel<0>,
        cudaFuncAttributeMaxDynamicSharedMemorySize, GEMM_SMEM_BYTES);
    cudaFuncSetAttribute(mma_gemm_kernel<1>,
        cudaFuncAttributeMaxDynamicSharedMemorySize, GEMM_SMEM_BYTES);

    split_kernel<0><<<BT*CC/4/256, 256>>>(x);
    wsplit_kernel<0><<<dim3(3*CC/32, CC/32), dim3(32,8)>>>(w_attn, 3*CC);
    wsplit_kernel<1><<<dim3(CC/32,   CC/32), dim3(32,8)>>>(w_proj, CC);
    mma_gemm_kernel<0><<<dim3(24, 32), 256, GEMM_SMEM_BYTES>>>(b_attn, nullptr);
    qrel_kernel<<<BH*TT/32, 256>>>(rel_k);
    attn_kernel<<<dim3(TT/BLKM, BH), NTH, ATTN_SMEM_BYTES>>>(att_base, att_mode);
    split_kernel<1><<<BT*CC/4/256, 256>>>(nullptr);
    mma_gemm_kernel<1><<<dim3(8, 32), 256, GEMM_SMEM_BYTES>>>(b_proj, y_out);
}

// round 13
// speedup vs baseline: 2.7960x; 1.0157x over previous
#include <cuda_runtime.h>
#include <cuda_bf16.h>
#include <math.h>
#include <stdint.h>

#define BB 2
#define TT 2048
#define CC 1024
#define HH 16
#define DD 64
#define NR 65                      // 2*MAXREL+1
#define BH (BB*HH)                 // 32
#define BT (BB*TT)                 // 4096
#define BLKM 256                   // q-rows per attention CTA (16 warps)

// ---------------- device scratch ----------------
__device__ float g_q[BH*TT*DD];        // fp32 q (for qrel)
__device__ float g_qrel[BH*TT*NR];     // [bh][t][r]
__device__ float g_y[BT*CC];           // fallback y sink
__device__ float g_att[(size_t)BH*TT*TT]; // fallback att sink

// bf16 hi/lo operands
__device__ __nv_bfloat16 g_qh[BH*TT*DD], g_ql[BH*TT*DD];   // [bh][t][d]
__device__ __nv_bfloat16 g_kh[BH*TT*DD], g_kl[BH*TT*DD];   // [bh][t][d]
__device__ __nv_bfloat16 g_vth[BH*DD*TT], g_vtl[BH*DD*TT]; // V^T [bh][d][t]
__device__ __nv_bfloat16 g_xa_hi[BT*CC],  g_xa_lo[BT*CC];
__device__ __nv_bfloat16 g_oa_hi[BT*CC],  g_oa_lo[BT*CC];  // written by attn
__device__ __nv_bfloat16 g_wta_hi[3*CC*CC], g_wta_lo[3*CC*CC];
__device__ __nv_bfloat16 g_wtp_hi[CC*CC],   g_wtp_lo[CC*CC];

// ===================== helpers =====================
__device__ __forceinline__ uint32_t smem_to_u32(const void* p) {
    uint32_t a;
    asm("{ .reg .u64 t; cvta.to.shared.u64 t, %1; cvt.u32.u64 %0, t; }" : "=r"(a) : "l"(p));
    return a;
}
__device__ __forceinline__ void cp_async16(uint32_t saddr, const void* gptr) {
    asm volatile("cp.async.cg.shared.global [%0], [%1], 16;" :: "r"(saddr), "l"(gptr));
}
#define CP_COMMIT() asm volatile("cp.async.commit_group;" ::: "memory")
#define CP_WAIT0()  asm volatile("cp.async.wait_group 0;" ::: "memory")
#define CP_WAIT1()  asm volatile("cp.async.wait_group 1;" ::: "memory")

__device__ __forceinline__ void mma_16816(float* c, const uint32_t* a, const uint32_t* b) {
    asm volatile("mma.sync.aligned.m16n8k16.row.col.f32.bf16.bf16.f32 "
        "{%0,%1,%2,%3}, {%4,%5,%6,%7}, {%8,%9}, {%0,%1,%2,%3};"
        : "+f"(c[0]), "+f"(c[1]), "+f"(c[2]), "+f"(c[3])
        : "r"(a[0]), "r"(a[1]), "r"(a[2]), "r"(a[3]), "r"(b[0]), "r"(b[1]));
}
__device__ __forceinline__ uint32_t pack_bf2(__nv_bfloat16 a, __nv_bfloat16 b) {
    return ((uint32_t)__bfloat16_as_ushort(b) << 16) | __bfloat16_as_ushort(a);
}
__device__ __forceinline__ uint32_t pack_hi_lo(float p0, float p1, uint32_t& lo) {
    __nv_bfloat16 h0 = __float2bfloat16(p0), h1 = __float2bfloat16(p1);
    __nv_bfloat16 l0 = __float2bfloat16(p0 - __bfloat162float(h0));
    __nv_bfloat16 l1 = __float2bfloat16(p1 - __bfloat162float(h1));
    lo = pack_bf2(l0, l1);
    return pack_bf2(h0, h1);
}

// =====================================================================
// Conversion kernels
// =====================================================================
__global__ __launch_bounds__(256) void split_kernel(const float* __restrict__ in)
{
    __nv_bfloat16* hi = g_xa_hi;
    __nv_bfloat16* lo = g_xa_lo;
    int i = blockIdx.x * 256 + threadIdx.x;
    float4 v = ((const float4*)in)[i];
    float a[4] = {v.x, v.y, v.z, v.w};
    __nv_bfloat16 hb[4], lb[4];
    #pragma unroll
    for (int c = 0; c < 4; c++) {
        hb[c] = __float2bfloat16(a[c]);
        lb[c] = __float2bfloat16(a[c] - __bfloat162float(hb[c]));
    }
    ((uint32_t*)hi)[i*2+0] = pack_bf2(hb[0], hb[1]);
    ((uint32_t*)hi)[i*2+1] = pack_bf2(hb[2], hb[3]);
    ((uint32_t*)lo)[i*2+0] = pack_bf2(lb[0], lb[1]);
    ((uint32_t*)lo)[i*2+1] = pack_bf2(lb[2], lb[3]);
}

template<int WSEL>  // 0: w_attn -> g_wta, 1: w_proj -> g_wtp
__global__ __launch_bounds__(256) void wsplit_kernel(const float* __restrict__ W, int N)
{
    __shared__ float ts[32][33];
    __nv_bfloat16* hi = (WSEL == 0) ? g_wta_hi : g_wtp_hi;
    __nv_bfloat16* lo = (WSEL == 0) ? g_wta_lo : g_wtp_lo;
    int nx = blockIdx.x * 32, kx = blockIdx.y * 32;
    int tx = threadIdx.x, ty = threadIdx.y;
    #pragma unroll
    for (int j = ty; j < 32; j += 8)
        ts[j][tx] = W[(size_t)(kx + j)*N + nx + tx];
    __syncthreads();
    #pragma unroll
    for (int j = ty; j < 32; j += 8) {
        float v = ts[tx][j];
        __nv_bfloat16 h = __float2bfloat16(v);
        __nv_bfloat16 l = __float2bfloat16(v - __bfloat162float(h));
        hi[(size_t)(nx + j)*CC + kx + tx] = h;
        lo[(size_t)(nx + j)*CC + kx + tx] = l;
    }
}

// =====================================================================
// mma.sync bf16x3 GEMM, cp.async double-buffered (unchanged from R9)
// =====================================================================
#define LDA 72
#define SM_ARR (128*LDA)
#define GEMM_BUF_BYTES (4*SM_ARR*2)
#define GEMM_SMEM_BYTES (2*GEMM_BUF_BYTES)

template<int MODE>
__global__ __launch_bounds__(256) void mma_gemm_kernel(const float* __restrict__ bias,
                                                       float* __restrict__ outp)
{
    extern __shared__ __nv_bfloat16 sb[];
    const uint32_t sbase = smem_to_u32(sb);

    const int tid  = threadIdx.x;
    const int wid  = tid >> 5, lane = tid & 31;
    const int wm   = wid >> 2, wn = wid & 3;
    const int m0   = blockIdx.y * 128;
    const int n0   = blockIdx.x * 128;

    const __nv_bfloat16* Ah = (MODE == 0) ? g_xa_hi : g_oa_hi;
    const __nv_bfloat16* Al = (MODE == 0) ? g_xa_lo : g_oa_lo;
    const __nv_bfloat16* Bh = (MODE == 0) ? g_wta_hi : g_wtp_hi;
    const __nv_bfloat16* Bl = (MODE == 0) ? g_wta_lo : g_wtp_lo;

    auto load_tile = [&](int kt, int buf) {
        const int k0 = kt * 64;
        const uint32_t b0 = sbase + (uint32_t)buf * GEMM_BUF_BYTES;
        #pragma unroll
        for (int it = 0; it < 4; it++) {
            int i = tid + it * 256;
            int r = i >> 3, c8 = i & 7;
            size_t ga = (size_t)(m0 + r) * CC + k0 + c8 * 8;
            size_t gb = (size_t)(n0 + r) * CC + k0 + c8 * 8;
            uint32_t so = (uint32_t)(r * LDA + c8 * 8) * 2;
            cp_async16(b0 + so,               &Ah[ga]);
            cp_async16(b0 + SM_ARR*2 + so,    &Al[ga]);
            cp_async16(b0 + 2*SM_ARR*2 + so,  &Bh[gb]);
            cp_async16(b0 + 3*SM_ARR*2 + so,  &Bl[gb]);
        }
        CP_COMMIT();
    };

    float acc[4][4][4];
    #pragma unroll
    for (int i = 0; i < 4; i++)
        #pragma unroll
        for (int j = 0; j < 4; j++)
            #pragma unroll
            for (int c = 0; c < 4; c++) acc[i][j][c] = 0.f;

    const int g  = lane >> 2;
    const int t2 = (lane & 3) * 2;

    load_tile(0, 0);

    for (int kt = 0; kt < 16; kt++) {
        CP_WAIT0();
        __syncthreads();
        if (kt + 1 < 16) load_tile(kt + 1, (kt + 1) & 1);

        const __nv_bfloat16* bAh = sb + (kt & 1) * (4*SM_ARR);
        const __nv_bfloat16* bAl = bAh + SM_ARR;
        const __nv_bfloat16* bBh = bAh + 2*SM_ARR;
        const __nv_bfloat16* bBl = bAh + 3*SM_ARR;

        #pragma unroll
        for (int ks = 0; ks < 4; ks++) {
            const int kb = ks * 16 + t2;
            uint32_t ah[4][4], al[4][4];
            #pragma unroll
            for (int tm = 0; tm < 4; tm++) {
                int r0 = (wm*64 + tm*16 + g) * LDA + kb;
                int r1 = r0 + 8 * LDA;
                ah[tm][0] = *(const uint32_t*)&bAh[r0];
                ah[tm][1] = *(const uint32_t*)&bAh[r1];
                ah[tm][2] = *(const uint32_t*)&bAh[r0 + 8];
                ah[tm][3] = *(const uint32_t*)&bAh[r1 + 8];
                al[tm][0] = *(const uint32_t*)&bAl[r0];
                al[tm][1] = *(const uint32_t*)&bAl[r1];
                al[tm][2] = *(const uint32_t*)&bAl[r0 + 8];
                al[tm][3] = *(const uint32_t*)&bAl[r1 + 8];
            }
            #pragma unroll
            for (int tn = 0; tn < 4; tn++) {
                int rb = (wn*32 + tn*8 + g) * LDA + kb;
                uint32_t bh[2], bl[2];
                bh[0] = *(const uint32_t*)&bBh[rb];
                bh[1] = *(const uint32_t*)&bBh[rb + 8];
                bl[0] = *(const uint32_t*)&bBl[rb];
                bl[1] = *(const uint32_t*)&bBl[rb + 8];
                #pragma unroll
                for (int tm = 0; tm < 4; tm++) {
                    mma_16816(acc[tm][tn], ah[tm], bh);
                    mma_16816(acc[tm][tn], ah[tm], bl);
                    mma_16816(acc[tm][tn], al[tm], bh);
                }
            }
        }
        __syncthreads();
    }

    const int lr = lane >> 2;
    const int lc = (lane & 3) * 2;
    #pragma unroll
    for (int tm = 0; tm < 4; tm++) {
        #pragma unroll
        for (int tn = 0; tn < 4; tn++) {
            int c = n0 + wn*32 + tn*8 + lc;
            float b0 = bias[c], b1 = bias[c+1];
            #pragma unroll
            for (int half = 0; half < 2; half++) {
                int m = m0 + wm*64 + tm*16 + lr + half*8;
                float v0 = acc[tm][tn][half*2+0] + b0;
                float v1 = acc[tm][tn][half*2+1] + b1;
                if (MODE == 0) {
                    int which = c >> 10, hh = (c >> 6) & 15, dd = c & 63;
                    int b_ = m >> 11, t_ = m & 2047;
                    int bhx = b_*HH + hh;
                    __nv_bfloat16 h0 = __float2bfloat16(v0);
                    __nv_bfloat16 h1 = __float2bfloat16(v1);
                    __nv_bfloat16 l0 = __float2bfloat16(v0 - __bfloat162float(h0));
                    __nv_bfloat16 l1 = __float2bfloat16(v1 - __bfloat162float(h1));
                    if (which == 0) {
                        size_t di = ((size_t)bhx*TT + t_)*DD + dd;
                        *(float2*)&g_q[di] = make_float2(v0, v1);
                        *(uint32_t*)&g_qh[di] = pack_bf2(h0, h1);
                        *(uint32_t*)&g_ql[di] = pack_bf2(l0, l1);
                    } else if (which == 1) {
                        size_t di = ((size_t)bhx*TT + t_)*DD + dd;
                        *(uint32_t*)&g_kh[di] = pack_bf2(h0, h1);
                        *(uint32_t*)&g_kl[di] = pack_bf2(l0, l1);
                    } else {
                        size_t vb = (size_t)bhx*DD;
                        g_vth[(vb + dd    )*TT + t_] = h0;
                        g_vth[(vb + dd + 1)*TT + t_] = h1;
                        g_vtl[(vb + dd    )*TT + t_] = l0;
                        g_vtl[(vb + dd + 1)*TT + t_] = l1;
                    }
                } else {
                    float* dst = outp ? outp : g_y;
                    *(float2*)&dst[(size_t)m*CC + c] = make_float2(v0, v1);
                }
            }
        }
    }
}

// =====================================================================
// qrel
// =====================================================================
__device__ __forceinline__ float dot4(float4 a, float4 b) {
    return a.x*b.x + a.y*b.y + a.z*b.z + a.w*b.w;
}

__global__ __launch_bounds__(256) void qrel_kernel(const float* __restrict__ rel)
{
    __shared__ float rs[NR*64];
    __shared__ float qs[32*64];
    const int tid = threadIdx.x;
    const int r0  = blockIdx.x * 32;

    for (int i = tid; i < NR*16; i += 256)
        ((float4*)rs)[i] = ((const float4*)rel)[i];
    for (int i = tid; i < 32*16; i += 256) {
        int t = i >> 4, d4 = i & 15;
        *(float4*)&qs[t*64 + d4*4] = *(const float4*)&g_q[(size_t)(r0+t)*64 + d4*4];
    }
    __syncthreads();

    for (int i = tid; i < 32*NR; i += 256) {
        int t = i / NR, r = i % NR;
        const float4* qq = (const float4*)&qs[t*64];
        const float4* rr = (const float4*)&rs[r*64];
        float acc = 0.f;
        #pragma unroll
        for (int d4 = 0; d4 < 16; d4++) acc += dot4(qq[d4], rr[d4]);
        g_qrel[(size_t)(r0+t)*NR + r] = acc;
    }
}

// =====================================================================
// Single-pass flash attention, 512 threads / 256 q-rows per CTA.
// cp.async double-buffered K/V staging; O written as bf16 hi/lo (g_oa).
// =====================================================================
#define SKW 72          // K smem row pitch (bf16)
#define SVW 136         // V^T smem row pitch (bf16)
#define NTH 512
#define KV_KH 0
#define KV_KL (128*SKW*2)
#define KV_VH (2*128*SKW*2)
#define KV_VL (2*128*SKW*2 + 64*SVW*2)
#define KV_BUF_BYTES (2*128*SKW*2 + 2*64*SVW*2)      // 71680
#define ATTN_SMEM_BYTES (2*KV_BUF_BYTES + BLKM*66*4 + BLKM*4 + 64)

__global__ __launch_bounds__(NTH, 1) void attn_kernel(float* __restrict__ out_att, int att_mode)
{
    extern __shared__ char smc[];
    const uint32_t sbase = smem_to_u32(smc);
    float* QR = (float*)(smc + 2*KV_BUF_BYTES);        // [256][66]
    float* sInv = QR + BLKM*66;                        // [256]

    const int tid = threadIdx.x, w = tid >> 5, lane = tid & 31;
    const int g = lane >> 2, t2 = (lane & 3) * 2;
    const int q0 = blockIdx.x * BLKM;
    const int bh = blockIdx.y;
    const int kend = q0 + BLKM;
    const size_t qbase = (size_t)bh * TT;
    float* att = att_mode ? g_att : out_att;

    // stage chunk (128 keys at kc) into buffer buf via cp.async
    auto stage = [&](int kc, int buf) {
        const uint32_t b0 = sbase + (uint32_t)buf * KV_BUF_BYTES;
        #pragma unroll
        for (int it = 0; it < 2; it++) {
            int i = tid + it * NTH;
            int r = i >> 3, c = i & 7;
            size_t gs = (qbase + kc + r)*DD + c*8;
            uint32_t so = (uint32_t)(r*SKW + c*8) * 2;
            cp_async16(b0 + KV_KH + so, &g_kh[gs]);
            cp_async16(b0 + KV_KL + so, &g_kl[gs]);
        }
        #pragma unroll
        for (int it = 0; it < 2; it++) {
            int i = tid + it * NTH;
            int d = i >> 4, c = i & 15;
            size_t gs = ((size_t)bh*DD + d)*TT + kc + c*8;
            uint32_t so = (uint32_t)(d*SVW + c*8) * 2;
            cp_async16(b0 + KV_VH + so, &g_vth[gs]);
            cp_async16(b0 + KV_VL + so, &g_vtl[gs]);
        }
        CP_COMMIT();
    };

    for (int i = tid; i < BLKM*NR; i += NTH) {
        int t = i / NR, r = i % NR;
        QR[t*66 + r] = g_qrel[(qbase + q0 + t)*NR + r];
    }

    const int tr0 = w*16 + g;
    const int r0 = q0 + tr0;
    const int r1 = r0 + 8;
    const int wmax = q0 + w*16 + 15;

    // Q fragments (hi/lo)
    uint32_t qfh[4][4], qfl[4][4];
    {
        size_t ra = (qbase + (size_t)r0) * DD;
        size_t rb = ra + 8*DD;
        #pragma unroll
        for (int ks = 0; ks < 4; ks++) {
            int c0 = ks*16 + t2;
            qfh[ks][0] = *(const uint32_t*)&g_qh[ra + c0];
            qfh[ks][1] = *(const uint32_t*)&g_qh[rb + c0];
            qfh[ks][2] = *(const uint32_t*)&g_qh[ra + c0 + 8];
            qfh[ks][3] = *(const uint32_t*)&g_qh[rb + c0 + 8];
            qfl[ks][0] = *(const uint32_t*)&g_ql[ra + c0];
            qfl[ks][1] = *(const uint32_t*)&g_ql[rb + c0];
            qfl[ks][2] = *(const uint32_t*)&g_ql[ra + c0 + 8];
            qfl[ks][3] = *(const uint32_t*)&g_ql[rb + c0 + 8];
        }
    }

    stage(0, 0);
    __syncthreads();
    const float qr0c = QR[tr0*66];        // rel constant for far tiles (idx 0)
    const float qr1c = QR[(tr0+8)*66];

    float o[8][4];
    #pragma unroll
    for (int dt = 0; dt < 8; dt++)
        #pragma unroll
        for (int c = 0; c < 4; c++) o[dt][c] = 0.f;
    float l0v = 0.f, l1v = 0.f;

    const size_t ab0 = (qbase + (size_t)r0) * TT;
    const size_t ab1 = (qbase + (size_t)r1) * TT;

    int cbuf = 0;
    for (int kc = 0; kc < kend; kc += 128, cbuf ^= 1) {
        if (kc + 128 < kend) stage(kc + 128, cbuf ^ 1);
        CP_COMMIT();                 // (possibly empty) keeps group count uniform
        CP_WAIT1();                  // chunk kc resident
        __syncthreads();

        const __nv_bfloat16* sKh = (const __nv_bfloat16*)(smc + cbuf*KV_BUF_BYTES + KV_KH);
        const __nv_bfloat16* sKl = (const __nv_bfloat16*)(smc + cbuf*KV_BUF_BYTES + KV_KL);
        const __nv_bfloat16* sVh = (const __nv_bfloat16*)(smc + cbuf*KV_BUF_BYTES + KV_VH);
        const __nv_bfloat16* sVl = (const __nv_bfloat16*)(smc + cbuf*KV_BUF_BYTES + KV_VL);

        #pragma unroll
        for (int ss2 = 0; ss2 < 4; ss2++) {       // 32-key sub-slices
            float p4[4][4];
            #pragma unroll
            for (int nt4 = 0; nt4 < 4; nt4++) {
                int nt = ss2*4 + nt4;
                int kbase = kc + nt*8;
                float c4[4] = {0.f, 0.f, 0.f, 0.f};
                if (kbase <= wmax) {
                    #pragma unroll
                    for (int ks = 0; ks < 4; ks++) {
                        int rb = (nt*8 + g)*SKW + ks*16 + t2;
                        uint32_t bh2[2], bl2[2];
                        bh2[0] = *(const uint32_t*)&sKh[rb];
                        bh2[1] = *(const uint32_t*)&sKh[rb + 8];
                        bl2[0] = *(const uint32_t*)&sKl[rb];
                        bl2[1] = *(const uint32_t*)&sKl[rb + 8];
                        mma_16816(c4, qfh[ks], bh2);
                        mma_16816(c4, qfh[ks], bl2);
                        mma_16816(c4, qfl[ks], bh2);
                    }
                }
                int kg = kbase + t2;
                if (kbase + 40 <= r0) {
                    // FAR tile: dist <= -33 for both rows -> rel idx 0, no mask
                    p4[nt4][0] = __expf((c4[0] + qr0c) * 0.125f);
                    p4[nt4][1] = __expf((c4[1] + qr0c) * 0.125f);
                    p4[nt4][2] = __expf((c4[2] + qr1c) * 0.125f);
                    p4[nt4][3] = __expf((c4[3] + qr1c) * 0.125f);
                    l0v += p4[nt4][0] + p4[nt4][1];
                    l1v += p4[nt4][2] + p4[nt4][3];
                } else {
                    {
                        int d0 = min(max(kg - r0, -32), 32) + 32;
                        int d1 = min(max(kg + 1 - r0, -32), 32) + 32;
                        float s0 = (c4[0] + QR[tr0*66 + d0]) * 0.125f;
                        float s1 = (c4[1] + QR[tr0*66 + d1]) * 0.125f;
                        p4[nt4][0] = (kg     <= r0) ? __expf(fminf(s0, 80.f)) : 0.f;
                        p4[nt4][1] = (kg + 1 <= r0) ? __expf(fminf(s1, 80.f)) : 0.f;
                        l0v += p4[nt4][0] + p4[nt4][1];
                    }
                    {
                        int d0 = min(max(kg - r1, -32), 32) + 32;
                        int d1 = min(max(kg + 1 - r1, -32), 32) + 32;
                        float s0 = (c4[2] + QR[(tr0+8)*66 + d0]) * 0.125f;
                        float s1 = (c4[3] + QR[(tr0+8)*66 + d1]) * 0.125f;
                        p4[nt4][2] = (kg     <= r1) ? __expf(fminf(s0, 80.f)) : 0.f;
                        p4[nt4][3] = (kg + 1 <= r1) ? __expf(fminf(s1, 80.f)) : 0.f;
                        l1v += p4[nt4][2] + p4[nt4][3];
                    }
                }
                *(float2*)&att[ab0 + kbase + t2] = make_float2(p4[nt4][0], p4[nt4][1]);
                *(float2*)&att[ab1 + kbase + t2] = make_float2(p4[nt4][2], p4[nt4][3]);
            }
            #pragma unroll
            for (int ksl = 0; ksl < 2; ksl++) {
                int kslice = kc + ss2*32 + ksl*16;
                if (kslice <= wmax) {
                    uint32_t ah[4], al[4];
                    ah[0] = pack_hi_lo(p4[2*ksl][0],   p4[2*ksl][1],   al[0]);
                    ah[1] = pack_hi_lo(p4[2*ksl][2],   p4[2*ksl][3],   al[1]);
                    ah[2] = pack_hi_lo(p4[2*ksl+1][0], p4[2*ksl+1][1], al[2]);
                    ah[3] = pack_hi_lo(p4[2*ksl+1][2], p4[2*ksl+1][3], al[3]);
                    int kloc = ss2*32 + ksl*16 + t2;
                    #pragma unroll
                    for (int dt = 0; dt < 8; dt++) {
                        int db = (dt*8 + g)*SVW + kloc;
                        uint32_t bh2[2], bl2[2];
                        bh2[0] = *(const uint32_t*)&sVh[db];
                        bh2[1] = *(const uint32_t*)&sVh[db + 8];
                        bl2[0] = *(const uint32_t*)&sVl[db];
                        bl2[1] = *(const uint32_t*)&sVl[db + 8];
                        mma_16816(o[dt], ah, bh2);
                        mma_16816(o[dt], ah, bl2);
                        mma_16816(o[dt], al, bh2);
                    }
                }
            }
        }
        __syncthreads();             // protect buffer before next-next stage
    }

    // ---- merge l across the quad (4 lanes share each row) ----
    #pragma unroll
    for (int off = 1; off <= 2; off <<= 1) {
        l0v += __shfl_xor_sync(0xffffffffu, l0v, off);
        l1v += __shfl_xor_sync(0xffffffffu, l1v, off);
    }
    const float inv0 = 1.f / l0v, inv1 = 1.f / l1v;
    if ((lane & 3) == 0) {
        sInv[tr0]     = inv0;
        sInv[tr0 + 8] = inv1;
    }

    // ---- write O scaled, directly as bf16 hi/lo (fused split for proj) ----
    {
        int b_ = bh >> 4, h_ = bh & 15;
        size_t ob0 = ((size_t)b_*TT + r0)*CC + h_*64;
        size_t ob1 = ((size_t)b_*TT + r1)*CC + h_*64;
        #pragma unroll
        for (int dt = 0; dt < 8; dt++) {
            uint32_t lo0, lo1;
            uint32_t hi0 = pack_hi_lo(o[dt][0]*inv0, o[dt][1]*inv0, lo0);
            uint32_t hi1 = pack_hi_lo(o[dt][2]*inv1, o[dt][3]*inv1, lo1);
            *(uint32_t*)&g_oa_hi[ob0 + dt*8 + t2] = hi0;
            *(uint32_t*)&g_oa_lo[ob0 + dt*8 + t2] = lo0;
            *(uint32_t*)&g_oa_hi[ob1 + dt*8 + t2] = hi1;
            *(uint32_t*)&g_oa_lo[ob1 + dt*8 + t2] = lo1;
        }
    }

    // ---- zero-fill att cols [kend, TT) ----
    {
        int zc4 = (TT - kend) >> 2;
        float4 z = make_float4(0.f, 0.f, 0.f, 0.f);
        if (zc4 > 0) {
            for (int i = tid; i < BLKM*zc4; i += NTH) {
                int row = i / zc4;
                int c4i = i - row*zc4;
                *(float4*)&att[(qbase + q0 + row)*TT + kend + c4i*4] = z;
            }
        }
    }

    // ---- in-CTA normalization sweep (rows just written, L2-hot) ----
    __syncthreads();
    for (int row = w; row < BLKM; row += 16) {
        float inv = sInv[row];
        int n = q0 + row + 1;
        int n4 = (n + 3) >> 2;
        float4* p = (float4*)(att + (qbase + q0 + row) * TT);
        for (int i = lane; i < n4; i += 32) {
            float4 v = p[i];
            v.x *= inv; v.y *= inv; v.z *= inv; v.w *= inv;
            p[i] = v;
        }
    }
}

// =====================================================================
extern "C" void kernel_launch(void* const* d_in, const int* in_sizes, int n_in,
                              void* d_out, int out_size)
{
    const float* x      = (const float*)d_in[0];
    const float* w_attn = (const float*)d_in[2];
    const float* b_attn = (const float*)d_in[3];
    const float* w_proj = (const float*)d_in[4];
    const float* b_proj = (const float*)d_in[5];
    const float* rel_k  = (const float*)d_in[6];
    float* out = (float*)d_out;

    const size_t YS = (size_t)BT*CC;
    const size_t AS = (size_t)BH*TT*TT;

    float* y_out = out;
    float* att_base = nullptr;
    int att_mode = 1;
    if ((size_t)out_size >= YS + AS) {
        y_out = out; att_base = out + YS; att_mode = 0;
    } else if ((size_t)out_size == AS) {
        att_base = out; att_mode = 0; y_out = nullptr;
    }

    cudaFuncSetAttribute(attn_kernel,
        cudaFuncAttributeMaxDynamicSharedMemorySize, ATTN_SMEM_BYTES);
    cudaFuncSetAttribute(mma_gemm_kernel<0>,
        cudaFuncAttributeMaxDynamicSharedMemorySize, GEMM_SMEM_BYTES);
    cudaFuncSetAttribute(mma_gemm_kernel<1>,
        cudaFuncAttributeMaxDynamicSharedMemorySize, GEMM_SMEM_BYTES);

    split_kernel<<<BT*CC/4/256, 256>>>(x);
    wsplit_kernel<0><<<dim3(3*CC/32, CC/32), dim3(32,8)>>>(w_attn, 3*CC);
    wsplit_kernel<1><<<dim3(CC/32,   CC/32), dim3(32,8)>>>(w_proj, CC);
    mma_gemm_kernel<0><<<dim3(24, 32), 256, GEMM_SMEM_BYTES>>>(b_attn, nullptr);
    qrel_kernel<<<BH*TT/32, 256>>>(rel_k);
    attn_kernel<<<dim3(TT/BLKM, BH), NTH, ATTN_SMEM_BYTES>>>(att_base, att_mode);
    mma_gemm_kernel<1><<<dim3(8, 32), 256, GEMM_SMEM_BYTES>>>(b_proj, y_out);
}